// round 11
// baseline (speedup 1.0000x reference)
#include <cuda_runtime.h>
#include <cuda_bf16.h>
#include <stdint.h>
#include <cstdint>
#include <math.h>

#define N_NODES 20000
#define N_EDGES 640000
#define HDIM    256
#define GN      16
#define OUTD    100
#define ATOMD   118
#define HH      (HDIM * HDIM)

// ---------------- scratch ----------------------------------------------------
__device__ __align__(16) float g_h  [N_NODES * HDIM];
__device__ __align__(16) float g_hd [N_NODES * HDIM];
__device__ __align__(16) float g_uv [2 * 2 * HDIM];     // [layer][u|vp]
__device__ __align__(16) float g_F1 [ATOMD * HDIM];
__device__ __align__(16) float g_F2 [3 * HDIM];
__device__ __align__(16) float g_bf [HDIM];
__device__ __align__(16) float g_feat[GN * HDIM];
__device__ int   g_cnt [N_NODES + 1];
__device__ int   g_offs[N_NODES + 1];
__device__ int   g_wp  [N_NODES];
__device__ int   g_csr [N_EDGES];
// bf16 split operands
__device__ __align__(16) __nv_bfloat16 g_xa_hi[N_NODES * 128];
__device__ __align__(16) __nv_bfloat16 g_xa_lo[N_NODES * 128];
__device__ __align__(16) __nv_bfloat16 g_h_hi [N_NODES * HDIM];
__device__ __align__(16) __nv_bfloat16 g_h_lo [N_NODES * HDIM];
__device__ __align__(16) __nv_bfloat16 g_r_hi [N_NODES * HDIM];
__device__ __align__(16) __nv_bfloat16 g_r_lo [N_NODES * HDIM];
__device__ __align__(16) __nv_bfloat16 g_s_hi [N_NODES * HDIM];  // hs bf16 (gather src)
__device__ __align__(16) __nv_bfloat16 g_Bt_hi[8 * HH];
__device__ __align__(16) __nv_bfloat16 g_Bt_lo[8 * HH];
__device__ __align__(16) __nv_bfloat16 g_F1t_hi[HDIM * 128];
__device__ __align__(16) __nv_bfloat16 g_F1t_lo[HDIM * 128];

// ---------------- PTX helpers (all sm_80-legal) ------------------------------
__device__ __forceinline__ uint32_t smem_to_u32(const void* p) {
    uint32_t a;
    asm("{ .reg .u64 t; cvta.to.shared.u64 t, %1; cvt.u32.u64 %0, t; }" : "=r"(a) : "l"(p));
    return a;
}
__device__ __forceinline__ void ldsm4(uint32_t* r, uint32_t addr) {
    asm volatile("ldmatrix.sync.aligned.m8n8.x4.shared.b16 {%0,%1,%2,%3}, [%4];"
                 : "=r"(r[0]), "=r"(r[1]), "=r"(r[2]), "=r"(r[3]) : "r"(addr));
}
__device__ __forceinline__ void mma16816(float* c, const uint32_t* a, uint32_t b0, uint32_t b1) {
    asm volatile("mma.sync.aligned.m16n8k16.row.col.f32.bf16.bf16.f32 "
                 "{%0,%1,%2,%3}, {%4,%5,%6,%7}, {%8,%9}, {%0,%1,%2,%3};"
                 : "+f"(c[0]), "+f"(c[1]), "+f"(c[2]), "+f"(c[3])
                 : "r"(a[0]), "r"(a[1]), "r"(a[2]), "r"(a[3]), "r"(b0), "r"(b1));
}
__device__ __forceinline__ void cp_async16(uint32_t d, const void* s, int src_sz) {
    asm volatile("cp.async.cg.shared.global [%0], [%1], 16, %2;"
                 :: "r"(d), "l"(s), "r"(src_sz) : "memory");
}
#define CP_COMMIT() asm volatile("cp.async.commit_group;" ::: "memory")
#define CP_WAIT0()  asm volatile("cp.async.wait_group 0;" ::: "memory")

// ---------------- CSR build --------------------------------------------------
__global__ void zero_pre_kernel(int N) {
    int stride = gridDim.x * blockDim.x;
    int i = blockIdx.x * blockDim.x + threadIdx.x;
    for (int t = i; t < N + 1; t += stride) g_cnt[t] = 0;
    for (int t = i; t < GN * HDIM; t += stride) g_feat[t] = 0.f;
}
__global__ void hist_kernel(const int* __restrict__ dst, int E) {
    int e = blockIdx.x * blockDim.x + threadIdx.x;
    if (e < E) atomicAdd(&g_cnt[dst[e]], 1);
}
__global__ void scan_kernel(int N) {
    __shared__ int partial[1024];
    int t = threadIdx.x;
    int per = (N + 1023) / 1024;
    int start = t * per;
    int stop  = min(start + per, N);
    int sum = 0;
    for (int i = start; i < stop; i++) sum += g_cnt[i];
    partial[t] = sum;
    __syncthreads();
    for (int d = 1; d < 1024; d <<= 1) {
        int v = (t >= d) ? partial[t - d] : 0;
        __syncthreads();
        partial[t] += v;
        __syncthreads();
    }
    int run = (t == 0) ? 0 : partial[t - 1];
    for (int i = start; i < stop; i++) {
        g_offs[i] = run;
        g_wp[i]   = run;
        run += g_cnt[i];
    }
    if (t == 1023) g_offs[N] = partial[1023];
}
__global__ void fill_kernel(const int* __restrict__ dst, int E) {
    int e = blockIdx.x * blockDim.x + threadIdx.x;
    if (e < E) {
        int pos = atomicAdd(&g_wp[dst[e]], 1);
        g_csr[pos] = e;
    }
}

// ---------------- weight folding / conversions -------------------------------
__global__ void fold_small_kernel(const float* __restrict__ Wc,
                                  const float* __restrict__ Wn,
                                  const float* __restrict__ ba,
                                  const float* __restrict__ bc,
                                  const float* __restrict__ bn) {
    int j = threadIdx.x;
    float f0 = 0.f, f1 = 0.f, f2 = 0.f, bias = 0.f;
    for (int h = 0; h < HDIM; h++) {
        float wtop = Wn[h * HDIM + j];
        float wbot = Wn[(HDIM + h) * HDIM + j];
        f0 += Wc[0 * HDIM + h] * wbot;
        f1 += Wc[1 * HDIM + h] * wbot;
        f2 += Wc[2 * HDIM + h] * wbot;
        bias += ba[h] * wtop + bc[h] * wbot;
    }
    g_F2[0 * HDIM + j] = f0;
    g_F2[1 * HDIM + j] = f1;
    g_F2[2 * HDIM + j] = f2;
    g_bf[j] = bias + bn[j];
}

__global__ void coord_init_kernel(const float* __restrict__ coord, int N) {
    int idx = blockIdx.x * blockDim.x + threadIdx.x;
    if (idx >= N * HDIM) return;
    int n = idx >> 8;
    int j = idx & 255;
    float c0 = coord[n * 3], c1 = coord[n * 3 + 1], c2 = coord[n * 3 + 2];
    g_hd[idx] = c0 * g_F2[j] + c1 * g_F2[HDIM + j] + c2 * g_F2[2 * HDIM + j] + g_bf[j];
}

__device__ __forceinline__ void split_bf16(float v, __nv_bfloat16& hi, __nv_bfloat16& lo) {
    hi = __float2bfloat16(v);
    lo = __float2bfloat16(v - __bfloat162float(hi));
}

__global__ void conv_x_kernel(const float* __restrict__ x, int N) {
    int e = blockIdx.x * blockDim.x + threadIdx.x;
    if (e >= N * 128) return;
    int n = e >> 7, kk = e & 127;
    float v = (kk < ATOMD) ? x[n * ATOMD + kk] : 0.f;
    __nv_bfloat16 hi, lo;
    split_bf16(v, hi, lo);
    g_xa_hi[e] = hi;
    g_xa_lo[e] = lo;
}

__global__ void conv_wT_kernel(const float* __restrict__ W_agg,
                               const float* __restrict__ W_glu_a,
                               const float* __restrict__ W_glu_b) {
    int z = blockIdx.y;
    const float* src;
    switch (z) {
        case 0: src = W_agg; break;
        case 1: src = W_agg + 2 * HH; break;
        case 2: src = W_agg + 3 * HH; break;
        case 3: src = W_agg + 5 * HH; break;
        case 4: src = W_glu_a; break;
        case 5: src = W_glu_b; break;
        case 6: src = W_glu_a + HH; break;
        default: src = W_glu_b + HH; break;
    }
    int e = blockIdx.x * blockDim.x + threadIdx.x;
    int n = e >> 8, k = e & 255;
    float v = src[k * HDIM + n];
    __nv_bfloat16 hi, lo;
    split_bf16(v, hi, lo);
    g_Bt_hi[z * HH + e] = hi;
    g_Bt_lo[z * HH + e] = lo;
}

__global__ void conv_F1t_kernel() {
    int e = blockIdx.x * blockDim.x + threadIdx.x;
    if (e >= HDIM * 128) return;
    int n = e >> 7, k = e & 127;
    float v = (k < ATOMD) ? g_F1[k * HDIM + n] : 0.f;
    __nv_bfloat16 hi, lo;
    split_bf16(v, hi, lo);
    g_F1t_hi[e] = hi;
    g_F1t_lo[e] = lo;
}

__global__ void uv_kernel(const float* __restrict__ W_agg,
                          const float* __restrict__ Wedge,
                          const float* __restrict__ bedge,
                          const float* __restrict__ b_agg) {
    int l = blockIdx.x;
    int j = threadIdx.x;
    const float* We = W_agg + (size_t)l * 3 * HH + HH;
    float u = 0.f, v = 0.f;
    for (int k = 0; k < HDIM; k++) {
        float we = We[k * HDIM + j];
        u += Wedge[k] * we;
        v += bedge[k] * we;
    }
    g_uv[l * 2 * HDIM + j] = u;
    g_uv[l * 2 * HDIM + HDIM + j] = v + b_agg[l * HDIM + j];
}

// ---------------- warp-per-node aggregation (bf16 gather) --------------------
__global__ void agg_kernel(const int* __restrict__ src,
                           const float* __restrict__ radius,
                           const float* __restrict__ exp_l,
                           const float* __restrict__ eps_l, int l, int N) {
    int warp = (blockIdx.x * blockDim.x + threadIdx.x) >> 5;
    int lane = threadIdx.x & 31;
    if (warp >= N) return;
    float el = __ldg(&exp_l[l]);
    const float* uvb = g_uv + l * 2 * HDIM;
    int beg = g_offs[warp], end = g_offs[warp + 1];
    float4 acc0 = make_float4(0.f, 0.f, 0.f, 0.f);
    float4 acc1 = make_float4(0.f, 0.f, 0.f, 0.f);
    float s1 = 0.f, swr = 0.f;
    int j0 = lane * 8;
    for (int base = beg; base < end; base += 32) {
        int p = base + lane;
        int s = 0;
        float w = 0.f;
        if (p < end) {
            int e = g_csr[p];
            s = src[e];
            float r = radius[e];
            w = __expf(__logf(r) * el);
            s1 += w;
            swr += w * r;
        }
        int cnt = min(32, end - base);
        for (int q = 0; q < cnt; q++) {
            int   sq = __shfl_sync(0xffffffffu, s, q);
            float wq = __shfl_sync(0xffffffffu, w, q);
            uint4 pv = *(const uint4*)(g_s_hi + (size_t)sq * HDIM + j0);
            float2 f0 = __bfloat1622float2(*(__nv_bfloat162*)&pv.x);
            float2 f1 = __bfloat1622float2(*(__nv_bfloat162*)&pv.y);
            float2 f2 = __bfloat1622float2(*(__nv_bfloat162*)&pv.z);
            float2 f3 = __bfloat1622float2(*(__nv_bfloat162*)&pv.w);
            acc0.x += wq * f0.x; acc0.y += wq * f0.y;
            acc0.z += wq * f1.x; acc0.w += wq * f1.y;
            acc1.x += wq * f2.x; acc1.y += wq * f2.y;
            acc1.z += wq * f3.x; acc1.w += wq * f3.y;
        }
    }
#pragma unroll
    for (int off = 16; off; off >>= 1) {
        s1  += __shfl_xor_sync(0xffffffffu, s1, off);
        swr += __shfl_xor_sync(0xffffffffu, swr, off);
    }
    float ep = 1.f + __ldg(&eps_l[l]);
    float4 u0  = *(const float4*)(uvb + j0);
    float4 u1  = *(const float4*)(uvb + j0 + 4);
    float4 vp0 = *(const float4*)(uvb + HDIM + j0);
    float4 vp1 = *(const float4*)(uvb + HDIM + j0 + 4);
    size_t idx = (size_t)warp * HDIM + j0;
    float4 h0  = *(const float4*)(g_h + idx);
    float4 h1  = *(const float4*)(g_h + idx + 4);
    float4 d0  = *(const float4*)(g_hd + idx);
    float4 d1  = *(const float4*)(g_hd + idx + 4);
    float v[8];
    v[0] = ep * h0.x + acc0.x + s1 * (d0.x + vp0.x) + swr * u0.x;
    v[1] = ep * h0.y + acc0.y + s1 * (d0.y + vp0.y) + swr * u0.y;
    v[2] = ep * h0.z + acc0.z + s1 * (d0.z + vp0.z) + swr * u0.z;
    v[3] = ep * h0.w + acc0.w + s1 * (d0.w + vp0.w) + swr * u0.w;
    v[4] = ep * h1.x + acc1.x + s1 * (d1.x + vp1.x) + swr * u1.x;
    v[5] = ep * h1.y + acc1.y + s1 * (d1.y + vp1.y) + swr * u1.y;
    v[6] = ep * h1.z + acc1.z + s1 * (d1.z + vp1.z) + swr * u1.z;
    v[7] = ep * h1.w + acc1.w + s1 * (d1.w + vp1.w) + swr * u1.w;
    __nv_bfloat16 hi8[8];
    __nv_bfloat16 lo8[8];
#pragma unroll
    for (int j = 0; j < 8; j++) split_bf16(v[j], hi8[j], lo8[j]);
    *(uint4*)(g_r_hi + idx) = *(uint4*)hi8;
    *(uint4*)(g_r_lo + idx) = *(uint4*)lo8;
}

// masked segment-sum over sorted graph_id -> g_feat (reads g_h)
__global__ void segsum_kernel(const int* __restrict__ mask,
                              const int* __restrict__ gid, int N) {
    int j  = threadIdx.x;
    int n0 = blockIdx.x * 128;
    if (n0 >= N) return;
    int n1 = min(n0 + 128, N);
    float acc = 0.f;
    int curg = gid[n0];
    for (int n = n0; n < n1; n++) {
        int g = gid[n];
        if (g != curg) {
            atomicAdd(&g_feat[curg * HDIM + j], acc);
            acc = 0.f;
            curg = g;
        }
        if (mask[n]) acc += g_h[n * HDIM + j];
    }
    atomicAdd(&g_feat[curg * HDIM + j], acc);
}

__global__ void mlp_kernel(const float* __restrict__ Wm,
                           const float* __restrict__ bm,
                           float* __restrict__ out, float invN) {
    int g = blockIdx.x;
    int o = threadIdx.x;
    if (o >= OUTD) return;
    float s = 0.f;
    for (int j = 0; j < HDIM; j++)
        s += g_feat[g * HDIM + j] * Wm[j * OUTD + o];
    s = s * invN + bm[o];
    out[g * OUTD + o] = 1.f / (1.f + __expf(-s));
}

// ---------------- mma.sync split-bf16 GEMM (R8 config: 256 thr, 32x64) -------
#define TSB 10240
#define OFF_AL 20480
#define OFF_BH 40960
#define OFF_BL 61440

__global__ __launch_bounds__(256, 2)
void mma_gemm(const __nv_bfloat16* __restrict__ Ahi, const __nv_bfloat16* __restrict__ Alo,
              int M, int Ktot,
              const __nv_bfloat16* __restrict__ Bh0, const __nv_bfloat16* __restrict__ Bl0,
              const __nv_bfloat16* __restrict__ Bh1, const __nv_bfloat16* __restrict__ Bl1,
              float* __restrict__ C0, float* __restrict__ C1,
              const float* __restrict__ addend,
              __nv_bfloat16* __restrict__ Chi0, __nv_bfloat16* __restrict__ Clo0,
              __nv_bfloat16* __restrict__ Chi1, __nv_bfloat16* __restrict__ Clo1) {
    extern __shared__ char smem[];
    const __nv_bfloat16* Bhi = blockIdx.z ? Bh1 : Bh0;
    const __nv_bfloat16* Blo = blockIdx.z ? Bl1 : Bl0;
    float* Cout = blockIdx.z ? C1 : C0;
    __nv_bfloat16* Chi = blockIdx.z ? Chi1 : Chi0;
    __nv_bfloat16* Clo = blockIdx.z ? Clo1 : Clo0;

    int tid = threadIdx.x;
    int wid = tid >> 5;
    int lane = tid & 31;
    int warp_m = wid & 3;
    int warp_n = wid >> 2;
    int m0 = blockIdx.x * 128;
    int n0 = blockIdx.y * 128;
    uint32_t sb = smem_to_u32(smem);

    float acc[2][8][4];
#pragma unroll
    for (int a = 0; a < 2; a++)
#pragma unroll
        for (int b = 0; b < 8; b++)
#pragma unroll
            for (int c = 0; c < 4; c++) acc[a][b][c] = 0.f;

    int KT = Ktot >> 5;
    int lrow = (lane & 7) + ((lane >> 3) & 1) * 8;
    int lcol = (lane >> 4) * 8;

    int row0 = tid >> 2,           kc0 = (tid & 3) * 8;
    int row1 = (tid + 256) >> 2,   kc1 = (tid & 3) * 8;
    int arow0 = (m0 + row0 < M) ? (m0 + row0) : 0;
    int arow1 = (m0 + row1 < M) ? (m0 + row1) : 0;
    int asz0  = (m0 + row0 < M) ? 16 : 0;
    int asz1  = (m0 + row1 < M) ? 16 : 0;

#define LOAD_STAGE(kt, buf)                                                        \
    do {                                                                           \
        int k0 = (kt) * 32;                                                        \
        uint32_t d0 = sb + (buf) * TSB + ((uint32_t)row0 * 40 + kc0) * 2;          \
        uint32_t d1 = sb + (buf) * TSB + ((uint32_t)row1 * 40 + kc1) * 2;          \
        size_t ao0 = (size_t)arow0 * Ktot + k0 + kc0;                              \
        size_t ao1 = (size_t)arow1 * Ktot + k0 + kc1;                              \
        size_t bo0 = (size_t)(n0 + row0) * Ktot + k0 + kc0;                        \
        size_t bo1 = (size_t)(n0 + row1) * Ktot + k0 + kc1;                        \
        cp_async16(d0,          Ahi + ao0, asz0);                                  \
        cp_async16(d0 + OFF_AL, Alo + ao0, asz0);                                  \
        cp_async16(d0 + OFF_BH, Bhi + bo0, 16);                                    \
        cp_async16(d0 + OFF_BL, Blo + bo0, 16);                                    \
        cp_async16(d1,          Ahi + ao1, asz1);                                  \
        cp_async16(d1 + OFF_AL, Alo + ao1, asz1);                                  \
        cp_async16(d1 + OFF_BH, Bhi + bo1, 16);                                    \
        cp_async16(d1 + OFF_BL, Blo + bo1, 16);                                    \
    } while (0)

    LOAD_STAGE(0, 0);
    CP_COMMIT();

#pragma unroll 1
    for (int kt = 0; kt < KT; kt++) {
        int buf = kt & 1;
        CP_WAIT0();
        __syncthreads();
        if (kt + 1 < KT) {
            LOAD_STAGE(kt + 1, buf ^ 1);
            CP_COMMIT();
        }
#pragma unroll
        for (int ks = 0; ks < 2; ks++) {
            int kc = ks * 16 + lcol;
            uint32_t ah[2][4], al[2][4];
#pragma unroll
            for (int mt = 0; mt < 2; mt++) {
                int r = warp_m * 32 + mt * 16 + lrow;
                uint32_t addr = sb + buf * TSB + ((uint32_t)r * 40 + kc) * 2;
                ldsm4(ah[mt], addr);
                ldsm4(al[mt], addr + OFF_AL);
            }
#pragma unroll
            for (int ng = 0; ng < 4; ng++) {
                int r = warp_n * 64 + ng * 16 + lrow;
                uint32_t baddr = sb + buf * TSB + ((uint32_t)r * 40 + kc) * 2 + OFF_BH;
                uint32_t bh[4], bl[4];
                ldsm4(bh, baddr);
                ldsm4(bl, baddr + (OFF_BL - OFF_BH));
#pragma unroll
                for (int mt = 0; mt < 2; mt++) {
                    mma16816(acc[mt][2 * ng],     ah[mt], bh[0], bh[2]);
                    mma16816(acc[mt][2 * ng],     ah[mt], bl[0], bl[2]);
                    mma16816(acc[mt][2 * ng],     al[mt], bh[0], bh[2]);
                    mma16816(acc[mt][2 * ng + 1], ah[mt], bh[1], bh[3]);
                    mma16816(acc[mt][2 * ng + 1], ah[mt], bl[1], bl[3]);
                    mma16816(acc[mt][2 * ng + 1], al[mt], bh[1], bh[3]);
                }
            }
        }
    }

    int gi = lane >> 2;
    int ci = (lane & 3) * 2;
#pragma unroll
    for (int mt = 0; mt < 2; mt++) {
#pragma unroll
        for (int nt = 0; nt < 8; nt++) {
            float* a4 = acc[mt][nt];
            int col = n0 + warp_n * 64 + nt * 8 + ci;
#pragma unroll
            for (int half = 0; half < 2; half++) {
                int row = m0 + warp_m * 32 + mt * 16 + gi + half * 8;
                if (row >= M) continue;
                float v0 = a4[half * 2];
                float v1 = a4[half * 2 + 1];
                size_t o = (size_t)row * HDIM + col;
                if (addend) {
                    float2 t = *(const float2*)(addend + o);
                    v0 += t.x; v1 += t.y;
                }
                if (Cout) *(float2*)(Cout + o) = make_float2(v0, v1);
                if (Chi) {
                    __nv_bfloat16 h0, l0, h1, l1;
                    split_bf16(v0, h0, l0);
                    split_bf16(v1, h1, l1);
                    __nv_bfloat162 hv; hv.x = h0; hv.y = h1;
                    *(__nv_bfloat162*)(Chi + o) = hv;
                    if (Clo) {
                        __nv_bfloat162 lv; lv.x = l0; lv.y = l1;
                        *(__nv_bfloat162*)(Clo + o) = lv;
                    }
                }
            }
        }
    }
#undef LOAD_STAGE
}

// ---------------- fused GLU GEMM: h = (A@Wa+ba) * sigmoid(A@Wb+bb) ----------
// 512 threads, 16 warps of 32x32; dual accumulators (ga, gb) per warp tile.
// SMEM per stage: Ah, Al, BhA, BlA, BhB, BlB @ 10240 B each = 61440; 2 stages.
#define GTSB   61440
#define GO_AL  10240
#define GO_BHA 20480
#define GO_BLA 30720
#define GO_BHB 40960
#define GO_BLB 51200

__global__ __launch_bounds__(512, 1)
void mma_glu(const __nv_bfloat16* __restrict__ Ahi, const __nv_bfloat16* __restrict__ Alo,
             int M,
             const __nv_bfloat16* __restrict__ BhA, const __nv_bfloat16* __restrict__ BlA,
             const __nv_bfloat16* __restrict__ BhB, const __nv_bfloat16* __restrict__ BlB,
             const float* __restrict__ biasA, const float* __restrict__ biasB,
             float* __restrict__ Hout,
             __nv_bfloat16* __restrict__ Hhi, __nv_bfloat16* __restrict__ Hlo) {
    extern __shared__ char smem[];
    const int Ktot = HDIM;
    int tid = threadIdx.x;
    int wid = tid >> 5;
    int lane = tid & 31;
    int warp_m = wid & 3;
    int warp_n = wid >> 2;
    int m0 = blockIdx.x * 128;
    int n0 = blockIdx.y * 128;
    uint32_t sb = smem_to_u32(smem);

    float acc[2][2][2][4];   // [mat][mt][ntPair...] -> [mat][mt][nt(0..1 of 2x8=16col? see below)]
    // layout: acc[mat][mt][nt][4] with nt<4 covering 32 cols? 32 cols = 4 nt of 8.
    // Use acc2[mat][mt][nt][4] flattened: mat*2*4*4
    float accf[2][2][4][4];
#pragma unroll
    for (int a = 0; a < 2; a++)
#pragma unroll
        for (int b = 0; b < 2; b++)
#pragma unroll
            for (int c = 0; c < 4; c++)
#pragma unroll
                for (int d = 0; d < 4; d++) accf[a][b][c][d] = 0.f;
    (void)acc;

    int KT = Ktot >> 5;  // 8
    int lrow = (lane & 7) + ((lane >> 3) & 1) * 8;
    int lcol = (lane >> 4) * 8;

    int rowL = tid >> 2, kcL = (tid & 3) * 8;
    int arowL = (m0 + rowL < M) ? (m0 + rowL) : 0;
    int aszL  = (m0 + rowL < M) ? 16 : 0;

#define GLOAD(kt, buf)                                                             \
    do {                                                                           \
        int k0 = (kt) * 32;                                                        \
        uint32_t dL = sb + (buf) * GTSB + ((uint32_t)rowL * 40 + kcL) * 2;         \
        size_t aoL = (size_t)arowL * Ktot + k0 + kcL;                              \
        size_t boL = (size_t)(n0 + rowL) * Ktot + k0 + kcL;                        \
        cp_async16(dL,           Ahi + aoL, aszL);                                 \
        cp_async16(dL + GO_AL,   Alo + aoL, aszL);                                 \
        cp_async16(dL + GO_BHA,  BhA + boL, 16);                                   \
        cp_async16(dL + GO_BLA,  BlA + boL, 16);                                   \
        cp_async16(dL + GO_BHB,  BhB + boL, 16);                                   \
        cp_async16(dL + GO_BLB,  BlB + boL, 16);                                   \
    } while (0)

    GLOAD(0, 0);
    CP_COMMIT();

#pragma unroll 1
    for (int kt = 0; kt < KT; kt++) {
        int buf = kt & 1;
        CP_WAIT0();
        __syncthreads();
        if (kt + 1 < KT) {
            GLOAD(kt + 1, buf ^ 1);
            CP_COMMIT();
        }
#pragma unroll
        for (int ks = 0; ks < 2; ks++) {
            int kc = ks * 16 + lcol;
            uint32_t ah[2][4], al[2][4];
#pragma unroll
            for (int mt = 0; mt < 2; mt++) {
                int r = warp_m * 32 + mt * 16 + lrow;
                uint32_t addr = sb + buf * GTSB + ((uint32_t)r * 40 + kc) * 2;
                ldsm4(ah[mt], addr);
                ldsm4(al[mt], addr + GO_AL);
            }
#pragma unroll
            for (int mat = 0; mat < 2; mat++) {
                uint32_t boff = mat ? GO_BHB : GO_BHA;
#pragma unroll
                for (int ng = 0; ng < 2; ng++) {
                    int r = warp_n * 32 + ng * 16 + lrow;
                    uint32_t baddr = sb + buf * GTSB + ((uint32_t)r * 40 + kc) * 2 + boff;
                    uint32_t bh[4], bl[4];
                    ldsm4(bh, baddr);
                    ldsm4(bl, baddr + 10240);   // lo sits 10240 after hi for both mats
#pragma unroll
                    for (int mt = 0; mt < 2; mt++) {
                        mma16816(accf[mat][mt][2 * ng],     ah[mt], bh[0], bh[2]);
                        mma16816(accf[mat][mt][2 * ng],     ah[mt], bl[0], bl[2]);
                        mma16816(accf[mat][mt][2 * ng],     al[mt], bh[0], bh[2]);
                        mma16816(accf[mat][mt][2 * ng + 1], ah[mt], bh[1], bh[3]);
                        mma16816(accf[mat][mt][2 * ng + 1], ah[mt], bl[1], bl[3]);
                        mma16816(accf[mat][mt][2 * ng + 1], al[mt], bh[1], bh[3]);
                    }
                }
            }
        }
    }

    // ---- fused GLU epilogue ----
    int gi = lane >> 2;
    int ci = (lane & 3) * 2;
#pragma unroll
    for (int mt = 0; mt < 2; mt++) {
#pragma unroll
        for (int nt = 0; nt < 4; nt++) {
            int col = n0 + warp_n * 32 + nt * 8 + ci;
            float ba0 = __ldg(&biasA[col]), ba1 = __ldg(&biasA[col + 1]);
            float bb0 = __ldg(&biasB[col]), bb1 = __ldg(&biasB[col + 1]);
#pragma unroll
            for (int half = 0; half < 2; half++) {
                int row = m0 + warp_m * 32 + mt * 16 + gi + half * 8;
                if (row >= M) continue;
                float ga0 = accf[0][mt][nt][half * 2]     + ba0;
                float ga1 = accf[0][mt][nt][half * 2 + 1] + ba1;
                float gb0 = accf[1][mt][nt][half * 2]     + bb0;
                float gb1 = accf[1][mt][nt][half * 2 + 1] + bb1;
                float h0 = ga0 * (1.f / (1.f + __expf(-gb0)));
                float h1 = ga1 * (1.f / (1.f + __expf(-gb1)));
                size_t o = (size_t)row * HDIM + col;
                *(float2*)(Hout + o) = make_float2(h0, h1);
                if (Hhi) {
                    __nv_bfloat16 hh0, hl0, hh1, hl1;
                    split_bf16(h0, hh0, hl0);
                    split_bf16(h1, hh1, hl1);
                    __nv_bfloat162 hv; hv.x = hh0; hv.y = hh1;
                    __nv_bfloat162 lv; lv.x = hl0; lv.y = hl1;
                    *(__nv_bfloat162*)(Hhi + o) = hv;
                    *(__nv_bfloat162*)(Hlo + o) = lv;
                }
            }
        }
    }
#undef GLOAD
}

// ---------------- small fp32 GEMM for the F1 fold (M=118) --------------------
__global__ __launch_bounds__(256, 2)
void sgemm_pair(const float* __restrict__ A, int M,
                const float* __restrict__ B0, const float* __restrict__ B1,
                float* __restrict__ C0, float* __restrict__ C1,
                const float* __restrict__ bias0, const float* __restrict__ bias1) {
    const float* B    = blockIdx.z ? B1 : B0;
    float*       C    = blockIdx.z ? C1 : C0;
    const float* bias = blockIdx.z ? bias1 : bias0;
    __shared__ float As[2][16][132];
    __shared__ float Bs[2][16][128];
    int tid = threadIdx.x;
    int m0 = blockIdx.x * 128;
    int n0 = blockIdx.y * 128;
    int tx = tid & 15, ty = tid >> 4;
    int ar = tid >> 2;
    int ac = (tid & 3) * 4;
    int bk = tid >> 5;
    int bn = (tid & 31) * 4;
    bool aval0 = (m0 + ar) < M;
    bool aval1 = (m0 + ar + 64) < M;
    const float* Arow0 = A + (size_t)(m0 + ar) * HDIM + ac;
    const float* Arow1 = A + (size_t)(m0 + ar + 64) * HDIM + ac;
    const float* Bp0 = B + (size_t)bk * HDIM + n0 + bn;
    const float* Bp1 = B + (size_t)(bk + 8) * HDIM + n0 + bn;
    float4 af0, af1, bf0, bf1;
    const float4 fz = make_float4(0.f, 0.f, 0.f, 0.f);
#define LOADG(k0) do { \
        af0 = aval0 ? *(const float4*)(Arow0 + (k0)) : fz; \
        af1 = aval1 ? *(const float4*)(Arow1 + (k0)) : fz; \
        bf0 = *(const float4*)(Bp0 + (size_t)(k0) * HDIM); \
        bf1 = *(const float4*)(Bp1 + (size_t)(k0) * HDIM); } while (0)
#define STORES(bufi) do { \
        As[bufi][ac + 0][ar] = af0.x; As[bufi][ac + 1][ar] = af0.y; \
        As[bufi][ac + 2][ar] = af0.z; As[bufi][ac + 3][ar] = af0.w; \
        As[bufi][ac + 0][ar + 64] = af1.x; As[bufi][ac + 1][ar + 64] = af1.y; \
        As[bufi][ac + 2][ar + 64] = af1.z; As[bufi][ac + 3][ar + 64] = af1.w; \
        *(float4*)&Bs[bufi][bk][bn] = bf0; *(float4*)&Bs[bufi][bk + 8][bn] = bf1; } while (0)
    float acc[8][8];
#pragma unroll
    for (int i = 0; i < 8; i++)
#pragma unroll
        for (int j = 0; j < 8; j++) acc[i][j] = 0.f;
    LOADG(0);
    STORES(0);
    __syncthreads();
    int buf = 0;
#pragma unroll 1
    for (int kt = 0; kt < 16; kt++) {
        if (kt < 15) LOADG((kt + 1) * 16);
#pragma unroll
        for (int k = 0; k < 16; k++) {
            float4 a0 = *(const float4*)&As[buf][k][ty * 8];
            float4 a1 = *(const float4*)&As[buf][k][ty * 8 + 4];
            float4 b0 = *(const float4*)&Bs[buf][k][tx * 8];
            float4 b1 = *(const float4*)&Bs[buf][k][tx * 8 + 4];
            float a[8] = {a0.x, a0.y, a0.z, a0.w, a1.x, a1.y, a1.z, a1.w};
            float b[8] = {b0.x, b0.y, b0.z, b0.w, b1.x, b1.y, b1.z, b1.w};
#pragma unroll
            for (int i = 0; i < 8; i++)
#pragma unroll
                for (int j = 0; j < 8; j++)
                    acc[i][j] += a[i] * b[j];
        }
        if (kt < 15) { STORES(buf ^ 1); __syncthreads(); buf ^= 1; }
    }
    float bv[8];
#pragma unroll
    for (int j = 0; j < 8; j++) bv[j] = bias ? bias[n0 + tx * 8 + j] : 0.f;
#pragma unroll
    for (int i = 0; i < 8; i++) {
        int mm = m0 + ty * 8 + i;
        if (mm >= M) continue;
        float* Cp = C + (size_t)mm * HDIM + n0 + tx * 8;
        *(float4*)Cp = make_float4(acc[i][0] + bv[0], acc[i][1] + bv[1],
                                   acc[i][2] + bv[2], acc[i][3] + bv[3]);
        *(float4*)(Cp + 4) = make_float4(acc[i][4] + bv[4], acc[i][5] + bv[5],
                                         acc[i][6] + bv[6], acc[i][7] + bv[7]);
    }
#undef LOADG
#undef STORES
}

// ---------------- launcher ---------------------------------------------------
extern "C" void kernel_launch(void* const* d_in, const int* in_sizes, int n_in,
                              void* d_out, int out_size) {
    const float* atomic_num = (const float*)d_in[0];
    const float* coord      = (const float*)d_in[1];
    const float* radius     = (const float*)d_in[2];
    const int*   src        = (const int*)  d_in[3];
    const int*   dst        = (const int*)  d_in[4];
    const int*   abs_mask   = (const int*)  d_in[5];
    const int*   graph_id   = (const int*)  d_in[6];
    const float* W_atom     = (const float*)d_in[7];
    const float* b_atom     = (const float*)d_in[8];
    const float* W_coord    = (const float*)d_in[9];
    const float* b_coord    = (const float*)d_in[10];
    const float* W_node     = (const float*)d_in[11];
    const float* b_node     = (const float*)d_in[12];
    const float* W_edge     = (const float*)d_in[13];
    const float* b_edge     = (const float*)d_in[14];
    const float* W_agg      = (const float*)d_in[15];
    const float* b_agg      = (const float*)d_in[16];
    const float* W_glu_a    = (const float*)d_in[17];
    const float* b_glu_a    = (const float*)d_in[18];
    const float* W_glu_b    = (const float*)d_in[19];
    const float* b_glu_b    = (const float*)d_in[20];
    const float* exp_l      = (const float*)d_in[21];
    const float* eps_l      = (const float*)d_in[22];
    const float* W_mlp      = (const float*)d_in[23];
    const float* b_mlp      = (const float*)d_in[24];
    float* out = (float*)d_out;

    int N = in_sizes[5];
    int E = in_sizes[2];

    float *p_h, *p_hd, *p_F1;
    __nv_bfloat16 *p_xh, *p_xl, *p_hh, *p_hl, *p_rh, *p_rl, *p_sh, *p_Bh, *p_Bl, *p_Fh, *p_Fl;
    cudaGetSymbolAddress((void**)&p_h,   g_h);
    cudaGetSymbolAddress((void**)&p_hd,  g_hd);
    cudaGetSymbolAddress((void**)&p_F1,  g_F1);
    cudaGetSymbolAddress((void**)&p_xh,  g_xa_hi);
    cudaGetSymbolAddress((void**)&p_xl,  g_xa_lo);
    cudaGetSymbolAddress((void**)&p_hh,  g_h_hi);
    cudaGetSymbolAddress((void**)&p_hl,  g_h_lo);
    cudaGetSymbolAddress((void**)&p_rh,  g_r_hi);
    cudaGetSymbolAddress((void**)&p_rl,  g_r_lo);
    cudaGetSymbolAddress((void**)&p_sh,  g_s_hi);
    cudaGetSymbolAddress((void**)&p_Bh,  g_Bt_hi);
    cudaGetSymbolAddress((void**)&p_Bl,  g_Bt_lo);
    cudaGetSymbolAddress((void**)&p_Fh,  g_F1t_hi);
    cudaGetSymbolAddress((void**)&p_Fl,  g_F1t_lo);

    const int MMA_SMEM = 81920;
    const int GLU_SMEM = 2 * GTSB;
    cudaFuncSetAttribute(mma_gemm, cudaFuncAttributeMaxDynamicSharedMemorySize, MMA_SMEM);
    cudaFuncSetAttribute(mma_glu,  cudaFuncAttributeMaxDynamicSharedMemorySize, GLU_SMEM);

    int mtiles = (N + 127) / 128;
    int eb = (E + 255) / 256;
    int nhb = (N * HDIM + 255) / 256;
    int aggb = (N + 7) / 8;

    // CSR build
    zero_pre_kernel<<<80, 256>>>(N);
    hist_kernel<<<eb, 256>>>(dst, E);
    scan_kernel<<<1, 1024>>>(N);
    fill_kernel<<<eb, 256>>>(dst, E);

    // folds + conversions
    sgemm_pair<<<dim3(1, 2, 1), 256>>>(W_atom, ATOMD, W_node, W_node, p_F1, p_F1,
                                       nullptr, nullptr);
    fold_small_kernel<<<1, HDIM>>>(W_coord, W_node, b_atom, b_coord, b_node);
    coord_init_kernel<<<nhb, 256>>>(coord, N);
    conv_x_kernel<<<(N * 128 + 255) / 256, 256>>>(atomic_num, N);
    conv_F1t_kernel<<<(HDIM * 128 + 255) / 256, 256>>>();
    conv_wT_kernel<<<dim3(HH / 256, 8, 1), 256>>>(W_agg, W_glu_a, W_glu_b);
    uv_kernel<<<2, HDIM>>>(W_agg, W_edge, b_edge, b_agg);

    // init: h = x@F1 + coordpart; write h fp32 + hi/lo
    mma_gemm<<<dim3(mtiles, 2, 1), 256, MMA_SMEM>>>(
        p_xh, p_xl, N, 128, p_Fh, p_Fl, p_Fh, p_Fl,
        p_h, p_h, p_hd,
        p_hh, p_hl, p_hh, p_hl);

    for (int l = 0; l < 2; l++) {
        // z=0: hs (bf16 hi only); z=1: hd (fp32 only)
        mma_gemm<<<dim3(mtiles, 2, 2), 256, MMA_SMEM>>>(
            p_hh, p_hl, N, HDIM,
            p_Bh + (size_t)(2 * l) * HH,     p_Bl + (size_t)(2 * l) * HH,
            p_Bh + (size_t)(2 * l + 1) * HH, p_Bl + (size_t)(2 * l + 1) * HH,
            nullptr, p_hd, nullptr,
            p_sh, nullptr, nullptr, nullptr);
        agg_kernel<<<aggb, 256>>>(src, radius, exp_l, eps_l, l, N);
        // fused GLU GEMM: h = (rst@Wa+ba) * sigmoid(rst@Wb+bb)
        mma_glu<<<dim3(mtiles, 2, 1), 512, GLU_SMEM>>>(
            p_rh, p_rl, N,
            p_Bh + (size_t)(4 + 2 * l) * HH, p_Bl + (size_t)(4 + 2 * l) * HH,
            p_Bh + (size_t)(5 + 2 * l) * HH, p_Bl + (size_t)(5 + 2 * l) * HH,
            b_glu_a + l * HDIM, b_glu_b + l * HDIM,
            p_h,
            (l == 0) ? p_hh : nullptr, (l == 0) ? p_hl : nullptr);
    }

    segsum_kernel<<<(N + 127) / 128, HDIM>>>(abs_mask, graph_id, N);
    mlp_kernel<<<GN, 128>>>(W_mlp, b_mlp, out, 1.0f / (float)N);
}

// round 12
// speedup vs baseline: 1.1964x; 1.1964x over previous
#include <cuda_runtime.h>
#include <cuda_fp16.h>
#include <stdint.h>
#include <cstdint>
#include <math.h>

#define N_NODES 20000
#define N_EDGES 640000
#define HDIM    256
#define GN      16
#define OUTD    100
#define ATOMD   118
#define HH      (HDIM * HDIM)

// ---------------- scratch ----------------------------------------------------
__device__ __align__(16) float g_hd32[N_NODES * HDIM];   // coord addend (init only)
__device__ __align__(16) float g_uv [2 * 2 * HDIM];      // [layer][u|vp]
__device__ __align__(16) float g_F1 [ATOMD * HDIM];
__device__ __align__(16) float g_F2 [3 * HDIM];
__device__ __align__(16) float g_bf [HDIM];
__device__ __align__(16) float g_feat[GN * HDIM];
__device__ int   g_cnt [N_NODES + 1];
__device__ int   g_offs[N_NODES + 1];
__device__ int   g_wp  [N_NODES];
__device__ int   g_csr [N_EDGES];
// fp16 activations (single precision level, 2^-11)
__device__ __align__(16) __half g_xa [N_NODES * 128];
__device__ __align__(16) __half g_hf [N_NODES * HDIM];   // h
__device__ __align__(16) __half g_s  [N_NODES * HDIM];   // hs (gather src)
__device__ __align__(16) __half g_hdh[N_NODES * HDIM];   // hd
__device__ __align__(16) __half g_r  [N_NODES * HDIM];   // rst
__device__ __align__(16) __half g_ga [N_NODES * HDIM];
__device__ __align__(16) __half g_gb [N_NODES * HDIM];
// fp16 split weights (hi+lo = exact to 2^-22)
__device__ __align__(16) __half g_Bt_hi[8 * HH];
__device__ __align__(16) __half g_Bt_lo[8 * HH];
__device__ __align__(16) __half g_F1t_hi[HDIM * 128];
__device__ __align__(16) __half g_F1t_lo[HDIM * 128];

// ---------------- PTX helpers (all sm_80-legal) ------------------------------
__device__ __forceinline__ uint32_t smem_to_u32(const void* p) {
    uint32_t a;
    asm("{ .reg .u64 t; cvta.to.shared.u64 t, %1; cvt.u32.u64 %0, t; }" : "=r"(a) : "l"(p));
    return a;
}
__device__ __forceinline__ void ldsm4(uint32_t* r, uint32_t addr) {
    asm volatile("ldmatrix.sync.aligned.m8n8.x4.shared.b16 {%0,%1,%2,%3}, [%4];"
                 : "=r"(r[0]), "=r"(r[1]), "=r"(r[2]), "=r"(r[3]) : "r"(addr));
}
__device__ __forceinline__ void mma16816(float* c, const uint32_t* a, uint32_t b0, uint32_t b1) {
    asm volatile("mma.sync.aligned.m16n8k16.row.col.f32.f16.f16.f32 "
                 "{%0,%1,%2,%3}, {%4,%5,%6,%7}, {%8,%9}, {%0,%1,%2,%3};"
                 : "+f"(c[0]), "+f"(c[1]), "+f"(c[2]), "+f"(c[3])
                 : "r"(a[0]), "r"(a[1]), "r"(a[2]), "r"(a[3]), "r"(b0), "r"(b1));
}
__device__ __forceinline__ void cp_async16(uint32_t d, const void* s, int src_sz) {
    asm volatile("cp.async.cg.shared.global [%0], [%1], 16, %2;"
                 :: "r"(d), "l"(s), "r"(src_sz) : "memory");
}
#define CP_COMMIT() asm volatile("cp.async.commit_group;" ::: "memory")
#define CP_WAIT0()  asm volatile("cp.async.wait_group 0;" ::: "memory")

// ---------------- CSR build --------------------------------------------------
__global__ void zero_pre_kernel(int N) {
    int stride = gridDim.x * blockDim.x;
    int i = blockIdx.x * blockDim.x + threadIdx.x;
    for (int t = i; t < N + 1; t += stride) g_cnt[t] = 0;
    for (int t = i; t < GN * HDIM; t += stride) g_feat[t] = 0.f;
}
__global__ void hist_kernel(const int* __restrict__ dst, int E) {
    int e = blockIdx.x * blockDim.x + threadIdx.x;
    if (e < E) atomicAdd(&g_cnt[dst[e]], 1);
}
__global__ void scan_kernel(int N) {
    __shared__ int partial[1024];
    int t = threadIdx.x;
    int per = (N + 1023) / 1024;
    int start = t * per;
    int stop  = min(start + per, N);
    int sum = 0;
    for (int i = start; i < stop; i++) sum += g_cnt[i];
    partial[t] = sum;
    __syncthreads();
    for (int d = 1; d < 1024; d <<= 1) {
        int v = (t >= d) ? partial[t - d] : 0;
        __syncthreads();
        partial[t] += v;
        __syncthreads();
    }
    int run = (t == 0) ? 0 : partial[t - 1];
    for (int i = start; i < stop; i++) {
        g_offs[i] = run;
        g_wp[i]   = run;
        run += g_cnt[i];
    }
    if (t == 1023) g_offs[N] = partial[1023];
}
__global__ void fill_kernel(const int* __restrict__ dst, int E) {
    int e = blockIdx.x * blockDim.x + threadIdx.x;
    if (e < E) {
        int pos = atomicAdd(&g_wp[dst[e]], 1);
        g_csr[pos] = e;
    }
}

// ---------------- weight folding / conversions -------------------------------
__global__ void fold_small_kernel(const float* __restrict__ Wc,
                                  const float* __restrict__ Wn,
                                  const float* __restrict__ ba,
                                  const float* __restrict__ bc,
                                  const float* __restrict__ bn) {
    int j = threadIdx.x;
    float f0 = 0.f, f1 = 0.f, f2 = 0.f, bias = 0.f;
    for (int h = 0; h < HDIM; h++) {
        float wtop = Wn[h * HDIM + j];
        float wbot = Wn[(HDIM + h) * HDIM + j];
        f0 += Wc[0 * HDIM + h] * wbot;
        f1 += Wc[1 * HDIM + h] * wbot;
        f2 += Wc[2 * HDIM + h] * wbot;
        bias += ba[h] * wtop + bc[h] * wbot;
    }
    g_F2[0 * HDIM + j] = f0;
    g_F2[1 * HDIM + j] = f1;
    g_F2[2 * HDIM + j] = f2;
    g_bf[j] = bias + bn[j];
}

__global__ void coord_init_kernel(const float* __restrict__ coord, int N) {
    int idx = blockIdx.x * blockDim.x + threadIdx.x;
    if (idx >= N * HDIM) return;
    int n = idx >> 8;
    int j = idx & 255;
    float c0 = coord[n * 3], c1 = coord[n * 3 + 1], c2 = coord[n * 3 + 2];
    g_hd32[idx] = c0 * g_F2[j] + c1 * g_F2[HDIM + j] + c2 * g_F2[2 * HDIM + j] + g_bf[j];
}

__device__ __forceinline__ void split_h16(float v, __half& hi, __half& lo) {
    hi = __float2half(v);
    lo = __float2half(v - __half2float(hi));
}

__global__ void conv_x_kernel(const float* __restrict__ x, int N) {
    int e = blockIdx.x * blockDim.x + threadIdx.x;
    if (e >= N * 128) return;
    int n = e >> 7, kk = e & 127;
    float v = (kk < ATOMD) ? x[n * ATOMD + kk] : 0.f;
    g_xa[e] = __float2half(v);
}

__global__ void conv_wT_kernel(const float* __restrict__ W_agg,
                               const float* __restrict__ W_glu_a,
                               const float* __restrict__ W_glu_b) {
    int z = blockIdx.y;
    const float* src;
    switch (z) {
        case 0: src = W_agg; break;
        case 1: src = W_agg + 2 * HH; break;
        case 2: src = W_agg + 3 * HH; break;
        case 3: src = W_agg + 5 * HH; break;
        case 4: src = W_glu_a; break;
        case 5: src = W_glu_b; break;
        case 6: src = W_glu_a + HH; break;
        default: src = W_glu_b + HH; break;
    }
    int e = blockIdx.x * blockDim.x + threadIdx.x;
    int n = e >> 8, k = e & 255;
    float v = src[k * HDIM + n];
    __half hi, lo;
    split_h16(v, hi, lo);
    g_Bt_hi[z * HH + e] = hi;
    g_Bt_lo[z * HH + e] = lo;
}

__global__ void conv_F1t_kernel() {
    int e = blockIdx.x * blockDim.x + threadIdx.x;
    if (e >= HDIM * 128) return;
    int n = e >> 7, k = e & 127;
    float v = (k < ATOMD) ? g_F1[k * HDIM + n] : 0.f;
    __half hi, lo;
    split_h16(v, hi, lo);
    g_F1t_hi[e] = hi;
    g_F1t_lo[e] = lo;
}

__global__ void uv_kernel(const float* __restrict__ W_agg,
                          const float* __restrict__ Wedge,
                          const float* __restrict__ bedge,
                          const float* __restrict__ b_agg) {
    int l = blockIdx.x;
    int j = threadIdx.x;
    const float* We = W_agg + (size_t)l * 3 * HH + HH;
    float u = 0.f, v = 0.f;
    for (int k = 0; k < HDIM; k++) {
        float we = We[k * HDIM + j];
        u += Wedge[k] * we;
        v += bedge[k] * we;
    }
    g_uv[l * 2 * HDIM + j] = u;
    g_uv[l * 2 * HDIM + HDIM + j] = v + b_agg[l * HDIM + j];
}

// ---------------- warp-per-node aggregation (fp16 gather) --------------------
__global__ void agg_kernel(const int* __restrict__ src,
                           const float* __restrict__ radius,
                           const float* __restrict__ exp_l,
                           const float* __restrict__ eps_l, int l, int N) {
    int warp = (blockIdx.x * blockDim.x + threadIdx.x) >> 5;
    int lane = threadIdx.x & 31;
    if (warp >= N) return;
    float el = __ldg(&exp_l[l]);
    const float* uvb = g_uv + l * 2 * HDIM;
    int beg = g_offs[warp], end = g_offs[warp + 1];
    float4 acc0 = make_float4(0.f, 0.f, 0.f, 0.f);
    float4 acc1 = make_float4(0.f, 0.f, 0.f, 0.f);
    float s1 = 0.f, swr = 0.f;
    int j0 = lane * 8;
    for (int base = beg; base < end; base += 32) {
        int p = base + lane;
        int s = 0;
        float w = 0.f;
        if (p < end) {
            int e = g_csr[p];
            s = src[e];
            float r = radius[e];
            w = __expf(__logf(r) * el);
            s1 += w;
            swr += w * r;
        }
        int cnt = min(32, end - base);
        for (int q = 0; q < cnt; q++) {
            int   sq = __shfl_sync(0xffffffffu, s, q);
            float wq = __shfl_sync(0xffffffffu, w, q);
            uint4 pv = *(const uint4*)(g_s + (size_t)sq * HDIM + j0);
            float2 f0 = __half22float2(*(__half2*)&pv.x);
            float2 f1 = __half22float2(*(__half2*)&pv.y);
            float2 f2 = __half22float2(*(__half2*)&pv.z);
            float2 f3 = __half22float2(*(__half2*)&pv.w);
            acc0.x += wq * f0.x; acc0.y += wq * f0.y;
            acc0.z += wq * f1.x; acc0.w += wq * f1.y;
            acc1.x += wq * f2.x; acc1.y += wq * f2.y;
            acc1.z += wq * f3.x; acc1.w += wq * f3.y;
        }
    }
#pragma unroll
    for (int off = 16; off; off >>= 1) {
        s1  += __shfl_xor_sync(0xffffffffu, s1, off);
        swr += __shfl_xor_sync(0xffffffffu, swr, off);
    }
    float ep = 1.f + __ldg(&eps_l[l]);
    float4 u0  = *(const float4*)(uvb + j0);
    float4 u1  = *(const float4*)(uvb + j0 + 4);
    float4 vp0 = *(const float4*)(uvb + HDIM + j0);
    float4 vp1 = *(const float4*)(uvb + HDIM + j0 + 4);
    size_t idx = (size_t)warp * HDIM + j0;
    uint4 hv = *(const uint4*)(g_hf + idx);
    uint4 dv = *(const uint4*)(g_hdh + idx);
    float2 h01 = __half22float2(*(__half2*)&hv.x);
    float2 h23 = __half22float2(*(__half2*)&hv.y);
    float2 h45 = __half22float2(*(__half2*)&hv.z);
    float2 h67 = __half22float2(*(__half2*)&hv.w);
    float2 d01 = __half22float2(*(__half2*)&dv.x);
    float2 d23 = __half22float2(*(__half2*)&dv.y);
    float2 d45 = __half22float2(*(__half2*)&dv.z);
    float2 d67 = __half22float2(*(__half2*)&dv.w);
    float v[8];
    v[0] = ep * h01.x + acc0.x + s1 * (d01.x + vp0.x) + swr * u0.x;
    v[1] = ep * h01.y + acc0.y + s1 * (d01.y + vp0.y) + swr * u0.y;
    v[2] = ep * h23.x + acc0.z + s1 * (d23.x + vp0.z) + swr * u0.z;
    v[3] = ep * h23.y + acc0.w + s1 * (d23.y + vp0.w) + swr * u0.w;
    v[4] = ep * h45.x + acc1.x + s1 * (d45.x + vp1.x) + swr * u1.x;
    v[5] = ep * h45.y + acc1.y + s1 * (d45.y + vp1.y) + swr * u1.y;
    v[6] = ep * h67.x + acc1.z + s1 * (d67.x + vp1.z) + swr * u1.z;
    v[7] = ep * h67.y + acc1.w + s1 * (d67.y + vp1.w) + swr * u1.w;
    uint4 rv;
    *(__half2*)&rv.x = __float22half2_rn(make_float2(v[0], v[1]));
    *(__half2*)&rv.y = __float22half2_rn(make_float2(v[2], v[3]));
    *(__half2*)&rv.z = __float22half2_rn(make_float2(v[4], v[5]));
    *(__half2*)&rv.w = __float22half2_rn(make_float2(v[6], v[7]));
    *(uint4*)(g_r + idx) = rv;
}

// layer-0 GLU: h = ga * sigmoid(gb), fp16 in/out (half2 vectorized)
__global__ void glu_kernel(int N) {
    int i = blockIdx.x * blockDim.x + threadIdx.x;
    if (i >= N * HDIM / 2) return;
    float2 ga = __half22float2(((const __half2*)g_ga)[i]);
    float2 gb = __half22float2(((const __half2*)g_gb)[i]);
    float h0 = ga.x * (1.f / (1.f + __expf(-gb.x)));
    float h1 = ga.y * (1.f / (1.f + __expf(-gb.y)));
    ((__half2*)g_hf)[i] = __float22half2_rn(make_float2(h0, h1));
}

// last layer: fused GLU + masked segment-sum from fp16 ga/gb
__global__ void glu_segsum_kernel(const int* __restrict__ mask,
                                  const int* __restrict__ gid, int N) {
    int j  = threadIdx.x;
    int n0 = blockIdx.x * 128;
    if (n0 >= N) return;
    int n1 = min(n0 + 128, N);
    float acc = 0.f;
    int curg = gid[n0];
    for (int n = n0; n < n1; n++) {
        int g = gid[n];
        if (g != curg) {
            atomicAdd(&g_feat[curg * HDIM + j], acc);
            acc = 0.f;
            curg = g;
        }
        if (mask[n]) {
            size_t o = (size_t)n * HDIM + j;
            float ga = __half2float(g_ga[o]);
            float gb = __half2float(g_gb[o]);
            acc += ga * (1.f / (1.f + __expf(-gb)));
        }
    }
    atomicAdd(&g_feat[curg * HDIM + j], acc);
}

__global__ void mlp_kernel(const float* __restrict__ Wm,
                           const float* __restrict__ bm,
                           float* __restrict__ out, float invN) {
    int g = blockIdx.x;
    int o = threadIdx.x;
    if (o >= OUTD) return;
    float s = 0.f;
    for (int j = 0; j < HDIM; j++)
        s += g_feat[g * HDIM + j] * Wm[j * OUTD + o];
    s = s * invN + bm[o];
    out[g * OUTD + o] = 1.f / (1.f + __expf(-s));
}

// ---------------- mma.sync fp16 2-term GEMM (256 thr, 32x64 warp tiles) ------
// C[M,256] = A @ (Bhi+Blo)^T ; A fp16 (single), B split fp16 hi/lo.
// SMEM per stage: A(10240) + Bh(10240) + Bl(10240) = 30720; 2 stages = 61440.
#define STSZ   30720
#define SOFF_BH 10240
#define SOFF_BL 20480

__global__ __launch_bounds__(256, 2)
void mma_gemm(const __half* __restrict__ A, int M, int Ktot,
              const __half* __restrict__ Bh0, const __half* __restrict__ Bl0,
              const __half* __restrict__ Bh1, const __half* __restrict__ Bl1,
              const float* __restrict__ bias0, const float* __restrict__ bias1,
              const float* __restrict__ addend,
              __half* __restrict__ H0, __half* __restrict__ H1) {
    extern __shared__ char smem[];
    const __half* Bhi = blockIdx.z ? Bh1 : Bh0;
    const __half* Blo = blockIdx.z ? Bl1 : Bl0;
    const float* bias = blockIdx.z ? bias1 : bias0;
    __half* Hout = blockIdx.z ? H1 : H0;

    int tid = threadIdx.x;
    int wid = tid >> 5;
    int lane = tid & 31;
    int warp_m = wid & 3;
    int warp_n = wid >> 2;
    int m0 = blockIdx.x * 128;
    int n0 = blockIdx.y * 128;
    uint32_t sb = smem_to_u32(smem);

    float acc[2][8][4];
#pragma unroll
    for (int a = 0; a < 2; a++)
#pragma unroll
        for (int b = 0; b < 8; b++)
#pragma unroll
            for (int c = 0; c < 4; c++) acc[a][b][c] = 0.f;

    int KT = Ktot >> 5;
    int lrow = (lane & 7) + ((lane >> 3) & 1) * 8;
    int lcol = (lane >> 4) * 8;

    int row0 = tid >> 2,         kc0 = (tid & 3) * 8;
    int row1 = (tid + 256) >> 2, kc1 = (tid & 3) * 8;
    int arow0 = (m0 + row0 < M) ? (m0 + row0) : 0;
    int arow1 = (m0 + row1 < M) ? (m0 + row1) : 0;
    int asz0  = (m0 + row0 < M) ? 16 : 0;
    int asz1  = (m0 + row1 < M) ? 16 : 0;

#define LOAD_STAGE(kt, buf)                                                        \
    do {                                                                           \
        int k0 = (kt) * 32;                                                        \
        uint32_t d0 = sb + (buf) * STSZ + ((uint32_t)row0 * 40 + kc0) * 2;         \
        uint32_t d1 = sb + (buf) * STSZ + ((uint32_t)row1 * 40 + kc1) * 2;         \
        size_t ao0 = (size_t)arow0 * Ktot + k0 + kc0;                              \
        size_t ao1 = (size_t)arow1 * Ktot + k0 + kc1;                              \
        size_t bo0 = (size_t)(n0 + row0) * Ktot + k0 + kc0;                        \
        size_t bo1 = (size_t)(n0 + row1) * Ktot + k0 + kc1;                        \
        cp_async16(d0,           A   + ao0, asz0);                                 \
        cp_async16(d0 + SOFF_BH, Bhi + bo0, 16);                                   \
        cp_async16(d0 + SOFF_BL, Blo + bo0, 16);                                   \
        cp_async16(d1,           A   + ao1, asz1);                                 \
        cp_async16(d1 + SOFF_BH, Bhi + bo1, 16);                                   \
        cp_async16(d1 + SOFF_BL, Blo + bo1, 16);                                   \
    } while (0)

    LOAD_STAGE(0, 0);
    CP_COMMIT();

#pragma unroll 1
    for (int kt = 0; kt < KT; kt++) {
        int buf = kt & 1;
        CP_WAIT0();
        __syncthreads();
        if (kt + 1 < KT) {
            LOAD_STAGE(kt + 1, buf ^ 1);
            CP_COMMIT();
        }
#pragma unroll
        for (int ks = 0; ks < 2; ks++) {
            int kc = ks * 16 + lcol;
            uint32_t ah[2][4];
#pragma unroll
            for (int mt = 0; mt < 2; mt++) {
                int r = warp_m * 32 + mt * 16 + lrow;
                ldsm4(ah[mt], sb + buf * STSZ + ((uint32_t)r * 40 + kc) * 2);
            }
#pragma unroll
            for (int ng = 0; ng < 4; ng++) {
                int r = warp_n * 64 + ng * 16 + lrow;
                uint32_t baddr = sb + buf * STSZ + ((uint32_t)r * 40 + kc) * 2 + SOFF_BH;
                uint32_t bh[4], bl[4];
                ldsm4(bh, baddr);
                ldsm4(bl, baddr + (SOFF_BL - SOFF_BH));
#pragma unroll
                for (int mt = 0; mt < 2; mt++) {
                    mma16816(acc[mt][2 * ng],     ah[mt], bh[0], bh[2]);
                    mma16816(acc[mt][2 * ng],     ah[mt], bl[0], bl[2]);
                    mma16816(acc[mt][2 * ng + 1], ah[mt], bh[1], bh[3]);
                    mma16816(acc[mt][2 * ng + 1], ah[mt], bl[1], bl[3]);
                }
            }
        }
    }

    // ---- epilogue: fp16 output, optional bias / fp32 addend ----
    int gi = lane >> 2;
    int ci = (lane & 3) * 2;
#pragma unroll
    for (int mt = 0; mt < 2; mt++) {
#pragma unroll
        for (int nt = 0; nt < 8; nt++) {
            float* a4 = acc[mt][nt];
            int col = n0 + warp_n * 64 + nt * 8 + ci;
            float b0 = 0.f, b1 = 0.f;
            if (bias) { b0 = __ldg(&bias[col]); b1 = __ldg(&bias[col + 1]); }
#pragma unroll
            for (int half_ = 0; half_ < 2; half_++) {
                int row = m0 + warp_m * 32 + mt * 16 + gi + half_ * 8;
                if (row >= M) continue;
                float v0 = a4[half_ * 2]     + b0;
                float v1 = a4[half_ * 2 + 1] + b1;
                size_t o = (size_t)row * HDIM + col;
                if (addend) {
                    float2 t = *(const float2*)(addend + o);
                    v0 += t.x; v1 += t.y;
                }
                *(__half2*)(Hout + o) = __float22half2_rn(make_float2(v0, v1));
            }
        }
    }
#undef LOAD_STAGE
}

// ---------------- small fp32 GEMM for the F1 fold (M=118) --------------------
__global__ __launch_bounds__(256, 2)
void sgemm_pair(const float* __restrict__ A, int M,
                const float* __restrict__ B0, const float* __restrict__ B1,
                float* __restrict__ C0, float* __restrict__ C1,
                const float* __restrict__ bias0, const float* __restrict__ bias1) {
    const float* B    = blockIdx.z ? B1 : B0;
    float*       C    = blockIdx.z ? C1 : C0;
    const float* bias = blockIdx.z ? bias1 : bias0;
    __shared__ float As[2][16][132];
    __shared__ float Bs[2][16][128];
    int tid = threadIdx.x;
    int m0 = blockIdx.x * 128;
    int n0 = blockIdx.y * 128;
    int tx = tid & 15, ty = tid >> 4;
    int ar = tid >> 2;
    int ac = (tid & 3) * 4;
    int bk = tid >> 5;
    int bn = (tid & 31) * 4;
    bool aval0 = (m0 + ar) < M;
    bool aval1 = (m0 + ar + 64) < M;
    const float* Arow0 = A + (size_t)(m0 + ar) * HDIM + ac;
    const float* Arow1 = A + (size_t)(m0 + ar + 64) * HDIM + ac;
    const float* Bp0 = B + (size_t)bk * HDIM + n0 + bn;
    const float* Bp1 = B + (size_t)(bk + 8) * HDIM + n0 + bn;
    float4 af0, af1, bf0, bf1;
    const float4 fz = make_float4(0.f, 0.f, 0.f, 0.f);
#define LOADG(k0) do { \
        af0 = aval0 ? *(const float4*)(Arow0 + (k0)) : fz; \
        af1 = aval1 ? *(const float4*)(Arow1 + (k0)) : fz; \
        bf0 = *(const float4*)(Bp0 + (size_t)(k0) * HDIM); \
        bf1 = *(const float4*)(Bp1 + (size_t)(k0) * HDIM); } while (0)
#define STORES(bufi) do { \
        As[bufi][ac + 0][ar] = af0.x; As[bufi][ac + 1][ar] = af0.y; \
        As[bufi][ac + 2][ar] = af0.z; As[bufi][ac + 3][ar] = af0.w; \
        As[bufi][ac + 0][ar + 64] = af1.x; As[bufi][ac + 1][ar + 64] = af1.y; \
        As[bufi][ac + 2][ar + 64] = af1.z; As[bufi][ac + 3][ar + 64] = af1.w; \
        *(float4*)&Bs[bufi][bk][bn] = bf0; *(float4*)&Bs[bufi][bk + 8][bn] = bf1; } while (0)
    float acc[8][8];
#pragma unroll
    for (int i = 0; i < 8; i++)
#pragma unroll
        for (int j = 0; j < 8; j++) acc[i][j] = 0.f;
    LOADG(0);
    STORES(0);
    __syncthreads();
    int buf = 0;
#pragma unroll 1
    for (int kt = 0; kt < 16; kt++) {
        if (kt < 15) LOADG((kt + 1) * 16);
#pragma unroll
        for (int k = 0; k < 16; k++) {
            float4 a0 = *(const float4*)&As[buf][k][ty * 8];
            float4 a1 = *(const float4*)&As[buf][k][ty * 8 + 4];
            float4 b0 = *(const float4*)&Bs[buf][k][tx * 8];
            float4 b1 = *(const float4*)&Bs[buf][k][tx * 8 + 4];
            float a[8] = {a0.x, a0.y, a0.z, a0.w, a1.x, a1.y, a1.z, a1.w};
            float b[8] = {b0.x, b0.y, b0.z, b0.w, b1.x, b1.y, b1.z, b1.w};
#pragma unroll
            for (int i = 0; i < 8; i++)
#pragma unroll
                for (int j = 0; j < 8; j++)
                    acc[i][j] += a[i] * b[j];
        }
        if (kt < 15) { STORES(buf ^ 1); __syncthreads(); buf ^= 1; }
    }
    float bv[8];
#pragma unroll
    for (int j = 0; j < 8; j++) bv[j] = bias ? bias[n0 + tx * 8 + j] : 0.f;
#pragma unroll
    for (int i = 0; i < 8; i++) {
        int mm = m0 + ty * 8 + i;
        if (mm >= M) continue;
        float* Cp = C + (size_t)mm * HDIM + n0 + tx * 8;
        *(float4*)Cp = make_float4(acc[i][0] + bv[0], acc[i][1] + bv[1],
                                   acc[i][2] + bv[2], acc[i][3] + bv[3]);
        *(float4*)(Cp + 4) = make_float4(acc[i][4] + bv[4], acc[i][5] + bv[5],
                                         acc[i][6] + bv[6], acc[i][7] + bv[7]);
    }
#undef LOADG
#undef STORES
}

// ---------------- launcher ---------------------------------------------------
extern "C" void kernel_launch(void* const* d_in, const int* in_sizes, int n_in,
                              void* d_out, int out_size) {
    const float* atomic_num = (const float*)d_in[0];
    const float* coord      = (const float*)d_in[1];
    const float* radius     = (const float*)d_in[2];
    const int*   src        = (const int*)  d_in[3];
    const int*   dst        = (const int*)  d_in[4];
    const int*   abs_mask   = (const int*)  d_in[5];
    const int*   graph_id   = (const int*)  d_in[6];
    const float* W_atom     = (const float*)d_in[7];
    const float* b_atom     = (const float*)d_in[8];
    const float* W_coord    = (const float*)d_in[9];
    const float* b_coord    = (const float*)d_in[10];
    const float* W_node     = (const float*)d_in[11];
    const float* b_node     = (const float*)d_in[12];
    const float* W_edge     = (const float*)d_in[13];
    const float* b_edge     = (const float*)d_in[14];
    const float* W_agg      = (const float*)d_in[15];
    const float* b_agg      = (const float*)d_in[16];
    const float* W_glu_a    = (const float*)d_in[17];
    const float* b_glu_a    = (const float*)d_in[18];
    const float* W_glu_b    = (const float*)d_in[19];
    const float* b_glu_b    = (const float*)d_in[20];
    const float* exp_l      = (const float*)d_in[21];
    const float* eps_l      = (const float*)d_in[22];
    const float* W_mlp      = (const float*)d_in[23];
    const float* b_mlp      = (const float*)d_in[24];
    float* out = (float*)d_out;

    int N = in_sizes[5];
    int E = in_sizes[2];

    float *p_hd32, *p_F1;
    __half *p_xa, *p_hf, *p_s, *p_hdh, *p_r, *p_ga, *p_gb, *p_Bh, *p_Bl, *p_Fh, *p_Fl;
    cudaGetSymbolAddress((void**)&p_hd32, g_hd32);
    cudaGetSymbolAddress((void**)&p_F1,   g_F1);
    cudaGetSymbolAddress((void**)&p_xa,   g_xa);
    cudaGetSymbolAddress((void**)&p_hf,   g_hf);
    cudaGetSymbolAddress((void**)&p_s,    g_s);
    cudaGetSymbolAddress((void**)&p_hdh,  g_hdh);
    cudaGetSymbolAddress((void**)&p_r,    g_r);
    cudaGetSymbolAddress((void**)&p_ga,   g_ga);
    cudaGetSymbolAddress((void**)&p_gb,   g_gb);
    cudaGetSymbolAddress((void**)&p_Bh,   g_Bt_hi);
    cudaGetSymbolAddress((void**)&p_Bl,   g_Bt_lo);
    cudaGetSymbolAddress((void**)&p_Fh,   g_F1t_hi);
    cudaGetSymbolAddress((void**)&p_Fl,   g_F1t_lo);

    const int MMA_SMEM = 2 * STSZ;
    cudaFuncSetAttribute(mma_gemm, cudaFuncAttributeMaxDynamicSharedMemorySize, MMA_SMEM);

    int mtiles = (N + 127) / 128;
    int eb = (E + 255) / 256;
    int nhb = (N * HDIM + 255) / 256;
    int aggb = (N + 7) / 8;

    // CSR build
    zero_pre_kernel<<<80, 256>>>(N);
    hist_kernel<<<eb, 256>>>(dst, E);
    scan_kernel<<<1, 1024>>>(N);
    fill_kernel<<<eb, 256>>>(dst, E);

    // folds + conversions
    sgemm_pair<<<dim3(1, 2, 1), 256>>>(W_atom, ATOMD, W_node, W_node, p_F1, p_F1,
                                       nullptr, nullptr);
    fold_small_kernel<<<1, HDIM>>>(W_coord, W_node, b_atom, b_coord, b_node);
    coord_init_kernel<<<nhb, 256>>>(coord, N);
    conv_x_kernel<<<(N * 128 + 255) / 256, 256>>>(atomic_num, N);
    conv_F1t_kernel<<<(HDIM * 128 + 255) / 256, 256>>>();
    conv_wT_kernel<<<dim3(HH / 256, 8, 1), 256>>>(W_agg, W_glu_a, W_glu_b);
    uv_kernel<<<2, HDIM>>>(W_agg, W_edge, b_edge, b_agg);

    // init: h = x@F1 + coordpart  -> g_hf (fp16)
    mma_gemm<<<dim3(mtiles, 2, 1), 256, MMA_SMEM>>>(
        p_xa, N, 128, p_Fh, p_Fl, p_Fh, p_Fl,
        nullptr, nullptr, p_hd32, p_hf, p_hf);

    for (int l = 0; l < 2; l++) {
        // z=0: hs -> g_s ; z=1: hd -> g_hdh
        mma_gemm<<<dim3(mtiles, 2, 2), 256, MMA_SMEM>>>(
            p_hf, N, HDIM,
            p_Bh + (size_t)(2 * l) * HH,     p_Bl + (size_t)(2 * l) * HH,
            p_Bh + (size_t)(2 * l + 1) * HH, p_Bl + (size_t)(2 * l + 1) * HH,
            nullptr, nullptr, nullptr, p_s, p_hdh);
        agg_kernel<<<aggb, 256>>>(src, radius, exp_l, eps_l, l, N);
        // z=0: ga ; z=1: gb  (with biases)
        mma_gemm<<<dim3(mtiles, 2, 2), 256, MMA_SMEM>>>(
            p_r, N, HDIM,
            p_Bh + (size_t)(4 + 2 * l) * HH, p_Bl + (size_t)(4 + 2 * l) * HH,
            p_Bh + (size_t)(5 + 2 * l) * HH, p_Bl + (size_t)(5 + 2 * l) * HH,
            b_glu_a + l * HDIM, b_glu_b + l * HDIM, nullptr, p_ga, p_gb);
        if (l == 0) glu_kernel<<<(N * HDIM / 2 + 255) / 256, 256>>>(N);
    }

    // fused last-layer GLU + masked segment-sum, then MLP head
    glu_segsum_kernel<<<(N + 127) / 128, HDIM>>>(abs_mask, graph_id, N);
    mlp_kernel<<<GN, 128>>>(W_mlp, b_mlp, out, 1.0f / (float)N);
}

// round 13
// speedup vs baseline: 1.2049x; 1.0071x over previous
#include <cuda_runtime.h>
#include <cuda_fp16.h>
#include <stdint.h>
#include <cstdint>
#include <math.h>

#define N_NODES 20000
#define N_EDGES 640000
#define HDIM    256
#define GN      16
#define OUTD    100
#define ATOMD   118
#define HH      (HDIM * HDIM)

// ---------------- scratch ----------------------------------------------------
__device__ __align__(16) float g_hd32[N_NODES * HDIM];   // coord addend (init only)
__device__ __align__(16) float g_uv [2 * 2 * HDIM];      // [layer][u|vp]
__device__ __align__(16) float g_F1 [ATOMD * HDIM];
__device__ __align__(16) float g_F2 [3 * HDIM];
__device__ __align__(16) float g_bf [HDIM];
__device__ __align__(16) float g_feat[GN * HDIM];
__device__ int   g_cnt [N_NODES + 1];
__device__ int   g_offs[N_NODES + 1];
__device__ int   g_wp  [N_NODES];
__device__ int   g_csr [N_EDGES];
// fp16 activations
__device__ __align__(16) __half g_xa [N_NODES * 128];
__device__ __align__(16) __half g_hf [N_NODES * HDIM];   // h
__device__ __align__(16) __half g_s  [N_NODES * HDIM];   // hs (gather src)
__device__ __align__(16) __half g_hdh[N_NODES * HDIM];   // hd
__device__ __align__(16) __half g_r  [N_NODES * HDIM];   // rst
__device__ __align__(16) __half g_ga [N_NODES * HDIM];
__device__ __align__(16) __half g_gb [N_NODES * HDIM];
// fp16 split weights (hi+lo exact to 2^-22)
__device__ __align__(16) __half g_Bt_hi[8 * HH];
__device__ __align__(16) __half g_Bt_lo[8 * HH];
__device__ __align__(16) __half g_F1t_hi[HDIM * 128];
__device__ __align__(16) __half g_F1t_lo[HDIM * 128];

// ---------------- PTX helpers (all sm_80-legal) ------------------------------
__device__ __forceinline__ uint32_t smem_to_u32(const void* p) {
    uint32_t a;
    asm("{ .reg .u64 t; cvta.to.shared.u64 t, %1; cvt.u32.u64 %0, t; }" : "=r"(a) : "l"(p));
    return a;
}
__device__ __forceinline__ void ldsm4(uint32_t* r, uint32_t addr) {
    asm volatile("ldmatrix.sync.aligned.m8n8.x4.shared.b16 {%0,%1,%2,%3}, [%4];"
                 : "=r"(r[0]), "=r"(r[1]), "=r"(r[2]), "=r"(r[3]) : "r"(addr));
}
__device__ __forceinline__ void mma16816(float* c, const uint32_t* a, uint32_t b0, uint32_t b1) {
    asm volatile("mma.sync.aligned.m16n8k16.row.col.f32.f16.f16.f32 "
                 "{%0,%1,%2,%3}, {%4,%5,%6,%7}, {%8,%9}, {%0,%1,%2,%3};"
                 : "+f"(c[0]), "+f"(c[1]), "+f"(c[2]), "+f"(c[3])
                 : "r"(a[0]), "r"(a[1]), "r"(a[2]), "r"(a[3]), "r"(b0), "r"(b1));
}
__device__ __forceinline__ void cp_async16(uint32_t d, const void* s, int src_sz) {
    asm volatile("cp.async.cg.shared.global [%0], [%1], 16, %2;"
                 :: "r"(d), "l"(s), "r"(src_sz) : "memory");
}
#define CP_COMMIT() asm volatile("cp.async.commit_group;" ::: "memory")
#define CP_WAIT0()  asm volatile("cp.async.wait_group 0;" ::: "memory")

// ---------------- CSR build + init zero + x conversion (merged) ---------------
__global__ void pre_conv_x_kernel(const float* __restrict__ x, int N) {
    int stride = gridDim.x * blockDim.x;
    int i = blockIdx.x * blockDim.x + threadIdx.x;
    for (int t = i; t < N + 1; t += stride) g_cnt[t] = 0;
    for (int t = i; t < GN * HDIM; t += stride) g_feat[t] = 0.f;
    for (int e = i; e < N * 128; e += stride) {
        int n = e >> 7, kk = e & 127;
        float v = (kk < ATOMD) ? x[n * ATOMD + kk] : 0.f;
        g_xa[e] = __float2half(v);
    }
}
__global__ void hist_kernel(const int* __restrict__ dst, int E) {
    int e = blockIdx.x * blockDim.x + threadIdx.x;
    if (e < E) atomicAdd(&g_cnt[dst[e]], 1);
}
__global__ void scan_kernel(int N) {
    __shared__ int partial[1024];
    int t = threadIdx.x;
    int per = (N + 1023) / 1024;
    int start = t * per;
    int stop  = min(start + per, N);
    int sum = 0;
    for (int i = start; i < stop; i++) sum += g_cnt[i];
    partial[t] = sum;
    __syncthreads();
    for (int d = 1; d < 1024; d <<= 1) {
        int v = (t >= d) ? partial[t - d] : 0;
        __syncthreads();
        partial[t] += v;
        __syncthreads();
    }
    int run = (t == 0) ? 0 : partial[t - 1];
    for (int i = start; i < stop; i++) {
        g_offs[i] = run;
        g_wp[i]   = run;
        run += g_cnt[i];
    }
    if (t == 1023) g_offs[N] = partial[1023];
}
__global__ void fill_kernel(const int* __restrict__ dst, int E) {
    int e = blockIdx.x * blockDim.x + threadIdx.x;
    if (e < E) {
        int pos = atomicAdd(&g_wp[dst[e]], 1);
        g_csr[pos] = e;
    }
}

// ---------------- weight folding (fold_small + uv merged) --------------------
__global__ void fold_uv_kernel(const float* __restrict__ Wc,
                               const float* __restrict__ Wn,
                               const float* __restrict__ ba,
                               const float* __restrict__ bc,
                               const float* __restrict__ bn,
                               const float* __restrict__ W_agg,
                               const float* __restrict__ Wedge,
                               const float* __restrict__ bedge,
                               const float* __restrict__ b_agg) {
    int j = threadIdx.x;
    if (blockIdx.x == 0) {
        float f0 = 0.f, f1 = 0.f, f2 = 0.f, bias = 0.f;
        for (int h = 0; h < HDIM; h++) {
            float wtop = Wn[h * HDIM + j];
            float wbot = Wn[(HDIM + h) * HDIM + j];
            f0 += Wc[0 * HDIM + h] * wbot;
            f1 += Wc[1 * HDIM + h] * wbot;
            f2 += Wc[2 * HDIM + h] * wbot;
            bias += ba[h] * wtop + bc[h] * wbot;
        }
        g_F2[0 * HDIM + j] = f0;
        g_F2[1 * HDIM + j] = f1;
        g_F2[2 * HDIM + j] = f2;
        g_bf[j] = bias + bn[j];
    } else {
        int l = blockIdx.x - 1;
        const float* We = W_agg + (size_t)l * 3 * HH + HH;
        float u = 0.f, v = 0.f;
        for (int k = 0; k < HDIM; k++) {
            float we = We[k * HDIM + j];
            u += Wedge[k] * we;
            v += bedge[k] * we;
        }
        g_uv[l * 2 * HDIM + j] = u;
        g_uv[l * 2 * HDIM + HDIM + j] = v + b_agg[l * HDIM + j];
    }
}

__global__ void coord_init_kernel(const float* __restrict__ coord, int N) {
    int idx = blockIdx.x * blockDim.x + threadIdx.x;
    if (idx >= N * HDIM) return;
    int n = idx >> 8;
    int j = idx & 255;
    float c0 = coord[n * 3], c1 = coord[n * 3 + 1], c2 = coord[n * 3 + 2];
    g_hd32[idx] = c0 * g_F2[j] + c1 * g_F2[HDIM + j] + c2 * g_F2[2 * HDIM + j] + g_bf[j];
}

__device__ __forceinline__ void split_h16(float v, __half& hi, __half& lo) {
    hi = __float2half(v);
    lo = __float2half(v - __half2float(hi));
}

// coalesced SMEM tile transpose + fp16 split: Bt[n][k] = W[k][n]
// grid: (8 tiles_n, 8 tiles_k, 8 matrices), block (32, 8)
__global__ void conv_wT_kernel(const float* __restrict__ W_agg,
                               const float* __restrict__ W_glu_a,
                               const float* __restrict__ W_glu_b) {
    __shared__ float tile[32][33];
    int z = blockIdx.z;
    const float* src;
    switch (z) {
        case 0: src = W_agg; break;
        case 1: src = W_agg + 2 * HH; break;
        case 2: src = W_agg + 3 * HH; break;
        case 3: src = W_agg + 5 * HH; break;
        case 4: src = W_glu_a; break;
        case 5: src = W_glu_b; break;
        case 6: src = W_glu_a + HH; break;
        default: src = W_glu_b + HH; break;
    }
    int n0 = blockIdx.x * 32;   // output row block (n)
    int k0 = blockIdx.y * 32;   // output col block (k)
    int tx = threadIdx.x, ty = threadIdx.y;
    // read W rows: k = k0+ty+q*8 (rows), n = n0+tx (contiguous)
#pragma unroll
    for (int q = 0; q < 4; q++) {
        int k = k0 + ty + q * 8;
        tile[ty + q * 8][tx] = src[(size_t)k * HDIM + n0 + tx];
    }
    __syncthreads();
    // write Bt rows: n = n0+ty+q*8 (rows), k = k0+tx (contiguous)
#pragma unroll
    for (int q = 0; q < 4; q++) {
        int n = n0 + ty + q * 8;
        float v = tile[tx][ty + q * 8];
        __half hi, lo;
        split_h16(v, hi, lo);
        size_t o = (size_t)z * HH + (size_t)n * HDIM + k0 + tx;
        g_Bt_hi[o] = hi;
        g_Bt_lo[o] = lo;
    }
}

// coalesced transpose of F1 [118,256] -> F1t [256,128] hi/lo
// grid: (8 tiles_n, 4 tiles_k), block (32, 8)
__global__ void conv_F1t_kernel() {
    __shared__ float tile[32][33];
    int n0 = blockIdx.x * 32;
    int k0 = blockIdx.y * 32;
    int tx = threadIdx.x, ty = threadIdx.y;
#pragma unroll
    for (int q = 0; q < 4; q++) {
        int k = k0 + ty + q * 8;
        tile[ty + q * 8][tx] = (k < ATOMD) ? g_F1[(size_t)k * HDIM + n0 + tx] : 0.f;
    }
    __syncthreads();
#pragma unroll
    for (int q = 0; q < 4; q++) {
        int n = n0 + ty + q * 8;
        float v = tile[tx][ty + q * 8];
        __half hi, lo;
        split_h16(v, hi, lo);
        size_t o = (size_t)n * 128 + k0 + tx;
        g_F1t_hi[o] = hi;
        g_F1t_lo[o] = lo;
    }
}

// ---------------- warp-per-node aggregation (fp16 gather) --------------------
__global__ void agg_kernel(const int* __restrict__ src,
                           const float* __restrict__ radius,
                           const float* __restrict__ exp_l,
                           const float* __restrict__ eps_l, int l, int N) {
    int warp = (blockIdx.x * blockDim.x + threadIdx.x) >> 5;
    int lane = threadIdx.x & 31;
    if (warp >= N) return;
    float el = __ldg(&exp_l[l]);
    const float* uvb = g_uv + l * 2 * HDIM;
    int beg = g_offs[warp], end = g_offs[warp + 1];
    float4 acc0 = make_float4(0.f, 0.f, 0.f, 0.f);
    float4 acc1 = make_float4(0.f, 0.f, 0.f, 0.f);
    float s1 = 0.f, swr = 0.f;
    int j0 = lane * 8;
    for (int base = beg; base < end; base += 32) {
        int p = base + lane;
        int s = 0;
        float w = 0.f;
        if (p < end) {
            int e = g_csr[p];
            s = src[e];
            float r = radius[e];
            w = __expf(__logf(r) * el);
            s1 += w;
            swr += w * r;
        }
        int cnt = min(32, end - base);
        for (int q = 0; q < cnt; q++) {
            int   sq = __shfl_sync(0xffffffffu, s, q);
            float wq = __shfl_sync(0xffffffffu, w, q);
            uint4 pv = *(const uint4*)(g_s + (size_t)sq * HDIM + j0);
            float2 f0 = __half22float2(*(__half2*)&pv.x);
            float2 f1 = __half22float2(*(__half2*)&pv.y);
            float2 f2 = __half22float2(*(__half2*)&pv.z);
            float2 f3 = __half22float2(*(__half2*)&pv.w);
            acc0.x += wq * f0.x; acc0.y += wq * f0.y;
            acc0.z += wq * f1.x; acc0.w += wq * f1.y;
            acc1.x += wq * f2.x; acc1.y += wq * f2.y;
            acc1.z += wq * f3.x; acc1.w += wq * f3.y;
        }
    }
#pragma unroll
    for (int off = 16; off; off >>= 1) {
        s1  += __shfl_xor_sync(0xffffffffu, s1, off);
        swr += __shfl_xor_sync(0xffffffffu, swr, off);
    }
    float ep = 1.f + __ldg(&eps_l[l]);
    float4 u0  = *(const float4*)(uvb + j0);
    float4 u1  = *(const float4*)(uvb + j0 + 4);
    float4 vp0 = *(const float4*)(uvb + HDIM + j0);
    float4 vp1 = *(const float4*)(uvb + HDIM + j0 + 4);
    size_t idx = (size_t)warp * HDIM + j0;
    uint4 hv = *(const uint4*)(g_hf + idx);
    uint4 dv = *(const uint4*)(g_hdh + idx);
    float2 h01 = __half22float2(*(__half2*)&hv.x);
    float2 h23 = __half22float2(*(__half2*)&hv.y);
    float2 h45 = __half22float2(*(__half2*)&hv.z);
    float2 h67 = __half22float2(*(__half2*)&hv.w);
    float2 d01 = __half22float2(*(__half2*)&dv.x);
    float2 d23 = __half22float2(*(__half2*)&dv.y);
    float2 d45 = __half22float2(*(__half2*)&dv.z);
    float2 d67 = __half22float2(*(__half2*)&dv.w);
    float v[8];
    v[0] = ep * h01.x + acc0.x + s1 * (d01.x + vp0.x) + swr * u0.x;
    v[1] = ep * h01.y + acc0.y + s1 * (d01.y + vp0.y) + swr * u0.y;
    v[2] = ep * h23.x + acc0.z + s1 * (d23.x + vp0.z) + swr * u0.z;
    v[3] = ep * h23.y + acc0.w + s1 * (d23.y + vp0.w) + swr * u0.w;
    v[4] = ep * h45.x + acc1.x + s1 * (d45.x + vp1.x) + swr * u1.x;
    v[5] = ep * h45.y + acc1.y + s1 * (d45.y + vp1.y) + swr * u1.y;
    v[6] = ep * h67.x + acc1.z + s1 * (d67.x + vp1.z) + swr * u1.z;
    v[7] = ep * h67.y + acc1.w + s1 * (d67.y + vp1.w) + swr * u1.w;
    uint4 rv;
    *(__half2*)&rv.x = __float22half2_rn(make_float2(v[0], v[1]));
    *(__half2*)&rv.y = __float22half2_rn(make_float2(v[2], v[3]));
    *(__half2*)&rv.z = __float22half2_rn(make_float2(v[4], v[5]));
    *(__half2*)&rv.w = __float22half2_rn(make_float2(v[6], v[7]));
    *(uint4*)(g_r + idx) = rv;
}

// layer-0 GLU: h = ga * sigmoid(gb), fp16 in/out (half2 vectorized)
__global__ void glu_kernel(int N) {
    int i = blockIdx.x * blockDim.x + threadIdx.x;
    if (i >= N * HDIM / 2) return;
    float2 ga = __half22float2(((const __half2*)g_ga)[i]);
    float2 gb = __half22float2(((const __half2*)g_gb)[i]);
    float h0 = ga.x * (1.f / (1.f + __expf(-gb.x)));
    float h1 = ga.y * (1.f / (1.f + __expf(-gb.y)));
    ((__half2*)g_hf)[i] = __float22half2_rn(make_float2(h0, h1));
}

// last layer: fused GLU + masked segment-sum from fp16 ga/gb
__global__ void glu_segsum_kernel(const int* __restrict__ mask,
                                  const int* __restrict__ gid, int N) {
    int j  = threadIdx.x;
    int n0 = blockIdx.x * 128;
    if (n0 >= N) return;
    int n1 = min(n0 + 128, N);
    float acc = 0.f;
    int curg = gid[n0];
    for (int n = n0; n < n1; n++) {
        int g = gid[n];
        if (g != curg) {
            atomicAdd(&g_feat[curg * HDIM + j], acc);
            acc = 0.f;
            curg = g;
        }
        if (mask[n]) {
            size_t o = (size_t)n * HDIM + j;
            float ga = __half2float(g_ga[o]);
            float gb = __half2float(g_gb[o]);
            acc += ga * (1.f / (1.f + __expf(-gb)));
        }
    }
    atomicAdd(&g_feat[curg * HDIM + j], acc);
}

__global__ void mlp_kernel(const float* __restrict__ Wm,
                           const float* __restrict__ bm,
                           float* __restrict__ out, float invN) {
    int g = blockIdx.x;
    int o = threadIdx.x;
    if (o >= OUTD) return;
    float s = 0.f;
    for (int j = 0; j < HDIM; j++)
        s += g_feat[g * HDIM + j] * Wm[j * OUTD + o];
    s = s * invN + bm[o];
    out[g * OUTD + o] = 1.f / (1.f + __expf(-s));
}

// ---------------- mma.sync fp16 2-term GEMM (256 thr, 32x64 warp tiles) ------
#define STSZ   30720
#define SOFF_BH 10240
#define SOFF_BL 20480

__global__ __launch_bounds__(256, 2)
void mma_gemm(const __half* __restrict__ A, int M, int Ktot,
              const __half* __restrict__ Bh0, const __half* __restrict__ Bl0,
              const __half* __restrict__ Bh1, const __half* __restrict__ Bl1,
              const float* __restrict__ bias0, const float* __restrict__ bias1,
              const float* __restrict__ addend,
              __half* __restrict__ H0, __half* __restrict__ H1) {
    extern __shared__ char smem[];
    const __half* Bhi = blockIdx.z ? Bh1 : Bh0;
    const __half* Blo = blockIdx.z ? Bl1 : Bl0;
    const float* bias = blockIdx.z ? bias1 : bias0;
    __half* Hout = blockIdx.z ? H1 : H0;

    int tid = threadIdx.x;
    int wid = tid >> 5;
    int lane = tid & 31;
    int warp_m = wid & 3;
    int warp_n = wid >> 2;
    int m0 = blockIdx.x * 128;
    int n0 = blockIdx.y * 128;
    uint32_t sb = smem_to_u32(smem);

    float acc[2][8][4];
#pragma unroll
    for (int a = 0; a < 2; a++)
#pragma unroll
        for (int b = 0; b < 8; b++)
#pragma unroll
            for (int c = 0; c < 4; c++) acc[a][b][c] = 0.f;

    int KT = Ktot >> 5;
    int lrow = (lane & 7) + ((lane >> 3) & 1) * 8;
    int lcol = (lane >> 4) * 8;

    int row0 = tid >> 2,         kc0 = (tid & 3) * 8;
    int row1 = (tid + 256) >> 2, kc1 = (tid & 3) * 8;
    int arow0 = (m0 + row0 < M) ? (m0 + row0) : 0;
    int arow1 = (m0 + row1 < M) ? (m0 + row1) : 0;
    int asz0  = (m0 + row0 < M) ? 16 : 0;
    int asz1  = (m0 + row1 < M) ? 16 : 0;

#define LOAD_STAGE(kt, buf)                                                        \
    do {                                                                           \
        int k0 = (kt) * 32;                                                        \
        uint32_t d0 = sb + (buf) * STSZ + ((uint32_t)row0 * 40 + kc0) * 2;         \
        uint32_t d1 = sb + (buf) * STSZ + ((uint32_t)row1 * 40 + kc1) * 2;         \
        size_t ao0 = (size_t)arow0 * Ktot + k0 + kc0;                              \
        size_t ao1 = (size_t)arow1 * Ktot + k0 + kc1;                              \
        size_t bo0 = (size_t)(n0 + row0) * Ktot + k0 + kc0;                        \
        size_t bo1 = (size_t)(n0 + row1) * Ktot + k0 + kc1;                        \
        cp_async16(d0,           A   + ao0, asz0);                                 \
        cp_async16(d0 + SOFF_BH, Bhi + bo0, 16);                                   \
        cp_async16(d0 + SOFF_BL, Blo + bo0, 16);                                   \
        cp_async16(d1,           A   + ao1, asz1);                                 \
        cp_async16(d1 + SOFF_BH, Bhi + bo1, 16);                                   \
        cp_async16(d1 + SOFF_BL, Blo + bo1, 16);                                   \
    } while (0)

    LOAD_STAGE(0, 0);
    CP_COMMIT();

#pragma unroll 1
    for (int kt = 0; kt < KT; kt++) {
        int buf = kt & 1;
        CP_WAIT0();
        __syncthreads();
        if (kt + 1 < KT) {
            LOAD_STAGE(kt + 1, buf ^ 1);
            CP_COMMIT();
        }
#pragma unroll
        for (int ks = 0; ks < 2; ks++) {
            int kc = ks * 16 + lcol;
            uint32_t ah[2][4];
#pragma unroll
            for (int mt = 0; mt < 2; mt++) {
                int r = warp_m * 32 + mt * 16 + lrow;
                ldsm4(ah[mt], sb + buf * STSZ + ((uint32_t)r * 40 + kc) * 2);
            }
#pragma unroll
            for (int ng = 0; ng < 4; ng++) {
                int r = warp_n * 64 + ng * 16 + lrow;
                uint32_t baddr = sb + buf * STSZ + ((uint32_t)r * 40 + kc) * 2 + SOFF_BH;
                uint32_t bh[4], bl[4];
                ldsm4(bh, baddr);
                ldsm4(bl, baddr + (SOFF_BL - SOFF_BH));
#pragma unroll
                for (int mt = 0; mt < 2; mt++) {
                    mma16816(acc[mt][2 * ng],     ah[mt], bh[0], bh[2]);
                    mma16816(acc[mt][2 * ng],     ah[mt], bl[0], bl[2]);
                    mma16816(acc[mt][2 * ng + 1], ah[mt], bh[1], bh[3]);
                    mma16816(acc[mt][2 * ng + 1], ah[mt], bl[1], bl[3]);
                }
            }
        }
    }

    // ---- epilogue: fp16 output, optional bias / fp32 addend ----
    int gi = lane >> 2;
    int ci = (lane & 3) * 2;
#pragma unroll
    for (int mt = 0; mt < 2; mt++) {
#pragma unroll
        for (int nt = 0; nt < 8; nt++) {
            float* a4 = acc[mt][nt];
            int col = n0 + warp_n * 64 + nt * 8 + ci;
            float b0 = 0.f, b1 = 0.f;
            if (bias) { b0 = __ldg(&bias[col]); b1 = __ldg(&bias[col + 1]); }
#pragma unroll
            for (int half_ = 0; half_ < 2; half_++) {
                int row = m0 + warp_m * 32 + mt * 16 + gi + half_ * 8;
                if (row >= M) continue;
                float v0 = a4[half_ * 2]     + b0;
                float v1 = a4[half_ * 2 + 1] + b1;
                size_t o = (size_t)row * HDIM + col;
                if (addend) {
                    float2 t = *(const float2*)(addend + o);
                    v0 += t.x; v1 += t.y;
                }
                *(__half2*)(Hout + o) = __float22half2_rn(make_float2(v0, v1));
            }
        }
    }
#undef LOAD_STAGE
}

// ---------------- small fp32 GEMM for the F1 fold (M=118) --------------------
__global__ __launch_bounds__(256, 2)
void sgemm_pair(const float* __restrict__ A, int M,
                const float* __restrict__ B0, const float* __restrict__ B1,
                float* __restrict__ C0, float* __restrict__ C1,
                const float* __restrict__ bias0, const float* __restrict__ bias1) {
    const float* B    = blockIdx.z ? B1 : B0;
    float*       C    = blockIdx.z ? C1 : C0;
    const float* bias = blockIdx.z ? bias1 : bias0;
    __shared__ float As[2][16][132];
    __shared__ float Bs[2][16][128];
    int tid = threadIdx.x;
    int m0 = blockIdx.x * 128;
    int n0 = blockIdx.y * 128;
    int tx = tid & 15, ty = tid >> 4;
    int ar = tid >> 2;
    int ac = (tid & 3) * 4;
    int bk = tid >> 5;
    int bn = (tid & 31) * 4;
    bool aval0 = (m0 + ar) < M;
    bool aval1 = (m0 + ar + 64) < M;
    const float* Arow0 = A + (size_t)(m0 + ar) * HDIM + ac;
    const float* Arow1 = A + (size_t)(m0 + ar + 64) * HDIM + ac;
    const float* Bp0 = B + (size_t)bk * HDIM + n0 + bn;
    const float* Bp1 = B + (size_t)(bk + 8) * HDIM + n0 + bn;
    float4 af0, af1, bf0, bf1;
    const float4 fz = make_float4(0.f, 0.f, 0.f, 0.f);
#define LOADG(k0) do { \
        af0 = aval0 ? *(const float4*)(Arow0 + (k0)) : fz; \
        af1 = aval1 ? *(const float4*)(Arow1 + (k0)) : fz; \
        bf0 = *(const float4*)(Bp0 + (size_t)(k0) * HDIM); \
        bf1 = *(const float4*)(Bp1 + (size_t)(k0) * HDIM); } while (0)
#define STORES(bufi) do { \
        As[bufi][ac + 0][ar] = af0.x; As[bufi][ac + 1][ar] = af0.y; \
        As[bufi][ac + 2][ar] = af0.z; As[bufi][ac + 3][ar] = af0.w; \
        As[bufi][ac + 0][ar + 64] = af1.x; As[bufi][ac + 1][ar + 64] = af1.y; \
        As[bufi][ac + 2][ar + 64] = af1.z; As[bufi][ac + 3][ar + 64] = af1.w; \
        *(float4*)&Bs[bufi][bk][bn] = bf0; *(float4*)&Bs[bufi][bk + 8][bn] = bf1; } while (0)
    float acc[8][8];
#pragma unroll
    for (int i = 0; i < 8; i++)
#pragma unroll
        for (int j = 0; j < 8; j++) acc[i][j] = 0.f;
    LOADG(0);
    STORES(0);
    __syncthreads();
    int buf = 0;
#pragma unroll 1
    for (int kt = 0; kt < 16; kt++) {
        if (kt < 15) LOADG((kt + 1) * 16);
#pragma unroll
        for (int k = 0; k < 16; k++) {
            float4 a0 = *(const float4*)&As[buf][k][ty * 8];
            float4 a1 = *(const float4*)&As[buf][k][ty * 8 + 4];
            float4 b0 = *(const float4*)&Bs[buf][k][tx * 8];
            float4 b1 = *(const float4*)&Bs[buf][k][tx * 8 + 4];
            float a[8] = {a0.x, a0.y, a0.z, a0.w, a1.x, a1.y, a1.z, a1.w};
            float b[8] = {b0.x, b0.y, b0.z, b0.w, b1.x, b1.y, b1.z, b1.w};
#pragma unroll
            for (int i = 0; i < 8; i++)
#pragma unroll
                for (int j = 0; j < 8; j++)
                    acc[i][j] += a[i] * b[j];
        }
        if (kt < 15) { STORES(buf ^ 1); __syncthreads(); buf ^= 1; }
    }
    float bv[8];
#pragma unroll
    for (int j = 0; j < 8; j++) bv[j] = bias ? bias[n0 + tx * 8 + j] : 0.f;
#pragma unroll
    for (int i = 0; i < 8; i++) {
        int mm = m0 + ty * 8 + i;
        if (mm >= M) continue;
        float* Cp = C + (size_t)mm * HDIM + n0 + tx * 8;
        *(float4*)Cp = make_float4(acc[i][0] + bv[0], acc[i][1] + bv[1],
                                   acc[i][2] + bv[2], acc[i][3] + bv[3]);
        *(float4*)(Cp + 4) = make_float4(acc[i][4] + bv[4], acc[i][5] + bv[5],
                                         acc[i][6] + bv[6], acc[i][7] + bv[7]);
    }
#undef LOADG
#undef STORES
}

// ---------------- launcher ---------------------------------------------------
extern "C" void kernel_launch(void* const* d_in, const int* in_sizes, int n_in,
                              void* d_out, int out_size) {
    const float* atomic_num = (const float*)d_in[0];
    const float* coord      = (const float*)d_in[1];
    const float* radius     = (const float*)d_in[2];
    const int*   src        = (const int*)  d_in[3];
    const int*   dst        = (const int*)  d_in[4];
    const int*   abs_mask   = (const int*)  d_in[5];
    const int*   graph_id   = (const int*)  d_in[6];
    const float* W_atom     = (const float*)d_in[7];
    const float* b_atom     = (const float*)d_in[8];
    const float* W_coord    = (const float*)d_in[9];
    const float* b_coord    = (const float*)d_in[10];
    const float* W_node     = (const float*)d_in[11];
    const float* b_node     = (const float*)d_in[12];
    const float* W_edge     = (const float*)d_in[13];
    const float* b_edge     = (const float*)d_in[14];
    const float* W_agg      = (const float*)d_in[15];
    const float* b_agg      = (const float*)d_in[16];
    const float* W_glu_a    = (const float*)d_in[17];
    const float* b_glu_a    = (const float*)d_in[18];
    const float* W_glu_b    = (const float*)d_in[19];
    const float* b_glu_b    = (const float*)d_in[20];
    const float* exp_l      = (const float*)d_in[21];
    const float* eps_l      = (const float*)d_in[22];
    const float* W_mlp      = (const float*)d_in[23];
    const float* b_mlp      = (const float*)d_in[24];
    float* out = (float*)d_out;

    int N = in_sizes[5];
    int E = in_sizes[2];

    float *p_hd32, *p_F1;
    __half *p_xa, *p_hf, *p_s, *p_hdh, *p_r, *p_ga, *p_gb, *p_Bh, *p_Bl, *p_Fh, *p_Fl;
    cudaGetSymbolAddress((void**)&p_hd32, g_hd32);
    cudaGetSymbolAddress((void**)&p_F1,   g_F1);
    cudaGetSymbolAddress((void**)&p_xa,   g_xa);
    cudaGetSymbolAddress((void**)&p_hf,   g_hf);
    cudaGetSymbolAddress((void**)&p_s,    g_s);
    cudaGetSymbolAddress((void**)&p_hdh,  g_hdh);
    cudaGetSymbolAddress((void**)&p_r,    g_r);
    cudaGetSymbolAddress((void**)&p_ga,   g_ga);
    cudaGetSymbolAddress((void**)&p_gb,   g_gb);
    cudaGetSymbolAddress((void**)&p_Bh,   g_Bt_hi);
    cudaGetSymbolAddress((void**)&p_Bl,   g_Bt_lo);
    cudaGetSymbolAddress((void**)&p_Fh,   g_F1t_hi);
    cudaGetSymbolAddress((void**)&p_Fl,   g_F1t_lo);

    const int MMA_SMEM = 2 * STSZ;
    cudaFuncSetAttribute(mma_gemm, cudaFuncAttributeMaxDynamicSharedMemorySize, MMA_SMEM);

    int mtiles = (N + 127) / 128;
    int eb = (E + 255) / 256;
    int nhb = (N * HDIM + 255) / 256;
    int aggb = (N + 7) / 8;

    // CSR build (+zero +x conversion merged)
    pre_conv_x_kernel<<<160, 256>>>(atomic_num, N);
    hist_kernel<<<eb, 256>>>(dst, E);
    scan_kernel<<<1, 1024>>>(N);
    fill_kernel<<<eb, 256>>>(dst, E);

    // folds + conversions
    sgemm_pair<<<dim3(1, 2, 1), 256>>>(W_atom, ATOMD, W_node, W_node, p_F1, p_F1,
                                       nullptr, nullptr);
    fold_uv_kernel<<<3, HDIM>>>(W_coord, W_node, b_atom, b_coord, b_node,
                                W_agg, W_edge, b_edge, b_agg);
    coord_init_kernel<<<nhb, 256>>>(coord, N);
    conv_F1t_kernel<<<dim3(8, 4), dim3(32, 8)>>>();
    conv_wT_kernel<<<dim3(8, 8, 8), dim3(32, 8)>>>(W_agg, W_glu_a, W_glu_b);

    // init: h = x@F1 + coordpart  -> g_hf (fp16)
    mma_gemm<<<dim3(mtiles, 2, 1), 256, MMA_SMEM>>>(
        p_xa, N, 128, p_Fh, p_Fl, p_Fh, p_Fl,
        nullptr, nullptr, p_hd32, p_hf, p_hf);

    for (int l = 0; l < 2; l++) {
        // z=0: hs -> g_s ; z=1: hd -> g_hdh
        mma_gemm<<<dim3(mtiles, 2, 2), 256, MMA_SMEM>>>(
            p_hf, N, HDIM,
            p_Bh + (size_t)(2 * l) * HH,     p_Bl + (size_t)(2 * l) * HH,
            p_Bh + (size_t)(2 * l + 1) * HH, p_Bl + (size_t)(2 * l + 1) * HH,
            nullptr, nullptr, nullptr, p_s, p_hdh);
        agg_kernel<<<aggb, 256>>>(src, radius, exp_l, eps_l, l, N);
        // z=0: ga ; z=1: gb  (with biases)
        mma_gemm<<<dim3(mtiles, 2, 2), 256, MMA_SMEM>>>(
            p_r, N, HDIM,
            p_Bh + (size_t)(4 + 2 * l) * HH, p_Bl + (size_t)(4 + 2 * l) * HH,
            p_Bh + (size_t)(5 + 2 * l) * HH, p_Bl + (size_t)(5 + 2 * l) * HH,
            b_glu_a + l * HDIM, b_glu_b + l * HDIM, nullptr, p_ga, p_gb);
        if (l == 0) glu_kernel<<<(N * HDIM / 2 + 255) / 256, 256>>>(N);
    }

    // fused last-layer GLU + masked segment-sum, then MLP head
    glu_segsum_kernel<<<(N + 127) / 128, HDIM>>>(abs_mask, graph_id, N);
    mlp_kernel<<<GN, 128>>>(W_mlp, b_mlp, out, 1.0f / (float)N);
}

// round 14
// speedup vs baseline: 1.2356x; 1.0255x over previous
#include <cuda_runtime.h>
#include <cuda_fp16.h>
#include <stdint.h>
#include <cstdint>
#include <math.h>

#define N_NODES 20000
#define N_EDGES 640000
#define HDIM    256
#define GN      16
#define OUTD    100
#define ATOMD   118
#define HH      (HDIM * HDIM)

// ---------------- scratch ----------------------------------------------------
__device__ __align__(16) float g_uv [2 * 2 * HDIM];      // [layer][u|vp]
__device__ __align__(16) float g_F1 [ATOMD * HDIM];
__device__ __align__(16) float g_F2 [3 * HDIM];
__device__ __align__(16) float g_bf [HDIM];
__device__ __align__(16) float g_feat[GN * HDIM];
__device__ int   g_cnt [N_NODES + 1];
__device__ int   g_offs[N_NODES + 1];
__device__ int   g_wp  [N_NODES];
__device__ int   g_csr [N_EDGES];
// fp16 activations
__device__ __align__(16) __half g_xa [N_NODES * 128];
__device__ __align__(16) __half g_hf [N_NODES * HDIM];   // h
__device__ __align__(16) __half g_s  [N_NODES * HDIM];   // hs (gather src)
__device__ __align__(16) __half g_hdh[N_NODES * HDIM];   // hd
__device__ __align__(16) __half g_r  [N_NODES * HDIM];   // rst
__device__ __align__(16) __half g_ga [N_NODES * HDIM];
__device__ __align__(16) __half g_gb [N_NODES * HDIM];
// fp16 split weights (hi+lo exact to 2^-22)
__device__ __align__(16) __half g_Bt_hi[8 * HH];
__device__ __align__(16) __half g_Bt_lo[8 * HH];
__device__ __align__(16) __half g_F1t_hi[HDIM * 128];
__device__ __align__(16) __half g_F1t_lo[HDIM * 128];

// ---------------- PTX helpers (all sm_80-legal) ------------------------------
__device__ __forceinline__ uint32_t smem_to_u32(const void* p) {
    uint32_t a;
    asm("{ .reg .u64 t; cvta.to.shared.u64 t, %1; cvt.u32.u64 %0, t; }" : "=r"(a) : "l"(p));
    return a;
}
__device__ __forceinline__ void ldsm4(uint32_t* r, uint32_t addr) {
    asm volatile("ldmatrix.sync.aligned.m8n8.x4.shared.b16 {%0,%1,%2,%3}, [%4];"
                 : "=r"(r[0]), "=r"(r[1]), "=r"(r[2]), "=r"(r[3]) : "r"(addr));
}
__device__ __forceinline__ void mma16816(float* c, const uint32_t* a, uint32_t b0, uint32_t b1) {
    asm volatile("mma.sync.aligned.m16n8k16.row.col.f32.f16.f16.f32 "
                 "{%0,%1,%2,%3}, {%4,%5,%6,%7}, {%8,%9}, {%0,%1,%2,%3};"
                 : "+f"(c[0]), "+f"(c[1]), "+f"(c[2]), "+f"(c[3])
                 : "r"(a[0]), "r"(a[1]), "r"(a[2]), "r"(a[3]), "r"(b0), "r"(b1));
}
__device__ __forceinline__ void cp_async16(uint32_t d, const void* s, int src_sz) {
    asm volatile("cp.async.cg.shared.global [%0], [%1], 16, %2;"
                 :: "r"(d), "l"(s), "r"(src_sz) : "memory");
}
#define CP_COMMIT() asm volatile("cp.async.commit_group;" ::: "memory")
#define CP_WAIT0()  asm volatile("cp.async.wait_group 0;" ::: "memory")
#define CP_WAIT1()  asm volatile("cp.async.wait_group 1;" ::: "memory")

// ---------------- CSR build + init zero + x conversion (merged) ---------------
__global__ void pre_conv_x_kernel(const float* __restrict__ x, int N) {
    int stride = gridDim.x * blockDim.x;
    int i = blockIdx.x * blockDim.x + threadIdx.x;
    for (int t = i; t < N + 1; t += stride) g_cnt[t] = 0;
    for (int t = i; t < GN * HDIM; t += stride) g_feat[t] = 0.f;
    for (int e = i; e < N * 128; e += stride) {
        int n = e >> 7, kk = e & 127;
        float v = (kk < ATOMD) ? x[n * ATOMD + kk] : 0.f;
        g_xa[e] = __float2half(v);
    }
}
__global__ void hist_kernel(const int* __restrict__ dst, int E) {
    int e = blockIdx.x * blockDim.x + threadIdx.x;
    if (e < E) atomicAdd(&g_cnt[dst[e]], 1);
}
__global__ void scan_kernel(int N) {
    __shared__ int partial[1024];
    int t = threadIdx.x;
    int per = (N + 1023) / 1024;
    int start = t * per;
    int stop  = min(start + per, N);
    int sum = 0;
    for (int i = start; i < stop; i++) sum += g_cnt[i];
    partial[t] = sum;
    __syncthreads();
    for (int d = 1; d < 1024; d <<= 1) {
        int v = (t >= d) ? partial[t - d] : 0;
        __syncthreads();
        partial[t] += v;
        __syncthreads();
    }
    int run = (t == 0) ? 0 : partial[t - 1];
    for (int i = start; i < stop; i++) {
        g_offs[i] = run;
        g_wp[i]   = run;
        run += g_cnt[i];
    }
    if (t == 1023) g_offs[N] = partial[1023];
}
__global__ void fill_kernel(const int* __restrict__ dst, int E) {
    int e = blockIdx.x * blockDim.x + threadIdx.x;
    if (e < E) {
        int pos = atomicAdd(&g_wp[dst[e]], 1);
        g_csr[pos] = e;
    }
}

// ---------------- weight folding (fold_small + uv merged) --------------------
__global__ void fold_uv_kernel(const float* __restrict__ Wc,
                               const float* __restrict__ Wn,
                               const float* __restrict__ ba,
                               const float* __restrict__ bc,
                               const float* __restrict__ bn,
                               const float* __restrict__ W_agg,
                               const float* __restrict__ Wedge,
                               const float* __restrict__ bedge,
                               const float* __restrict__ b_agg) {
    int j = threadIdx.x;
    if (blockIdx.x == 0) {
        float f0 = 0.f, f1 = 0.f, f2 = 0.f, bias = 0.f;
        for (int h = 0; h < HDIM; h++) {
            float wtop = Wn[h * HDIM + j];
            float wbot = Wn[(HDIM + h) * HDIM + j];
            f0 += Wc[0 * HDIM + h] * wbot;
            f1 += Wc[1 * HDIM + h] * wbot;
            f2 += Wc[2 * HDIM + h] * wbot;
            bias += ba[h] * wtop + bc[h] * wbot;
        }
        g_F2[0 * HDIM + j] = f0;
        g_F2[1 * HDIM + j] = f1;
        g_F2[2 * HDIM + j] = f2;
        g_bf[j] = bias + bn[j];
    } else {
        int l = blockIdx.x - 1;
        const float* We = W_agg + (size_t)l * 3 * HH + HH;
        float u = 0.f, v = 0.f;
        for (int k = 0; k < HDIM; k++) {
            float we = We[k * HDIM + j];
            u += Wedge[k] * we;
            v += bedge[k] * we;
        }
        g_uv[l * 2 * HDIM + j] = u;
        g_uv[l * 2 * HDIM + HDIM + j] = v + b_agg[l * HDIM + j];
    }
}

__device__ __forceinline__ void split_h16(float v, __half& hi, __half& lo) {
    hi = __float2half(v);
    lo = __float2half(v - __half2float(hi));
}

// coalesced SMEM tile transpose + fp16 split: Bt[n][k] = W[k][n]
__global__ void conv_wT_kernel(const float* __restrict__ W_agg,
                               const float* __restrict__ W_glu_a,
                               const float* __restrict__ W_glu_b) {
    __shared__ float tile[32][33];
    int z = blockIdx.z;
    const float* src;
    switch (z) {
        case 0: src = W_agg; break;
        case 1: src = W_agg + 2 * HH; break;
        case 2: src = W_agg + 3 * HH; break;
        case 3: src = W_agg + 5 * HH; break;
        case 4: src = W_glu_a; break;
        case 5: src = W_glu_b; break;
        case 6: src = W_glu_a + HH; break;
        default: src = W_glu_b + HH; break;
    }
    int n0 = blockIdx.x * 32;
    int k0 = blockIdx.y * 32;
    int tx = threadIdx.x, ty = threadIdx.y;
#pragma unroll
    for (int q = 0; q < 4; q++) {
        int k = k0 + ty + q * 8;
        tile[ty + q * 8][tx] = src[(size_t)k * HDIM + n0 + tx];
    }
    __syncthreads();
#pragma unroll
    for (int q = 0; q < 4; q++) {
        int n = n0 + ty + q * 8;
        float v = tile[tx][ty + q * 8];
        __half hi, lo;
        split_h16(v, hi, lo);
        size_t o = (size_t)z * HH + (size_t)n * HDIM + k0 + tx;
        g_Bt_hi[o] = hi;
        g_Bt_lo[o] = lo;
    }
}

// coalesced transpose of F1 [118,256] -> F1t [256,128] hi/lo
__global__ void conv_F1t_kernel() {
    __shared__ float tile[32][33];
    int n0 = blockIdx.x * 32;
    int k0 = blockIdx.y * 32;
    int tx = threadIdx.x, ty = threadIdx.y;
#pragma unroll
    for (int q = 0; q < 4; q++) {
        int k = k0 + ty + q * 8;
        tile[ty + q * 8][tx] = (k < ATOMD) ? g_F1[(size_t)k * HDIM + n0 + tx] : 0.f;
    }
    __syncthreads();
#pragma unroll
    for (int q = 0; q < 4; q++) {
        int n = n0 + ty + q * 8;
        float v = tile[tx][ty + q * 8];
        __half hi, lo;
        split_h16(v, hi, lo);
        size_t o = (size_t)n * 128 + k0 + tx;
        g_F1t_hi[o] = hi;
        g_F1t_lo[o] = lo;
    }
}

// ---------------- warp-per-node aggregation (fp16 gather) --------------------
__global__ void agg_kernel(const int* __restrict__ src,
                           const float* __restrict__ radius,
                           const float* __restrict__ exp_l,
                           const float* __restrict__ eps_l, int l, int N) {
    int warp = (blockIdx.x * blockDim.x + threadIdx.x) >> 5;
    int lane = threadIdx.x & 31;
    if (warp >= N) return;
    float el = __ldg(&exp_l[l]);
    const float* uvb = g_uv + l * 2 * HDIM;
    int beg = g_offs[warp], end = g_offs[warp + 1];
    float4 acc0 = make_float4(0.f, 0.f, 0.f, 0.f);
    float4 acc1 = make_float4(0.f, 0.f, 0.f, 0.f);
    float s1 = 0.f, swr = 0.f;
    int j0 = lane * 8;
    for (int base = beg; base < end; base += 32) {
        int p = base + lane;
        int s = 0;
        float w = 0.f;
        if (p < end) {
            int e = g_csr[p];
            s = src[e];
            float r = radius[e];
            w = __expf(__logf(r) * el);
            s1 += w;
            swr += w * r;
        }
        int cnt = min(32, end - base);
        for (int q = 0; q < cnt; q++) {
            int   sq = __shfl_sync(0xffffffffu, s, q);
            float wq = __shfl_sync(0xffffffffu, w, q);
            uint4 pv = *(const uint4*)(g_s + (size_t)sq * HDIM + j0);
            float2 f0 = __half22float2(*(__half2*)&pv.x);
            float2 f1 = __half22float2(*(__half2*)&pv.y);
            float2 f2 = __half22float2(*(__half2*)&pv.z);
            float2 f3 = __half22float2(*(__half2*)&pv.w);
            acc0.x += wq * f0.x; acc0.y += wq * f0.y;
            acc0.z += wq * f1.x; acc0.w += wq * f1.y;
            acc1.x += wq * f2.x; acc1.y += wq * f2.y;
            acc1.z += wq * f3.x; acc1.w += wq * f3.y;
        }
    }
#pragma unroll
    for (int off = 16; off; off >>= 1) {
        s1  += __shfl_xor_sync(0xffffffffu, s1, off);
        swr += __shfl_xor_sync(0xffffffffu, swr, off);
    }
    float ep = 1.f + __ldg(&eps_l[l]);
    float4 u0  = *(const float4*)(uvb + j0);
    float4 u1  = *(const float4*)(uvb + j0 + 4);
    float4 vp0 = *(const float4*)(uvb + HDIM + j0);
    float4 vp1 = *(const float4*)(uvb + HDIM + j0 + 4);
    size_t idx = (size_t)warp * HDIM + j0;
    uint4 hv = *(const uint4*)(g_hf + idx);
    uint4 dv = *(const uint4*)(g_hdh + idx);
    float2 h01 = __half22float2(*(__half2*)&hv.x);
    float2 h23 = __half22float2(*(__half2*)&hv.y);
    float2 h45 = __half22float2(*(__half2*)&hv.z);
    float2 h67 = __half22float2(*(__half2*)&hv.w);
    float2 d01 = __half22float2(*(__half2*)&dv.x);
    float2 d23 = __half22float2(*(__half2*)&dv.y);
    float2 d45 = __half22float2(*(__half2*)&dv.z);
    float2 d67 = __half22float2(*(__half2*)&dv.w);
    float v[8];
    v[0] = ep * h01.x + acc0.x + s1 * (d01.x + vp0.x) + swr * u0.x;
    v[1] = ep * h01.y + acc0.y + s1 * (d01.y + vp0.y) + swr * u0.y;
    v[2] = ep * h23.x + acc0.z + s1 * (d23.x + vp0.z) + swr * u0.z;
    v[3] = ep * h23.y + acc0.w + s1 * (d23.y + vp0.w) + swr * u0.w;
    v[4] = ep * h45.x + acc1.x + s1 * (d45.x + vp1.x) + swr * u1.x;
    v[5] = ep * h45.y + acc1.y + s1 * (d45.y + vp1.y) + swr * u1.y;
    v[6] = ep * h67.x + acc1.z + s1 * (d67.x + vp1.z) + swr * u1.z;
    v[7] = ep * h67.y + acc1.w + s1 * (d67.y + vp1.w) + swr * u1.w;
    uint4 rv;
    *(__half2*)&rv.x = __float22half2_rn(make_float2(v[0], v[1]));
    *(__half2*)&rv.y = __float22half2_rn(make_float2(v[2], v[3]));
    *(__half2*)&rv.z = __float22half2_rn(make_float2(v[4], v[5]));
    *(__half2*)&rv.w = __float22half2_rn(make_float2(v[6], v[7]));
    *(uint4*)(g_r + idx) = rv;
}

// layer-0 GLU: h = ga * sigmoid(gb), fp16 in/out
__global__ void glu_kernel(int N) {
    int i = blockIdx.x * blockDim.x + threadIdx.x;
    if (i >= N * HDIM / 2) return;
    float2 ga = __half22float2(((const __half2*)g_ga)[i]);
    float2 gb = __half22float2(((const __half2*)g_gb)[i]);
    float h0 = ga.x * (1.f / (1.f + __expf(-gb.x)));
    float h1 = ga.y * (1.f / (1.f + __expf(-gb.y)));
    ((__half2*)g_hf)[i] = __float22half2_rn(make_float2(h0, h1));
}

// last layer: fused GLU + masked segment-sum from fp16 ga/gb
__global__ void glu_segsum_kernel(const int* __restrict__ mask,
                                  const int* __restrict__ gid, int N) {
    int j  = threadIdx.x;
    int n0 = blockIdx.x * 128;
    if (n0 >= N) return;
    int n1 = min(n0 + 128, N);
    float acc = 0.f;
    int curg = gid[n0];
    for (int n = n0; n < n1; n++) {
        int g = gid[n];
        if (g != curg) {
            atomicAdd(&g_feat[curg * HDIM + j], acc);
            acc = 0.f;
            curg = g;
        }
        if (mask[n]) {
            size_t o = (size_t)n * HDIM + j;
            float ga = __half2float(g_ga[o]);
            float gb = __half2float(g_gb[o]);
            acc += ga * (1.f / (1.f + __expf(-gb)));
        }
    }
    atomicAdd(&g_feat[curg * HDIM + j], acc);
}

__global__ void mlp_kernel(const float* __restrict__ Wm,
                           const float* __restrict__ bm,
                           float* __restrict__ out, float invN) {
    int g = blockIdx.x;
    int o = threadIdx.x;
    if (o >= OUTD) return;
    float s = 0.f;
    for (int j = 0; j < HDIM; j++)
        s += g_feat[g * HDIM + j] * Wm[j * OUTD + o];
    s = s * invN + bm[o];
    out[g * OUTD + o] = 1.f / (1.f + __expf(-s));
}

// ---------------- mma.sync fp16 2-term GEMM (3-stage cp.async pipeline) ------
#define STSZ   30720
#define SOFF_BH 10240
#define SOFF_BL 20480

__global__ __launch_bounds__(256, 2)
void mma_gemm(const __half* __restrict__ A, int M, int Ktot,
              const __half* __restrict__ Bh0, const __half* __restrict__ Bl0,
              const __half* __restrict__ Bh1, const __half* __restrict__ Bl1,
              const float* __restrict__ bias0, const float* __restrict__ bias1,
              const float* __restrict__ coord,           // optional rank-3 addend
              const float* __restrict__ F2v, const float* __restrict__ bfv,
              __half* __restrict__ H0, __half* __restrict__ H1) {
    extern __shared__ char smem[];
    const __half* Bhi = blockIdx.z ? Bh1 : Bh0;
    const __half* Blo = blockIdx.z ? Bl1 : Bl0;
    const float* bias = blockIdx.z ? bias1 : bias0;
    __half* Hout = blockIdx.z ? H1 : H0;

    int tid = threadIdx.x;
    int wid = tid >> 5;
    int lane = tid & 31;
    int warp_m = wid & 3;
    int warp_n = wid >> 2;
    int m0 = blockIdx.x * 128;
    int n0 = blockIdx.y * 128;
    uint32_t sb = smem_to_u32(smem);

    float acc[2][8][4];
#pragma unroll
    for (int a = 0; a < 2; a++)
#pragma unroll
        for (int b = 0; b < 8; b++)
#pragma unroll
            for (int c = 0; c < 4; c++) acc[a][b][c] = 0.f;

    int KT = Ktot >> 5;
    int lrow = (lane & 7) + ((lane >> 3) & 1) * 8;
    int lcol = (lane >> 4) * 8;

    int row0 = tid >> 2,         kc0 = (tid & 3) * 8;
    int row1 = (tid + 256) >> 2, kc1 = (tid & 3) * 8;
    int arow0 = (m0 + row0 < M) ? (m0 + row0) : 0;
    int arow1 = (m0 + row1 < M) ? (m0 + row1) : 0;
    int asz0  = (m0 + row0 < M) ? 16 : 0;
    int asz1  = (m0 + row1 < M) ? 16 : 0;

#define LOAD_STAGE(kt, buf)                                                        \
    do {                                                                           \
        int k0 = (kt) * 32;                                                        \
        uint32_t d0 = sb + (buf) * STSZ + ((uint32_t)row0 * 40 + kc0) * 2;         \
        uint32_t d1 = sb + (buf) * STSZ + ((uint32_t)row1 * 40 + kc1) * 2;         \
        size_t ao0 = (size_t)arow0 * Ktot + k0 + kc0;                              \
        size_t ao1 = (size_t)arow1 * Ktot + k0 + kc1;                              \
        size_t bo0 = (size_t)(n0 + row0) * Ktot + k0 + kc0;                        \
        size_t bo1 = (size_t)(n0 + row1) * Ktot + k0 + kc1;                        \
        cp_async16(d0,           A   + ao0, asz0);                                 \
        cp_async16(d0 + SOFF_BH, Bhi + bo0, 16);                                   \
        cp_async16(d0 + SOFF_BL, Blo + bo0, 16);                                   \
        cp_async16(d1,           A   + ao1, asz1);                                 \
        cp_async16(d1 + SOFF_BH, Bhi + bo1, 16);                                   \
        cp_async16(d1 + SOFF_BL, Blo + bo1, 16);                                   \
    } while (0)

    LOAD_STAGE(0, 0);
    CP_COMMIT();
    LOAD_STAGE(1, 1);
    CP_COMMIT();

    int buf = 0;
#pragma unroll 1
    for (int kt = 0; kt < KT; kt++) {
        if (kt + 1 < KT) CP_WAIT1(); else CP_WAIT0();
        __syncthreads();
        if (kt + 2 < KT) {
            int nb = buf + 2; if (nb >= 3) nb -= 3;
            LOAD_STAGE(kt + 2, nb);
            CP_COMMIT();
        }
#pragma unroll
        for (int ks = 0; ks < 2; ks++) {
            int kc = ks * 16 + lcol;
            uint32_t ah[2][4];
#pragma unroll
            for (int mt = 0; mt < 2; mt++) {
                int r = warp_m * 32 + mt * 16 + lrow;
                ldsm4(ah[mt], sb + buf * STSZ + ((uint32_t)r * 40 + kc) * 2);
            }
#pragma unroll
            for (int ng = 0; ng < 4; ng++) {
                int r = warp_n * 64 + ng * 16 + lrow;
                uint32_t baddr = sb + buf * STSZ + ((uint32_t)r * 40 + kc) * 2 + SOFF_BH;
                uint32_t bh[4], bl[4];
                ldsm4(bh, baddr);
                ldsm4(bl, baddr + (SOFF_BL - SOFF_BH));
#pragma unroll
                for (int mt = 0; mt < 2; mt++) {
                    mma16816(acc[mt][2 * ng],     ah[mt], bh[0], bh[2]);
                    mma16816(acc[mt][2 * ng],     ah[mt], bl[0], bl[2]);
                    mma16816(acc[mt][2 * ng + 1], ah[mt], bh[1], bh[3]);
                    mma16816(acc[mt][2 * ng + 1], ah[mt], bl[1], bl[3]);
                }
            }
        }
        buf++; if (buf == 3) buf = 0;
    }

    // ---- epilogue: fp16 output, optional bias / rank-3 coord addend ----
    int gi = lane >> 2;
    int ci = (lane & 3) * 2;
#pragma unroll
    for (int mt = 0; mt < 2; mt++) {
#pragma unroll
        for (int half_ = 0; half_ < 2; half_++) {
            int row = m0 + warp_m * 32 + mt * 16 + gi + half_ * 8;
            if (row >= M) continue;
            float c0 = 0.f, c1 = 0.f, c2 = 0.f;
            if (coord) {
                c0 = __ldg(&coord[row * 3]);
                c1 = __ldg(&coord[row * 3 + 1]);
                c2 = __ldg(&coord[row * 3 + 2]);
            }
#pragma unroll
            for (int nt = 0; nt < 8; nt++) {
                float* a4 = acc[mt][nt];
                int col = n0 + warp_n * 64 + nt * 8 + ci;
                float v0 = a4[half_ * 2];
                float v1 = a4[half_ * 2 + 1];
                if (bias) {
                    v0 += __ldg(&bias[col]);
                    v1 += __ldg(&bias[col + 1]);
                }
                if (coord) {
                    v0 += c0 * __ldg(&F2v[col])     + c1 * __ldg(&F2v[HDIM + col])
                        + c2 * __ldg(&F2v[2 * HDIM + col])     + __ldg(&bfv[col]);
                    v1 += c0 * __ldg(&F2v[col + 1]) + c1 * __ldg(&F2v[HDIM + col + 1])
                        + c2 * __ldg(&F2v[2 * HDIM + col + 1]) + __ldg(&bfv[col + 1]);
                }
                size_t o = (size_t)row * HDIM + col;
                *(__half2*)(Hout + o) = __float22half2_rn(make_float2(v0, v1));
            }
        }
    }
#undef LOAD_STAGE
}

// ---------------- small fp32 GEMM for the F1 fold (M=118) --------------------
__global__ __launch_bounds__(256, 2)
void sgemm_pair(const float* __restrict__ A, int M,
                const float* __restrict__ B0, const float* __restrict__ B1,
                float* __restrict__ C0, float* __restrict__ C1,
                const float* __restrict__ bias0, const float* __restrict__ bias1) {
    const float* B    = blockIdx.z ? B1 : B0;
    float*       C    = blockIdx.z ? C1 : C0;
    const float* bias = blockIdx.z ? bias1 : bias0;
    __shared__ float As[2][16][132];
    __shared__ float Bs[2][16][128];
    int tid = threadIdx.x;
    int m0 = blockIdx.x * 128;
    int n0 = blockIdx.y * 128;
    int tx = tid & 15, ty = tid >> 4;
    int ar = tid >> 2;
    int ac = (tid & 3) * 4;
    int bk = tid >> 5;
    int bn = (tid & 31) * 4;
    bool aval0 = (m0 + ar) < M;
    bool aval1 = (m0 + ar + 64) < M;
    const float* Arow0 = A + (size_t)(m0 + ar) * HDIM + ac;
    const float* Arow1 = A + (size_t)(m0 + ar + 64) * HDIM + ac;
    const float* Bp0 = B + (size_t)bk * HDIM + n0 + bn;
    const float* Bp1 = B + (size_t)(bk + 8) * HDIM + n0 + bn;
    float4 af0, af1, bf0, bf1;
    const float4 fz = make_float4(0.f, 0.f, 0.f, 0.f);
#define LOADG(k0) do { \
        af0 = aval0 ? *(const float4*)(Arow0 + (k0)) : fz; \
        af1 = aval1 ? *(const float4*)(Arow1 + (k0)) : fz; \
        bf0 = *(const float4*)(Bp0 + (size_t)(k0) * HDIM); \
        bf1 = *(const float4*)(Bp1 + (size_t)(k0) * HDIM); } while (0)
#define STORES(bufi) do { \
        As[bufi][ac + 0][ar] = af0.x; As[bufi][ac + 1][ar] = af0.y; \
        As[bufi][ac + 2][ar] = af0.z; As[bufi][ac + 3][ar] = af0.w; \
        As[bufi][ac + 0][ar + 64] = af1.x; As[bufi][ac + 1][ar + 64] = af1.y; \
        As[bufi][ac + 2][ar + 64] = af1.z; As[bufi][ac + 3][ar + 64] = af1.w; \
        *(float4*)&Bs[bufi][bk][bn] = bf0; *(float4*)&Bs[bufi][bk + 8][bn] = bf1; } while (0)
    float acc[8][8];
#pragma unroll
    for (int i = 0; i < 8; i++)
#pragma unroll
        for (int j = 0; j < 8; j++) acc[i][j] = 0.f;
    LOADG(0);
    STORES(0);
    __syncthreads();
    int buf = 0;
#pragma unroll 1
    for (int kt = 0; kt < 16; kt++) {
        if (kt < 15) LOADG((kt + 1) * 16);
#pragma unroll
        for (int k = 0; k < 16; k++) {
            float4 a0 = *(const float4*)&As[buf][k][ty * 8];
            float4 a1 = *(const float4*)&As[buf][k][ty * 8 + 4];
            float4 b0 = *(const float4*)&Bs[buf][k][tx * 8];
            float4 b1 = *(const float4*)&Bs[buf][k][tx * 8 + 4];
            float a[8] = {a0.x, a0.y, a0.z, a0.w, a1.x, a1.y, a1.z, a1.w};
            float b[8] = {b0.x, b0.y, b0.z, b0.w, b1.x, b1.y, b1.z, b1.w};
#pragma unroll
            for (int i = 0; i < 8; i++)
#pragma unroll
                for (int j = 0; j < 8; j++)
                    acc[i][j] += a[i] * b[j];
        }
        if (kt < 15) { STORES(buf ^ 1); __syncthreads(); buf ^= 1; }
    }
    float bv[8];
#pragma unroll
    for (int j = 0; j < 8; j++) bv[j] = bias ? bias[n0 + tx * 8 + j] : 0.f;
#pragma unroll
    for (int i = 0; i < 8; i++) {
        int mm = m0 + ty * 8 + i;
        if (mm >= M) continue;
        float* Cp = C + (size_t)mm * HDIM + n0 + tx * 8;
        *(float4*)Cp = make_float4(acc[i][0] + bv[0], acc[i][1] + bv[1],
                                   acc[i][2] + bv[2], acc[i][3] + bv[3]);
        *(float4*)(Cp + 4) = make_float4(acc[i][4] + bv[4], acc[i][5] + bv[5],
                                         acc[i][6] + bv[6], acc[i][7] + bv[7]);
    }
#undef LOADG
#undef STORES
}

// ---------------- launcher ---------------------------------------------------
extern "C" void kernel_launch(void* const* d_in, const int* in_sizes, int n_in,
                              void* d_out, int out_size) {
    const float* atomic_num = (const float*)d_in[0];
    const float* coord      = (const float*)d_in[1];
    const float* radius     = (const float*)d_in[2];
    const int*   src        = (const int*)  d_in[3];
    const int*   dst        = (const int*)  d_in[4];
    const int*   abs_mask   = (const int*)  d_in[5];
    const int*   graph_id   = (const int*)  d_in[6];
    const float* W_atom     = (const float*)d_in[7];
    const float* b_atom     = (const float*)d_in[8];
    const float* W_coord    = (const float*)d_in[9];
    const float* b_coord    = (const float*)d_in[10];
    const float* W_node     = (const float*)d_in[11];
    const float* b_node     = (const float*)d_in[12];
    const float* W_edge     = (const float*)d_in[13];
    const float* b_edge     = (const float*)d_in[14];
    const float* W_agg      = (const float*)d_in[15];
    const float* b_agg      = (const float*)d_in[16];
    const float* W_glu_a    = (const float*)d_in[17];
    const float* b_glu_a    = (const float*)d_in[18];
    const float* W_glu_b    = (const float*)d_in[19];
    const float* b_glu_b    = (const float*)d_in[20];
    const float* exp_l      = (const float*)d_in[21];
    const float* eps_l      = (const float*)d_in[22];
    const float* W_mlp      = (const float*)d_in[23];
    const float* b_mlp      = (const float*)d_in[24];
    float* out = (float*)d_out;

    int N = in_sizes[5];
    int E = in_sizes[2];

    float *p_F1, *p_F2, *p_bf;
    __half *p_xa, *p_hf, *p_s, *p_hdh, *p_r, *p_ga, *p_gb, *p_Bh, *p_Bl, *p_Fh, *p_Fl;
    cudaGetSymbolAddress((void**)&p_F1,   g_F1);
    cudaGetSymbolAddress((void**)&p_F2,   g_F2);
    cudaGetSymbolAddress((void**)&p_bf,   g_bf);
    cudaGetSymbolAddress((void**)&p_xa,   g_xa);
    cudaGetSymbolAddress((void**)&p_hf,   g_hf);
    cudaGetSymbolAddress((void**)&p_s,    g_s);
    cudaGetSymbolAddress((void**)&p_hdh,  g_hdh);
    cudaGetSymbolAddress((void**)&p_r,    g_r);
    cudaGetSymbolAddress((void**)&p_ga,   g_ga);
    cudaGetSymbolAddress((void**)&p_gb,   g_gb);
    cudaGetSymbolAddress((void**)&p_Bh,   g_Bt_hi);
    cudaGetSymbolAddress((void**)&p_Bl,   g_Bt_lo);
    cudaGetSymbolAddress((void**)&p_Fh,   g_F1t_hi);
    cudaGetSymbolAddress((void**)&p_Fl,   g_F1t_lo);

    const int MMA_SMEM = 3 * STSZ;
    cudaFuncSetAttribute(mma_gemm, cudaFuncAttributeMaxDynamicSharedMemorySize, MMA_SMEM);

    int mtiles = (N + 127) / 128;
    int eb = (E + 255) / 256;
    int aggb = (N + 7) / 8;

    // CSR build (+zero +x conversion merged)
    pre_conv_x_kernel<<<160, 256>>>(atomic_num, N);
    hist_kernel<<<eb, 256>>>(dst, E);
    scan_kernel<<<1, 1024>>>(N);
    fill_kernel<<<eb, 256>>>(dst, E);

    // folds + conversions
    sgemm_pair<<<dim3(1, 2, 1), 256>>>(W_atom, ATOMD, W_node, W_node, p_F1, p_F1,
                                       nullptr, nullptr);
    fold_uv_kernel<<<3, HDIM>>>(W_coord, W_node, b_atom, b_coord, b_node,
                                W_agg, W_edge, b_edge, b_agg);
    conv_F1t_kernel<<<dim3(8, 4), dim3(32, 8)>>>();
    conv_wT_kernel<<<dim3(8, 8, 8), dim3(32, 8)>>>(W_agg, W_glu_a, W_glu_b);

    // init: h = x@F1 + (coord@F2 + bf) fused in epilogue -> g_hf (fp16)
    mma_gemm<<<dim3(mtiles, 2, 1), 256, MMA_SMEM>>>(
        p_xa, N, 128, p_Fh, p_Fl, p_Fh, p_Fl,
        nullptr, nullptr, coord, p_F2, p_bf, p_hf, p_hf);

    for (int l = 0; l < 2; l++) {
        // z=0: hs -> g_s ; z=1: hd -> g_hdh
        mma_gemm<<<dim3(mtiles, 2, 2), 256, MMA_SMEM>>>(
            p_hf, N, HDIM,
            p_Bh + (size_t)(2 * l) * HH,     p_Bl + (size_t)(2 * l) * HH,
            p_Bh + (size_t)(2 * l + 1) * HH, p_Bl + (size_t)(2 * l + 1) * HH,
            nullptr, nullptr, nullptr, nullptr, nullptr, p_s, p_hdh);
        agg_kernel<<<aggb, 256>>>(src, radius, exp_l, eps_l, l, N);
        // z=0: ga ; z=1: gb  (with biases)
        mma_gemm<<<dim3(mtiles, 2, 2), 256, MMA_SMEM>>>(
            p_r, N, HDIM,
            p_Bh + (size_t)(4 + 2 * l) * HH, p_Bl + (size_t)(4 + 2 * l) * HH,
            p_Bh + (size_t)(5 + 2 * l) * HH, p_Bl + (size_t)(5 + 2 * l) * HH,
            b_glu_a + l * HDIM, b_glu_b + l * HDIM, nullptr, nullptr, nullptr,
            p_ga, p_gb);
        if (l == 0) glu_kernel<<<(N * HDIM / 2 + 255) / 256, 256>>>(N);
    }

    // fused last-layer GLU + masked segment-sum, then MLP head
    glu_segsum_kernel<<<(N + 127) / 128, HDIM>>>(abs_mask, graph_id, N);
    mlp_kernel<<<GN, 128>>>(W_mlp, b_mlp, out, 1.0f / (float)N);
}

// round 15
// speedup vs baseline: 1.4033x; 1.1357x over previous
#include <cuda_runtime.h>
#include <cuda_fp16.h>
#include <stdint.h>
#include <cstdint>
#include <math.h>

#define N_NODES 20000
#define N_EDGES 640000
#define HDIM    256
#define GN      16
#define OUTD    100
#define ATOMD   118
#define HH      (HDIM * HDIM)

// ---------------- scratch ----------------------------------------------------
__device__ __align__(16) float g_uv [2 * 2 * HDIM];      // [layer][u|vp]
__device__ __align__(16) float g_F1 [ATOMD * HDIM];
__device__ __align__(16) float g_F2 [3 * HDIM];
__device__ __align__(16) float g_bf [HDIM];
__device__ __align__(16) float g_feat[GN * HDIM];
__device__ int   g_cnt [N_NODES + 1];
__device__ int   g_offs[N_NODES + 1];
__device__ int   g_wp  [N_NODES];
__device__ int   g_csr [N_EDGES];
// fp16 activations
__device__ __align__(16) __half g_xa [N_NODES * 128];
__device__ __align__(16) __half g_hf [N_NODES * HDIM];   // h
__device__ __align__(16) __half g_s  [N_NODES * HDIM];   // hs (gather src)
__device__ __align__(16) __half g_hdh[N_NODES * HDIM];   // hd
__device__ __align__(16) __half g_r  [N_NODES * HDIM];   // rst
__device__ __align__(16) __half g_ga [N_NODES * HDIM];
__device__ __align__(16) __half g_gb [N_NODES * HDIM];
// fp16 weights (single precision)
__device__ __align__(16) __half g_Bt [8 * HH];
__device__ __align__(16) __half g_F1t[HDIM * 128];

// ---------------- PTX helpers (all sm_80-legal) ------------------------------
__device__ __forceinline__ uint32_t smem_to_u32(const void* p) {
    uint32_t a;
    asm("{ .reg .u64 t; cvta.to.shared.u64 t, %1; cvt.u32.u64 %0, t; }" : "=r"(a) : "l"(p));
    return a;
}
__device__ __forceinline__ void ldsm4(uint32_t* r, uint32_t addr) {
    asm volatile("ldmatrix.sync.aligned.m8n8.x4.shared.b16 {%0,%1,%2,%3}, [%4];"
                 : "=r"(r[0]), "=r"(r[1]), "=r"(r[2]), "=r"(r[3]) : "r"(addr));
}
__device__ __forceinline__ void mma16816(float* c, const uint32_t* a, uint32_t b0, uint32_t b1) {
    asm volatile("mma.sync.aligned.m16n8k16.row.col.f32.f16.f16.f32 "
                 "{%0,%1,%2,%3}, {%4,%5,%6,%7}, {%8,%9}, {%0,%1,%2,%3};"
                 : "+f"(c[0]), "+f"(c[1]), "+f"(c[2]), "+f"(c[3])
                 : "r"(a[0]), "r"(a[1]), "r"(a[2]), "r"(a[3]), "r"(b0), "r"(b1));
}
__device__ __forceinline__ void cp_async16(uint32_t d, const void* s, int src_sz) {
    asm volatile("cp.async.cg.shared.global [%0], [%1], 16, %2;"
                 :: "r"(d), "l"(s), "r"(src_sz) : "memory");
}
#define CP_COMMIT() asm volatile("cp.async.commit_group;" ::: "memory")
#define CP_WAIT0()  asm volatile("cp.async.wait_group 0;" ::: "memory")
#define CP_WAIT1()  asm volatile("cp.async.wait_group 1;" ::: "memory")

// ---------------- CSR build + init zero + x conversion (merged) ---------------
__global__ void pre_conv_x_kernel(const float* __restrict__ x, int N) {
    int stride = gridDim.x * blockDim.x;
    int i = blockIdx.x * blockDim.x + threadIdx.x;
    for (int t = i; t < N + 1; t += stride) g_cnt[t] = 0;
    for (int t = i; t < GN * HDIM; t += stride) g_feat[t] = 0.f;
    for (int e = i; e < N * 128; e += stride) {
        int n = e >> 7, kk = e & 127;
        float v = (kk < ATOMD) ? x[n * ATOMD + kk] : 0.f;
        g_xa[e] = __float2half(v);
    }
}
__global__ void hist_kernel(const int* __restrict__ dst, int E) {
    int e = blockIdx.x * blockDim.x + threadIdx.x;
    if (e < E) atomicAdd(&g_cnt[dst[e]], 1);
}
__global__ void scan_kernel(int N) {
    __shared__ int partial[1024];
    int t = threadIdx.x;
    int per = (N + 1023) / 1024;
    int start = t * per;
    int stop  = min(start + per, N);
    int sum = 0;
    for (int i = start; i < stop; i++) sum += g_cnt[i];
    partial[t] = sum;
    __syncthreads();
    for (int d = 1; d < 1024; d <<= 1) {
        int v = (t >= d) ? partial[t - d] : 0;
        __syncthreads();
        partial[t] += v;
        __syncthreads();
    }
    int run = (t == 0) ? 0 : partial[t - 1];
    for (int i = start; i < stop; i++) {
        g_offs[i] = run;
        g_wp[i]   = run;
        run += g_cnt[i];
    }
    if (t == 1023) g_offs[N] = partial[1023];
}
__global__ void fill_kernel(const int* __restrict__ dst, int E) {
    int e = blockIdx.x * blockDim.x + threadIdx.x;
    if (e < E) {
        int pos = atomicAdd(&g_wp[dst[e]], 1);
        g_csr[pos] = e;
    }
}

// ---------------- weight folding (fold_small + uv merged) --------------------
__global__ void fold_uv_kernel(const float* __restrict__ Wc,
                               const float* __restrict__ Wn,
                               const float* __restrict__ ba,
                               const float* __restrict__ bc,
                               const float* __restrict__ bn,
                               const float* __restrict__ W_agg,
                               const float* __restrict__ Wedge,
                               const float* __restrict__ bedge,
                               const float* __restrict__ b_agg) {
    int j = threadIdx.x;
    if (blockIdx.x == 0) {
        float f0 = 0.f, f1 = 0.f, f2 = 0.f, bias = 0.f;
        for (int h = 0; h < HDIM; h++) {
            float wtop = Wn[h * HDIM + j];
            float wbot = Wn[(HDIM + h) * HDIM + j];
            f0 += Wc[0 * HDIM + h] * wbot;
            f1 += Wc[1 * HDIM + h] * wbot;
            f2 += Wc[2 * HDIM + h] * wbot;
            bias += ba[h] * wtop + bc[h] * wbot;
        }
        g_F2[0 * HDIM + j] = f0;
        g_F2[1 * HDIM + j] = f1;
        g_F2[2 * HDIM + j] = f2;
        g_bf[j] = bias + bn[j];
    } else {
        int l = blockIdx.x - 1;
        const float* We = W_agg + (size_t)l * 3 * HH + HH;
        float u = 0.f, v = 0.f;
        for (int k = 0; k < HDIM; k++) {
            float we = We[k * HDIM + j];
            u += Wedge[k] * we;
            v += bedge[k] * we;
        }
        g_uv[l * 2 * HDIM + j] = u;
        g_uv[l * 2 * HDIM + HDIM + j] = v + b_agg[l * HDIM + j];
    }
}

// coalesced SMEM tile transpose + fp16: Bt[n][k] = W[k][n]
__global__ void conv_wT_kernel(const float* __restrict__ W_agg,
                               const float* __restrict__ W_glu_a,
                               const float* __restrict__ W_glu_b) {
    __shared__ float tile[32][33];
    int z = blockIdx.z;
    const float* src;
    switch (z) {
        case 0: src = W_agg; break;
        case 1: src = W_agg + 2 * HH; break;
        case 2: src = W_agg + 3 * HH; break;
        case 3: src = W_agg + 5 * HH; break;
        case 4: src = W_glu_a; break;
        case 5: src = W_glu_b; break;
        case 6: src = W_glu_a + HH; break;
        default: src = W_glu_b + HH; break;
    }
    int n0 = blockIdx.x * 32;
    int k0 = blockIdx.y * 32;
    int tx = threadIdx.x, ty = threadIdx.y;
#pragma unroll
    for (int q = 0; q < 4; q++) {
        int k = k0 + ty + q * 8;
        tile[ty + q * 8][tx] = src[(size_t)k * HDIM + n0 + tx];
    }
    __syncthreads();
#pragma unroll
    for (int q = 0; q < 4; q++) {
        int n = n0 + ty + q * 8;
        size_t o = (size_t)z * HH + (size_t)n * HDIM + k0 + tx;
        g_Bt[o] = __float2half(tile[tx][ty + q * 8]);
    }
}

// coalesced transpose of F1 [118,256] -> F1t [256,128] fp16
__global__ void conv_F1t_kernel() {
    __shared__ float tile[32][33];
    int n0 = blockIdx.x * 32;
    int k0 = blockIdx.y * 32;
    int tx = threadIdx.x, ty = threadIdx.y;
#pragma unroll
    for (int q = 0; q < 4; q++) {
        int k = k0 + ty + q * 8;
        tile[ty + q * 8][tx] = (k < ATOMD) ? g_F1[(size_t)k * HDIM + n0 + tx] : 0.f;
    }
    __syncthreads();
#pragma unroll
    for (int q = 0; q < 4; q++) {
        int n = n0 + ty + q * 8;
        size_t o = (size_t)n * 128 + k0 + tx;
        g_F1t[o] = __float2half(tile[tx][ty + q * 8]);
    }
}

// ---------------- warp-per-node aggregation (fp16 gather) --------------------
__global__ void agg_kernel(const int* __restrict__ src,
                           const float* __restrict__ radius,
                           const float* __restrict__ exp_l,
                           const float* __restrict__ eps_l, int l, int N) {
    int warp = (blockIdx.x * blockDim.x + threadIdx.x) >> 5;
    int lane = threadIdx.x & 31;
    if (warp >= N) return;
    float el = __ldg(&exp_l[l]);
    const float* uvb = g_uv + l * 2 * HDIM;
    int beg = g_offs[warp], end = g_offs[warp + 1];
    float4 acc0 = make_float4(0.f, 0.f, 0.f, 0.f);
    float4 acc1 = make_float4(0.f, 0.f, 0.f, 0.f);
    float s1 = 0.f, swr = 0.f;
    int j0 = lane * 8;
    for (int base = beg; base < end; base += 32) {
        int p = base + lane;
        int s = 0;
        float w = 0.f;
        if (p < end) {
            int e = g_csr[p];
            s = src[e];
            float r = radius[e];
            w = __expf(__logf(r) * el);
            s1 += w;
            swr += w * r;
        }
        int cnt = min(32, end - base);
        for (int q = 0; q < cnt; q++) {
            int   sq = __shfl_sync(0xffffffffu, s, q);
            float wq = __shfl_sync(0xffffffffu, w, q);
            uint4 pv = *(const uint4*)(g_s + (size_t)sq * HDIM + j0);
            float2 f0 = __half22float2(*(__half2*)&pv.x);
            float2 f1 = __half22float2(*(__half2*)&pv.y);
            float2 f2 = __half22float2(*(__half2*)&pv.z);
            float2 f3 = __half22float2(*(__half2*)&pv.w);
            acc0.x += wq * f0.x; acc0.y += wq * f0.y;
            acc0.z += wq * f1.x; acc0.w += wq * f1.y;
            acc1.x += wq * f2.x; acc1.y += wq * f2.y;
            acc1.z += wq * f3.x; acc1.w += wq * f3.y;
        }
    }
#pragma unroll
    for (int off = 16; off; off >>= 1) {
        s1  += __shfl_xor_sync(0xffffffffu, s1, off);
        swr += __shfl_xor_sync(0xffffffffu, swr, off);
    }
    float ep = 1.f + __ldg(&eps_l[l]);
    float4 u0  = *(const float4*)(uvb + j0);
    float4 u1  = *(const float4*)(uvb + j0 + 4);
    float4 vp0 = *(const float4*)(uvb + HDIM + j0);
    float4 vp1 = *(const float4*)(uvb + HDIM + j0 + 4);
    size_t idx = (size_t)warp * HDIM + j0;
    uint4 hv = *(const uint4*)(g_hf + idx);
    uint4 dv = *(const uint4*)(g_hdh + idx);
    float2 h01 = __half22float2(*(__half2*)&hv.x);
    float2 h23 = __half22float2(*(__half2*)&hv.y);
    float2 h45 = __half22float2(*(__half2*)&hv.z);
    float2 h67 = __half22float2(*(__half2*)&hv.w);
    float2 d01 = __half22float2(*(__half2*)&dv.x);
    float2 d23 = __half22float2(*(__half2*)&dv.y);
    float2 d45 = __half22float2(*(__half2*)&dv.z);
    float2 d67 = __half22float2(*(__half2*)&dv.w);
    float v[8];
    v[0] = ep * h01.x + acc0.x + s1 * (d01.x + vp0.x) + swr * u0.x;
    v[1] = ep * h01.y + acc0.y + s1 * (d01.y + vp0.y) + swr * u0.y;
    v[2] = ep * h23.x + acc0.z + s1 * (d23.x + vp0.z) + swr * u0.z;
    v[3] = ep * h23.y + acc0.w + s1 * (d23.y + vp0.w) + swr * u0.w;
    v[4] = ep * h45.x + acc1.x + s1 * (d45.x + vp1.x) + swr * u1.x;
    v[5] = ep * h45.y + acc1.y + s1 * (d45.y + vp1.y) + swr * u1.y;
    v[6] = ep * h67.x + acc1.z + s1 * (d67.x + vp1.z) + swr * u1.z;
    v[7] = ep * h67.y + acc1.w + s1 * (d67.y + vp1.w) + swr * u1.w;
    uint4 rv;
    *(__half2*)&rv.x = __float22half2_rn(make_float2(v[0], v[1]));
    *(__half2*)&rv.y = __float22half2_rn(make_float2(v[2], v[3]));
    *(__half2*)&rv.z = __float22half2_rn(make_float2(v[4], v[5]));
    *(__half2*)&rv.w = __float22half2_rn(make_float2(v[6], v[7]));
    *(uint4*)(g_r + idx) = rv;
}

// layer-0 GLU: h = ga * sigmoid(gb), fp16 in/out
__global__ void glu_kernel(int N) {
    int i = blockIdx.x * blockDim.x + threadIdx.x;
    if (i >= N * HDIM / 2) return;
    float2 ga = __half22float2(((const __half2*)g_ga)[i]);
    float2 gb = __half22float2(((const __half2*)g_gb)[i]);
    float h0 = ga.x * (1.f / (1.f + __expf(-gb.x)));
    float h1 = ga.y * (1.f / (1.f + __expf(-gb.y)));
    ((__half2*)g_hf)[i] = __float22half2_rn(make_float2(h0, h1));
}

// last layer: fused GLU + masked segment-sum from fp16 ga/gb
__global__ void glu_segsum_kernel(const int* __restrict__ mask,
                                  const int* __restrict__ gid, int N) {
    int j  = threadIdx.x;
    int n0 = blockIdx.x * 128;
    if (n0 >= N) return;
    int n1 = min(n0 + 128, N);
    float acc = 0.f;
    int curg = gid[n0];
    for (int n = n0; n < n1; n++) {
        int g = gid[n];
        if (g != curg) {
            atomicAdd(&g_feat[curg * HDIM + j], acc);
            acc = 0.f;
            curg = g;
        }
        if (mask[n]) {
            size_t o = (size_t)n * HDIM + j;
            float ga = __half2float(g_ga[o]);
            float gb = __half2float(g_gb[o]);
            acc += ga * (1.f / (1.f + __expf(-gb)));
        }
    }
    atomicAdd(&g_feat[curg * HDIM + j], acc);
}

__global__ void mlp_kernel(const float* __restrict__ Wm,
                           const float* __restrict__ bm,
                           float* __restrict__ out, float invN) {
    int g = blockIdx.x;
    int o = threadIdx.x;
    if (o >= OUTD) return;
    float s = 0.f;
    for (int j = 0; j < HDIM; j++)
        s += g_feat[g * HDIM + j] * Wm[j * OUTD + o];
    s = s * invN + bm[o];
    out[g * OUTD + o] = 1.f / (1.f + __expf(-s));
}

// ---------------- mma.sync fp16 GEMM (3-stage cp.async pipeline) -------------
// C[M,256] = A @ B^T ; A, B single fp16. Stage = A(10240) + B(10240).
#define STSZ   20480
#define SOFF_B 10240

__global__ __launch_bounds__(256, 2)
void mma_gemm(const __half* __restrict__ A, int M, int Ktot,
              const __half* __restrict__ B0, const __half* __restrict__ B1,
              const float* __restrict__ bias0, const float* __restrict__ bias1,
              const float* __restrict__ coord,           // optional rank-3 addend
              const float* __restrict__ F2v, const float* __restrict__ bfv,
              __half* __restrict__ H0, __half* __restrict__ H1) {
    extern __shared__ char smem[];
    const __half* B = blockIdx.z ? B1 : B0;
    const float* bias = blockIdx.z ? bias1 : bias0;
    __half* Hout = blockIdx.z ? H1 : H0;

    int tid = threadIdx.x;
    int wid = tid >> 5;
    int lane = tid & 31;
    int warp_m = wid & 3;
    int warp_n = wid >> 2;
    int m0 = blockIdx.x * 128;
    int n0 = blockIdx.y * 128;
    uint32_t sb = smem_to_u32(smem);

    float acc[2][8][4];
#pragma unroll
    for (int a = 0; a < 2; a++)
#pragma unroll
        for (int b = 0; b < 8; b++)
#pragma unroll
            for (int c = 0; c < 4; c++) acc[a][b][c] = 0.f;

    int KT = Ktot >> 5;
    int lrow = (lane & 7) + ((lane >> 3) & 1) * 8;
    int lcol = (lane >> 4) * 8;

    int row0 = tid >> 2,         kc0 = (tid & 3) * 8;
    int row1 = (tid + 256) >> 2, kc1 = (tid & 3) * 8;
    int arow0 = (m0 + row0 < M) ? (m0 + row0) : 0;
    int arow1 = (m0 + row1 < M) ? (m0 + row1) : 0;
    int asz0  = (m0 + row0 < M) ? 16 : 0;
    int asz1  = (m0 + row1 < M) ? 16 : 0;

#define LOAD_STAGE(kt, buf)                                                        \
    do {                                                                           \
        int k0 = (kt) * 32;                                                        \
        uint32_t d0 = sb + (buf) * STSZ + ((uint32_t)row0 * 40 + kc0) * 2;         \
        uint32_t d1 = sb + (buf) * STSZ + ((uint32_t)row1 * 40 + kc1) * 2;         \
        size_t ao0 = (size_t)arow0 * Ktot + k0 + kc0;                              \
        size_t ao1 = (size_t)arow1 * Ktot + k0 + kc1;                              \
        size_t bo0 = (size_t)(n0 + row0) * Ktot + k0 + kc0;                        \
        size_t bo1 = (size_t)(n0 + row1) * Ktot + k0 + kc1;                        \
        cp_async16(d0,          A + ao0, asz0);                                    \
        cp_async16(d0 + SOFF_B, B + bo0, 16);                                      \
        cp_async16(d1,          A + ao1, asz1);                                    \
        cp_async16(d1 + SOFF_B, B + bo1, 16);                                      \
    } while (0)

    LOAD_STAGE(0, 0);
    CP_COMMIT();
    LOAD_STAGE(1, 1);
    CP_COMMIT();

    int buf = 0;
#pragma unroll 1
    for (int kt = 0; kt < KT; kt++) {
        if (kt + 1 < KT) CP_WAIT1(); else CP_WAIT0();
        __syncthreads();
        if (kt + 2 < KT) {
            int nb = buf + 2; if (nb >= 3) nb -= 3;
            LOAD_STAGE(kt + 2, nb);
            CP_COMMIT();
        }
#pragma unroll
        for (int ks = 0; ks < 2; ks++) {
            int kc = ks * 16 + lcol;
            uint32_t ah[2][4];
#pragma unroll
            for (int mt = 0; mt < 2; mt++) {
                int r = warp_m * 32 + mt * 16 + lrow;
                ldsm4(ah[mt], sb + buf * STSZ + ((uint32_t)r * 40 + kc) * 2);
            }
#pragma unroll
            for (int ng = 0; ng < 4; ng++) {
                int r = warp_n * 64 + ng * 16 + lrow;
                uint32_t bh[4];
                ldsm4(bh, sb + buf * STSZ + ((uint32_t)r * 40 + kc) * 2 + SOFF_B);
#pragma unroll
                for (int mt = 0; mt < 2; mt++) {
                    mma16816(acc[mt][2 * ng],     ah[mt], bh[0], bh[2]);
                    mma16816(acc[mt][2 * ng + 1], ah[mt], bh[1], bh[3]);
                }
            }
        }
        buf++; if (buf == 3) buf = 0;
    }

    // ---- epilogue: fp16 output, optional bias / rank-3 coord addend ----
    int gi = lane >> 2;
    int ci = (lane & 3) * 2;
#pragma unroll
    for (int mt = 0; mt < 2; mt++) {
#pragma unroll
        for (int half_ = 0; half_ < 2; half_++) {
            int row = m0 + warp_m * 32 + mt * 16 + gi + half_ * 8;
            if (row >= M) continue;
            float c0 = 0.f, c1 = 0.f, c2 = 0.f;
            if (coord) {
                c0 = __ldg(&coord[row * 3]);
                c1 = __ldg(&coord[row * 3 + 1]);
                c2 = __ldg(&coord[row * 3 + 2]);
            }
#pragma unroll
            for (int nt = 0; nt < 8; nt++) {
                float* a4 = acc[mt][nt];
                int col = n0 + warp_n * 64 + nt * 8 + ci;
                float v0 = a4[half_ * 2];
                float v1 = a4[half_ * 2 + 1];
                if (bias) {
                    v0 += __ldg(&bias[col]);
                    v1 += __ldg(&bias[col + 1]);
                }
                if (coord) {
                    v0 += c0 * __ldg(&F2v[col])     + c1 * __ldg(&F2v[HDIM + col])
                        + c2 * __ldg(&F2v[2 * HDIM + col])     + __ldg(&bfv[col]);
                    v1 += c0 * __ldg(&F2v[col + 1]) + c1 * __ldg(&F2v[HDIM + col + 1])
                        + c2 * __ldg(&F2v[2 * HDIM + col + 1]) + __ldg(&bfv[col + 1]);
                }
                size_t o = (size_t)row * HDIM + col;
                *(__half2*)(Hout + o) = __float22half2_rn(make_float2(v0, v1));
            }
        }
    }
#undef LOAD_STAGE
}

// ---------------- small fp32 GEMM for the F1 fold (M=118) --------------------
__global__ __launch_bounds__(256, 2)
void sgemm_pair(const float* __restrict__ A, int M,
                const float* __restrict__ B0, const float* __restrict__ B1,
                float* __restrict__ C0, float* __restrict__ C1,
                const float* __restrict__ bias0, const float* __restrict__ bias1) {
    const float* B    = blockIdx.z ? B1 : B0;
    float*       C    = blockIdx.z ? C1 : C0;
    const float* bias = blockIdx.z ? bias1 : bias0;
    __shared__ float As[2][16][132];
    __shared__ float Bs[2][16][128];
    int tid = threadIdx.x;
    int m0 = blockIdx.x * 128;
    int n0 = blockIdx.y * 128;
    int tx = tid & 15, ty = tid >> 4;
    int ar = tid >> 2;
    int ac = (tid & 3) * 4;
    int bk = tid >> 5;
    int bn = (tid & 31) * 4;
    bool aval0 = (m0 + ar) < M;
    bool aval1 = (m0 + ar + 64) < M;
    const float* Arow0 = A + (size_t)(m0 + ar) * HDIM + ac;
    const float* Arow1 = A + (size_t)(m0 + ar + 64) * HDIM + ac;
    const float* Bp0 = B + (size_t)bk * HDIM + n0 + bn;
    const float* Bp1 = B + (size_t)(bk + 8) * HDIM + n0 + bn;
    float4 af0, af1, bf0, bf1;
    const float4 fz = make_float4(0.f, 0.f, 0.f, 0.f);
#define LOADG(k0) do { \
        af0 = aval0 ? *(const float4*)(Arow0 + (k0)) : fz; \
        af1 = aval1 ? *(const float4*)(Arow1 + (k0)) : fz; \
        bf0 = *(const float4*)(Bp0 + (size_t)(k0) * HDIM); \
        bf1 = *(const float4*)(Bp1 + (size_t)(k0) * HDIM); } while (0)
#define STORES(bufi) do { \
        As[bufi][ac + 0][ar] = af0.x; As[bufi][ac + 1][ar] = af0.y; \
        As[bufi][ac + 2][ar] = af0.z; As[bufi][ac + 3][ar] = af0.w; \
        As[bufi][ac + 0][ar + 64] = af1.x; As[bufi][ac + 1][ar + 64] = af1.y; \
        As[bufi][ac + 2][ar + 64] = af1.z; As[bufi][ac + 3][ar + 64] = af1.w; \
        *(float4*)&Bs[bufi][bk][bn] = bf0; *(float4*)&Bs[bufi][bk + 8][bn] = bf1; } while (0)
    float acc[8][8];
#pragma unroll
    for (int i = 0; i < 8; i++)
#pragma unroll
        for (int j = 0; j < 8; j++) acc[i][j] = 0.f;
    LOADG(0);
    STORES(0);
    __syncthreads();
    int buf = 0;
#pragma unroll 1
    for (int kt = 0; kt < 16; kt++) {
        if (kt < 15) LOADG((kt + 1) * 16);
#pragma unroll
        for (int k = 0; k < 16; k++) {
            float4 a0 = *(const float4*)&As[buf][k][ty * 8];
            float4 a1 = *(const float4*)&As[buf][k][ty * 8 + 4];
            float4 b0 = *(const float4*)&Bs[buf][k][tx * 8];
            float4 b1 = *(const float4*)&Bs[buf][k][tx * 8 + 4];
            float a[8] = {a0.x, a0.y, a0.z, a0.w, a1.x, a1.y, a1.z, a1.w};
            float b[8] = {b0.x, b0.y, b0.z, b0.w, b1.x, b1.y, b1.z, b1.w};
#pragma unroll
            for (int i = 0; i < 8; i++)
#pragma unroll
                for (int j = 0; j < 8; j++)
                    acc[i][j] += a[i] * b[j];
        }
        if (kt < 15) { STORES(buf ^ 1); __syncthreads(); buf ^= 1; }
    }
    float bv[8];
#pragma unroll
    for (int j = 0; j < 8; j++) bv[j] = bias ? bias[n0 + tx * 8 + j] : 0.f;
#pragma unroll
    for (int i = 0; i < 8; i++) {
        int mm = m0 + ty * 8 + i;
        if (mm >= M) continue;
        float* Cp = C + (size_t)mm * HDIM + n0 + tx * 8;
        *(float4*)Cp = make_float4(acc[i][0] + bv[0], acc[i][1] + bv[1],
                                   acc[i][2] + bv[2], acc[i][3] + bv[3]);
        *(float4*)(Cp + 4) = make_float4(acc[i][4] + bv[4], acc[i][5] + bv[5],
                                         acc[i][6] + bv[6], acc[i][7] + bv[7]);
    }
#undef LOADG
#undef STORES
}

// ---------------- launcher ---------------------------------------------------
extern "C" void kernel_launch(void* const* d_in, const int* in_sizes, int n_in,
                              void* d_out, int out_size) {
    const float* atomic_num = (const float*)d_in[0];
    const float* coord      = (const float*)d_in[1];
    const float* radius     = (const float*)d_in[2];
    const int*   src        = (const int*)  d_in[3];
    const int*   dst        = (const int*)  d_in[4];
    const int*   abs_mask   = (const int*)  d_in[5];
    const int*   graph_id   = (const int*)  d_in[6];
    const float* W_atom     = (const float*)d_in[7];
    const float* b_atom     = (const float*)d_in[8];
    const float* W_coord    = (const float*)d_in[9];
    const float* b_coord    = (const float*)d_in[10];
    const float* W_node     = (const float*)d_in[11];
    const float* b_node     = (const float*)d_in[12];
    const float* W_edge     = (const float*)d_in[13];
    const float* b_edge     = (const float*)d_in[14];
    const float* W_agg      = (const float*)d_in[15];
    const float* b_agg      = (const float*)d_in[16];
    const float* W_glu_a    = (const float*)d_in[17];
    const float* b_glu_a    = (const float*)d_in[18];
    const float* W_glu_b    = (const float*)d_in[19];
    const float* b_glu_b    = (const float*)d_in[20];
    const float* exp_l      = (const float*)d_in[21];
    const float* eps_l      = (const float*)d_in[22];
    const float* W_mlp      = (const float*)d_in[23];
    const float* b_mlp      = (const float*)d_in[24];
    float* out = (float*)d_out;

    int N = in_sizes[5];
    int E = in_sizes[2];

    float *p_F1, *p_F2, *p_bf;
    __half *p_xa, *p_hf, *p_s, *p_hdh, *p_r, *p_ga, *p_gb, *p_Bt, *p_Ft;
    cudaGetSymbolAddress((void**)&p_F1,   g_F1);
    cudaGetSymbolAddress((void**)&p_F2,   g_F2);
    cudaGetSymbolAddress((void**)&p_bf,   g_bf);
    cudaGetSymbolAddress((void**)&p_xa,   g_xa);
    cudaGetSymbolAddress((void**)&p_hf,   g_hf);
    cudaGetSymbolAddress((void**)&p_s,    g_s);
    cudaGetSymbolAddress((void**)&p_hdh,  g_hdh);
    cudaGetSymbolAddress((void**)&p_r,    g_r);
    cudaGetSymbolAddress((void**)&p_ga,   g_ga);
    cudaGetSymbolAddress((void**)&p_gb,   g_gb);
    cudaGetSymbolAddress((void**)&p_Bt,   g_Bt);
    cudaGetSymbolAddress((void**)&p_Ft,   g_F1t);

    const int MMA_SMEM = 3 * STSZ;
    cudaFuncSetAttribute(mma_gemm, cudaFuncAttributeMaxDynamicSharedMemorySize, MMA_SMEM);

    int mtiles = (N + 127) / 128;
    int eb = (E + 255) / 256;
    int aggb = (N + 7) / 8;

    // CSR build (+zero +x conversion merged)
    pre_conv_x_kernel<<<160, 256>>>(atomic_num, N);
    hist_kernel<<<eb, 256>>>(dst, E);
    scan_kernel<<<1, 1024>>>(N);
    fill_kernel<<<eb, 256>>>(dst, E);

    // folds + conversions
    sgemm_pair<<<dim3(1, 2, 1), 256>>>(W_atom, ATOMD, W_node, W_node, p_F1, p_F1,
                                       nullptr, nullptr);
    fold_uv_kernel<<<3, HDIM>>>(W_coord, W_node, b_atom, b_coord, b_node,
                                W_agg, W_edge, b_edge, b_agg);
    conv_F1t_kernel<<<dim3(8, 4), dim3(32, 8)>>>();
    conv_wT_kernel<<<dim3(8, 8, 8), dim3(32, 8)>>>(W_agg, W_glu_a, W_glu_b);

    // init: h = x@F1 + (coord@F2 + bf) fused in epilogue -> g_hf (fp16)
    mma_gemm<<<dim3(mtiles, 2, 1), 256, MMA_SMEM>>>(
        p_xa, N, 128, p_Ft, p_Ft,
        nullptr, nullptr, coord, p_F2, p_bf, p_hf, p_hf);

    for (int l = 0; l < 2; l++) {
        // z=0: hs -> g_s ; z=1: hd -> g_hdh
        mma_gemm<<<dim3(mtiles, 2, 2), 256, MMA_SMEM>>>(
            p_hf, N, HDIM,
            p_Bt + (size_t)(2 * l) * HH, p_Bt + (size_t)(2 * l + 1) * HH,
            nullptr, nullptr, nullptr, nullptr, nullptr, p_s, p_hdh);
        agg_kernel<<<aggb, 256>>>(src, radius, exp_l, eps_l, l, N);
        // z=0: ga ; z=1: gb  (with biases)
        mma_gemm<<<dim3(mtiles, 2, 2), 256, MMA_SMEM>>>(
            p_r, N, HDIM,
            p_Bt + (size_t)(4 + 2 * l) * HH, p_Bt + (size_t)(5 + 2 * l) * HH,
            b_glu_a + l * HDIM, b_glu_b + l * HDIM, nullptr, nullptr, nullptr,
            p_ga, p_gb);
        if (l == 0) glu_kernel<<<(N * HDIM / 2 + 255) / 256, 256>>>(N);
    }

    // fused last-layer GLU + masked segment-sum, then MLP head
    glu_segsum_kernel<<<(N + 127) / 128, HDIM>>>(abs_mask, graph_id, N);
    mlp_kernel<<<GN, 128>>>(W_mlp, b_mlp, out, 1.0f / (float)N);
}

// round 16
// speedup vs baseline: 1.4792x; 1.0541x over previous
#include <cuda_runtime.h>
#include <cuda_fp16.h>
#include <stdint.h>
#include <cstdint>
#include <math.h>

#define N_NODES 20000
#define N_EDGES 640000
#define HDIM    256
#define GN      16
#define OUTD    100
#define ATOMD   118
#define HH      (HDIM * HDIM)

// ---------------- scratch ----------------------------------------------------
__device__ __align__(16) float g_uv [2 * 2 * HDIM];      // [layer][u|vp]
__device__ __align__(16) float g_F2 [3 * HDIM];
__device__ __align__(16) float g_bf [HDIM];
__device__ __align__(16) float g_feat[GN * HDIM];        // zero-init; re-zeroed by mlp
__device__ int   g_cnt [N_NODES + 1];                    // zero-init; re-zeroed by scan
__device__ int   g_offs[N_NODES + 1];
__device__ int   g_wp  [N_NODES];
__device__ int   g_csr [N_EDGES];
// fp16 activations
__device__ __align__(16) __half g_xa [N_NODES * 128];
__device__ __align__(16) __half g_hf [N_NODES * HDIM];   // h
__device__ __align__(16) __half g_s  [N_NODES * HDIM];   // hs (gather src)
__device__ __align__(16) __half g_hdh[N_NODES * HDIM];   // hd
__device__ __align__(16) __half g_r  [N_NODES * HDIM];   // rst
__device__ __align__(16) __half g_ga [N_NODES * HDIM];
__device__ __align__(16) __half g_gb [N_NODES * HDIM];
// fp16 weights
__device__ __align__(16) __half g_Bt [8 * HH];
__device__ __align__(16) __half g_F1t[HDIM * 128];       // zero-init (cols 118..127 stay 0)

// ---------------- PTX helpers (all sm_80-legal) ------------------------------
__device__ __forceinline__ uint32_t smem_to_u32(const void* p) {
    uint32_t a;
    asm("{ .reg .u64 t; cvta.to.shared.u64 t, %1; cvt.u32.u64 %0, t; }" : "=r"(a) : "l"(p));
    return a;
}
__device__ __forceinline__ void ldsm4(uint32_t* r, uint32_t addr) {
    asm volatile("ldmatrix.sync.aligned.m8n8.x4.shared.b16 {%0,%1,%2,%3}, [%4];"
                 : "=r"(r[0]), "=r"(r[1]), "=r"(r[2]), "=r"(r[3]) : "r"(addr));
}
__device__ __forceinline__ void mma16816(float* c, const uint32_t* a, uint32_t b0, uint32_t b1) {
    asm volatile("mma.sync.aligned.m16n8k16.row.col.f32.f16.f16.f32 "
                 "{%0,%1,%2,%3}, {%4,%5,%6,%7}, {%8,%9}, {%0,%1,%2,%3};"
                 : "+f"(c[0]), "+f"(c[1]), "+f"(c[2]), "+f"(c[3])
                 : "r"(a[0]), "r"(a[1]), "r"(a[2]), "r"(a[3]), "r"(b0), "r"(b1));
}
__device__ __forceinline__ void cp_async16(uint32_t d, const void* s, int src_sz) {
    asm volatile("cp.async.cg.shared.global [%0], [%1], 16, %2;"
                 :: "r"(d), "l"(s), "r"(src_sz) : "memory");
}
#define CP_COMMIT() asm volatile("cp.async.commit_group;" ::: "memory")
#define CP_WAIT0()  asm volatile("cp.async.wait_group 0;" ::: "memory")
#define CP_WAIT1()  asm volatile("cp.async.wait_group 1;" ::: "memory")
#define CP_WAIT2()  asm volatile("cp.async.wait_group 2;" ::: "memory")

// ---------------- pre: x conversion + dst histogram (cnt pre-zeroed) ----------
__global__ void pre_kernel(const float* __restrict__ x,
                           const int* __restrict__ dst, int N, int E) {
    int stride = gridDim.x * blockDim.x;
    int i = blockIdx.x * blockDim.x + threadIdx.x;
    for (int e = i; e < N * 128; e += stride) {
        int n = e >> 7, kk = e & 127;
        float v = (kk < ATOMD) ? x[n * ATOMD + kk] : 0.f;
        g_xa[e] = __float2half(v);
    }
    for (int e = i; e < E; e += stride) atomicAdd(&g_cnt[dst[e]], 1);
}
__global__ void scan_kernel(int N) {
    __shared__ int partial[1024];
    int t = threadIdx.x;
    int per = (N + 1023) / 1024;
    int start = t * per;
    int stop  = min(start + per, N);
    int sum = 0;
    for (int i = start; i < stop; i++) sum += g_cnt[i];
    partial[t] = sum;
    __syncthreads();
    for (int d = 1; d < 1024; d <<= 1) {
        int v = (t >= d) ? partial[t - d] : 0;
        __syncthreads();
        partial[t] += v;
        __syncthreads();
    }
    int run = (t == 0) ? 0 : partial[t - 1];
    for (int i = start; i < stop; i++) {
        g_offs[i] = run;
        g_wp[i]   = run;
        run += g_cnt[i];
        g_cnt[i] = 0;                    // restore zero for next launch
    }
    if (t == 1023) { g_offs[N] = partial[1023]; g_cnt[N] = 0; }
}
__global__ void fill_kernel(const int* __restrict__ dst, int E) {
    int e = blockIdx.x * blockDim.x + threadIdx.x;
    if (e < E) {
        int pos = atomicAdd(&g_wp[dst[e]], 1);
        g_csr[pos] = e;
    }
}

// ---------------- merged weight prep: conv_wT (z<8) + fold/uv (z==8) ---------
__global__ void prep_w_kernel(const float* __restrict__ W_agg,
                              const float* __restrict__ W_glu_a,
                              const float* __restrict__ W_glu_b,
                              const float* __restrict__ Wc,
                              const float* __restrict__ Wn,
                              const float* __restrict__ ba,
                              const float* __restrict__ bc,
                              const float* __restrict__ bn,
                              const float* __restrict__ Wedge,
                              const float* __restrict__ bedge,
                              const float* __restrict__ b_agg) {
    int z = blockIdx.z;
    int tx = threadIdx.x, ty = threadIdx.y;
    if (z == 8) {
        if (blockIdx.y != 0 || blockIdx.x >= 3) return;
        int j = ty * 32 + tx;
        if (blockIdx.x == 0) {
            float f0 = 0.f, f1 = 0.f, f2 = 0.f, bias = 0.f;
            for (int h = 0; h < HDIM; h++) {
                float wtop = Wn[h * HDIM + j];
                float wbot = Wn[(HDIM + h) * HDIM + j];
                f0 += Wc[0 * HDIM + h] * wbot;
                f1 += Wc[1 * HDIM + h] * wbot;
                f2 += Wc[2 * HDIM + h] * wbot;
                bias += ba[h] * wtop + bc[h] * wbot;
            }
            g_F2[0 * HDIM + j] = f0;
            g_F2[1 * HDIM + j] = f1;
            g_F2[2 * HDIM + j] = f2;
            g_bf[j] = bias + bn[j];
        } else {
            int l = blockIdx.x - 1;
            const float* We = W_agg + (size_t)l * 3 * HH + HH;
            float u = 0.f, v = 0.f;
            for (int k = 0; k < HDIM; k++) {
                float we = We[k * HDIM + j];
                u += Wedge[k] * we;
                v += bedge[k] * we;
            }
            g_uv[l * 2 * HDIM + j] = u;
            g_uv[l * 2 * HDIM + HDIM + j] = v + b_agg[l * HDIM + j];
        }
        return;
    }
    __shared__ float tile[32][33];
    const float* src;
    switch (z) {
        case 0: src = W_agg; break;
        case 1: src = W_agg + 2 * HH; break;
        case 2: src = W_agg + 3 * HH; break;
        case 3: src = W_agg + 5 * HH; break;
        case 4: src = W_glu_a; break;
        case 5: src = W_glu_b; break;
        case 6: src = W_glu_a + HH; break;
        default: src = W_glu_b + HH; break;
    }
    int n0 = blockIdx.x * 32;
    int k0 = blockIdx.y * 32;
#pragma unroll
    for (int q = 0; q < 4; q++) {
        int k = k0 + ty + q * 8;
        tile[ty + q * 8][tx] = src[(size_t)k * HDIM + n0 + tx];
    }
    __syncthreads();
#pragma unroll
    for (int q = 0; q < 4; q++) {
        int n = n0 + ty + q * 8;
        size_t o = (size_t)z * HH + (size_t)n * HDIM + k0 + tx;
        g_Bt[o] = __float2half(tile[tx][ty + q * 8]);
    }
}

// ---------------- warp-per-node aggregation (fp16 gather) --------------------
__global__ void agg_kernel(const int* __restrict__ src,
                           const float* __restrict__ radius,
                           const float* __restrict__ exp_l,
                           const float* __restrict__ eps_l, int l, int N) {
    int warp = (blockIdx.x * blockDim.x + threadIdx.x) >> 5;
    int lane = threadIdx.x & 31;
    if (warp >= N) return;
    float el = __ldg(&exp_l[l]);
    const float* uvb = g_uv + l * 2 * HDIM;
    int beg = g_offs[warp], end = g_offs[warp + 1];
    float4 acc0 = make_float4(0.f, 0.f, 0.f, 0.f);
    float4 acc1 = make_float4(0.f, 0.f, 0.f, 0.f);
    float s1 = 0.f, swr = 0.f;
    int j0 = lane * 8;
    for (int base = beg; base < end; base += 32) {
        int p = base + lane;
        int s = 0;
        float w = 0.f;
        if (p < end) {
            int e = g_csr[p];
            s = src[e];
            float r = radius[e];
            w = __expf(__logf(r) * el);
            s1 += w;
            swr += w * r;
        }
        int cnt = min(32, end - base);
        for (int q = 0; q < cnt; q++) {
            int   sq = __shfl_sync(0xffffffffu, s, q);
            float wq = __shfl_sync(0xffffffffu, w, q);
            uint4 pv = *(const uint4*)(g_s + (size_t)sq * HDIM + j0);
            float2 f0 = __half22float2(*(__half2*)&pv.x);
            float2 f1 = __half22float2(*(__half2*)&pv.y);
            float2 f2 = __half22float2(*(__half2*)&pv.z);
            float2 f3 = __half22float2(*(__half2*)&pv.w);
            acc0.x += wq * f0.x; acc0.y += wq * f0.y;
            acc0.z += wq * f1.x; acc0.w += wq * f1.y;
            acc1.x += wq * f2.x; acc1.y += wq * f2.y;
            acc1.z += wq * f3.x; acc1.w += wq * f3.y;
        }
    }
#pragma unroll
    for (int off = 16; off; off >>= 1) {
        s1  += __shfl_xor_sync(0xffffffffu, s1, off);
        swr += __shfl_xor_sync(0xffffffffu, swr, off);
    }
    float ep = 1.f + __ldg(&eps_l[l]);
    float4 u0  = *(const float4*)(uvb + j0);
    float4 u1  = *(const float4*)(uvb + j0 + 4);
    float4 vp0 = *(const float4*)(uvb + HDIM + j0);
    float4 vp1 = *(const float4*)(uvb + HDIM + j0 + 4);
    size_t idx = (size_t)warp * HDIM + j0;
    uint4 hv = *(const uint4*)(g_hf + idx);
    uint4 dv = *(const uint4*)(g_hdh + idx);
    float2 h01 = __half22float2(*(__half2*)&hv.x);
    float2 h23 = __half22float2(*(__half2*)&hv.y);
    float2 h45 = __half22float2(*(__half2*)&hv.z);
    float2 h67 = __half22float2(*(__half2*)&hv.w);
    float2 d01 = __half22float2(*(__half2*)&dv.x);
    float2 d23 = __half22float2(*(__half2*)&dv.y);
    float2 d45 = __half22float2(*(__half2*)&dv.z);
    float2 d67 = __half22float2(*(__half2*)&dv.w);
    float v[8];
    v[0] = ep * h01.x + acc0.x + s1 * (d01.x + vp0.x) + swr * u0.x;
    v[1] = ep * h01.y + acc0.y + s1 * (d01.y + vp0.y) + swr * u0.y;
    v[2] = ep * h23.x + acc0.z + s1 * (d23.x + vp0.z) + swr * u0.z;
    v[3] = ep * h23.y + acc0.w + s1 * (d23.y + vp0.w) + swr * u0.w;
    v[4] = ep * h45.x + acc1.x + s1 * (d45.x + vp1.x) + swr * u1.x;
    v[5] = ep * h45.y + acc1.y + s1 * (d45.y + vp1.y) + swr * u1.y;
    v[6] = ep * h67.x + acc1.z + s1 * (d67.x + vp1.z) + swr * u1.z;
    v[7] = ep * h67.y + acc1.w + s1 * (d67.y + vp1.w) + swr * u1.w;
    uint4 rv;
    *(__half2*)&rv.x = __float22half2_rn(make_float2(v[0], v[1]));
    *(__half2*)&rv.y = __float22half2_rn(make_float2(v[2], v[3]));
    *(__half2*)&rv.z = __float22half2_rn(make_float2(v[4], v[5]));
    *(__half2*)&rv.w = __float22half2_rn(make_float2(v[6], v[7]));
    *(uint4*)(g_r + idx) = rv;
}

// layer-0 GLU: h = ga * sigmoid(gb), fp16 in/out
__global__ void glu_kernel(int N) {
    int i = blockIdx.x * blockDim.x + threadIdx.x;
    if (i >= N * HDIM / 2) return;
    float2 ga = __half22float2(((const __half2*)g_ga)[i]);
    float2 gb = __half22float2(((const __half2*)g_gb)[i]);
    float h0 = ga.x * (1.f / (1.f + __expf(-gb.x)));
    float h1 = ga.y * (1.f / (1.f + __expf(-gb.y)));
    ((__half2*)g_hf)[i] = __float22half2_rn(make_float2(h0, h1));
}

// last layer: fused GLU + masked segment-sum from fp16 ga/gb
__global__ void glu_segsum_kernel(const int* __restrict__ mask,
                                  const int* __restrict__ gid, int N) {
    int j  = threadIdx.x;
    int n0 = blockIdx.x * 128;
    if (n0 >= N) return;
    int n1 = min(n0 + 128, N);
    float acc = 0.f;
    int curg = gid[n0];
    for (int n = n0; n < n1; n++) {
        int g = gid[n];
        if (g != curg) {
            atomicAdd(&g_feat[curg * HDIM + j], acc);
            acc = 0.f;
            curg = g;
        }
        if (mask[n]) {
            size_t o = (size_t)n * HDIM + j;
            float ga = __half2float(g_ga[o]);
            float gb = __half2float(g_gb[o]);
            acc += ga * (1.f / (1.f + __expf(-gb)));
        }
    }
    atomicAdd(&g_feat[curg * HDIM + j], acc);
}

// MLP head; re-zeroes g_feat row after use (graph-replay invariant)
__global__ void mlp_kernel(const float* __restrict__ Wm,
                           const float* __restrict__ bm,
                           float* __restrict__ out, float invN) {
    int g = blockIdx.x;
    int o = threadIdx.x;
    if (o < OUTD) {
        float s = 0.f;
        for (int j = 0; j < HDIM; j++)
            s += g_feat[g * HDIM + j] * Wm[j * OUTD + o];
        s = s * invN + bm[o];
        out[g * OUTD + o] = 1.f / (1.f + __expf(-s));
    }
    __syncthreads();
    for (int j = threadIdx.x; j < HDIM; j += blockDim.x)
        g_feat[g * HDIM + j] = 0.f;
}

// ---------------- mma.sync fp16 GEMM (4-stage cp.async pipeline) -------------
#define STSZ   20480
#define SOFF_B 10240

__global__ __launch_bounds__(256, 2)
void mma_gemm(const __half* __restrict__ A, int M, int Ktot,
              const __half* __restrict__ B0, const __half* __restrict__ B1,
              const float* __restrict__ bias0, const float* __restrict__ bias1,
              const float* __restrict__ coord,
              const float* __restrict__ F2v, const float* __restrict__ bfv,
              __half* __restrict__ H0, __half* __restrict__ H1) {
    extern __shared__ char smem[];
    const __half* B = blockIdx.z ? B1 : B0;
    const float* bias = blockIdx.z ? bias1 : bias0;
    __half* Hout = blockIdx.z ? H1 : H0;

    int tid = threadIdx.x;
    int wid = tid >> 5;
    int lane = tid & 31;
    int warp_m = wid & 3;
    int warp_n = wid >> 2;
    int m0 = blockIdx.x * 128;
    int n0 = blockIdx.y * 128;
    uint32_t sb = smem_to_u32(smem);

    float acc[2][8][4];
#pragma unroll
    for (int a = 0; a < 2; a++)
#pragma unroll
        for (int b = 0; b < 8; b++)
#pragma unroll
            for (int c = 0; c < 4; c++) acc[a][b][c] = 0.f;

    int KT = Ktot >> 5;
    int lrow = (lane & 7) + ((lane >> 3) & 1) * 8;
    int lcol = (lane >> 4) * 8;

    int row0 = tid >> 2,         kc0 = (tid & 3) * 8;
    int row1 = (tid + 256) >> 2, kc1 = (tid & 3) * 8;
    int arow0 = (m0 + row0 < M) ? (m0 + row0) : 0;
    int arow1 = (m0 + row1 < M) ? (m0 + row1) : 0;
    int asz0  = (m0 + row0 < M) ? 16 : 0;
    int asz1  = (m0 + row1 < M) ? 16 : 0;

#define LOAD_STAGE(kt, buf)                                                        \
    do {                                                                           \
        int k0 = (kt) * 32;                                                        \
        uint32_t d0 = sb + (buf) * STSZ + ((uint32_t)row0 * 40 + kc0) * 2;         \
        uint32_t d1 = sb + (buf) * STSZ + ((uint32_t)row1 * 40 + kc1) * 2;         \
        size_t ao0 = (size_t)arow0 * Ktot + k0 + kc0;                              \
        size_t ao1 = (size_t)arow1 * Ktot + k0 + kc1;                              \
        size_t bo0 = (size_t)(n0 + row0) * Ktot + k0 + kc0;                        \
        size_t bo1 = (size_t)(n0 + row1) * Ktot + k0 + kc1;                        \
        cp_async16(d0,          A + ao0, asz0);                                    \
        cp_async16(d0 + SOFF_B, B + bo0, 16);                                      \
        cp_async16(d1,          A + ao1, asz1);                                    \
        cp_async16(d1 + SOFF_B, B + bo1, 16);                                      \
    } while (0)

    LOAD_STAGE(0, 0);
    CP_COMMIT();
    if (KT > 1) { LOAD_STAGE(1, 1); CP_COMMIT(); }
    if (KT > 2) { LOAD_STAGE(2, 2); CP_COMMIT(); }

    int buf = 0;
#pragma unroll 1
    for (int kt = 0; kt < KT; kt++) {
        if (kt + 2 < KT)      CP_WAIT2();
        else if (kt + 1 < KT) CP_WAIT1();
        else                  CP_WAIT0();
        __syncthreads();
        if (kt + 3 < KT) {
            int nb = buf + 3; if (nb >= 4) nb -= 4;
            LOAD_STAGE(kt + 3, nb);
            CP_COMMIT();
        }
#pragma unroll
        for (int ks = 0; ks < 2; ks++) {
            int kc = ks * 16 + lcol;
            uint32_t ah[2][4];
#pragma unroll
            for (int mt = 0; mt < 2; mt++) {
                int r = warp_m * 32 + mt * 16 + lrow;
                ldsm4(ah[mt], sb + buf * STSZ + ((uint32_t)r * 40 + kc) * 2);
            }
#pragma unroll
            for (int ng = 0; ng < 4; ng++) {
                int r = warp_n * 64 + ng * 16 + lrow;
                uint32_t bh[4];
                ldsm4(bh, sb + buf * STSZ + ((uint32_t)r * 40 + kc) * 2 + SOFF_B);
#pragma unroll
                for (int mt = 0; mt < 2; mt++) {
                    mma16816(acc[mt][2 * ng],     ah[mt], bh[0], bh[2]);
                    mma16816(acc[mt][2 * ng + 1], ah[mt], bh[1], bh[3]);
                }
            }
        }
        buf++; if (buf == 4) buf = 0;
    }

    // ---- epilogue: fp16 output, optional bias / rank-3 coord addend ----
    int gi = lane >> 2;
    int ci = (lane & 3) * 2;
#pragma unroll
    for (int mt = 0; mt < 2; mt++) {
#pragma unroll
        for (int half_ = 0; half_ < 2; half_++) {
            int row = m0 + warp_m * 32 + mt * 16 + gi + half_ * 8;
            if (row >= M) continue;
            float c0 = 0.f, c1 = 0.f, c2 = 0.f;
            if (coord) {
                c0 = __ldg(&coord[row * 3]);
                c1 = __ldg(&coord[row * 3 + 1]);
                c2 = __ldg(&coord[row * 3 + 2]);
            }
#pragma unroll
            for (int nt = 0; nt < 8; nt++) {
                float* a4 = acc[mt][nt];
                int col = n0 + warp_n * 64 + nt * 8 + ci;
                float v0 = a4[half_ * 2];
                float v1 = a4[half_ * 2 + 1];
                if (bias) {
                    v0 += __ldg(&bias[col]);
                    v1 += __ldg(&bias[col + 1]);
                }
                if (coord) {
                    v0 += c0 * __ldg(&F2v[col])     + c1 * __ldg(&F2v[HDIM + col])
                        + c2 * __ldg(&F2v[2 * HDIM + col])     + __ldg(&bfv[col]);
                    v1 += c0 * __ldg(&F2v[col + 1]) + c1 * __ldg(&F2v[HDIM + col + 1])
                        + c2 * __ldg(&F2v[2 * HDIM + col + 1]) + __ldg(&bfv[col + 1]);
                }
                size_t o = (size_t)row * HDIM + col;
                *(__half2*)(Hout + o) = __float22half2_rn(make_float2(v0, v1));
            }
        }
    }
#undef LOAD_STAGE
}

// ---------------- fold GEMM: F1t(fp16, transposed) = (W_atom @ Wn_top)^T -----
__global__ __launch_bounds__(256, 2)
void sgemm_fold(const float* __restrict__ A, int M,
                const float* __restrict__ B,
                __half* __restrict__ Ft) {
    __shared__ float As[2][16][132];
    __shared__ float Bs[2][16][128];
    int tid = threadIdx.x;
    int m0 = 0;
    int n0 = blockIdx.y * 128;
    int tx = tid & 15, ty = tid >> 4;
    int ar = tid >> 2;
    int ac = (tid & 3) * 4;
    int bk = tid >> 5;
    int bn = (tid & 31) * 4;
    bool aval0 = (m0 + ar) < M;
    bool aval1 = (m0 + ar + 64) < M;
    const float* Arow0 = A + (size_t)(m0 + ar) * HDIM + ac;
    const float* Arow1 = A + (size_t)(m0 + ar + 64) * HDIM + ac;
    const float* Bp0 = B + (size_t)bk * HDIM + n0 + bn;
    const float* Bp1 = B + (size_t)(bk + 8) * HDIM + n0 + bn;
    float4 af0, af1, bf0, bf1;
    const float4 fz = make_float4(0.f, 0.f, 0.f, 0.f);
#define LOADG(k0) do { \
        af0 = aval0 ? *(const float4*)(Arow0 + (k0)) : fz; \
        af1 = aval1 ? *(const float4*)(Arow1 + (k0)) : fz; \
        bf0 = *(const float4*)(Bp0 + (size_t)(k0) * HDIM); \
        bf1 = *(const float4*)(Bp1 + (size_t)(k0) * HDIM); } while (0)
#define STORES(bufi) do { \
        As[bufi][ac + 0][ar] = af0.x; As[bufi][ac + 1][ar] = af0.y; \
        As[bufi][ac + 2][ar] = af0.z; As[bufi][ac + 3][ar] = af0.w; \
        As[bufi][ac + 0][ar + 64] = af1.x; As[bufi][ac + 1][ar + 64] = af1.y; \
        As[bufi][ac + 2][ar + 64] = af1.z; As[bufi][ac + 3][ar + 64] = af1.w; \
        *(float4*)&Bs[bufi][bk][bn] = bf0; *(float4*)&Bs[bufi][bk + 8][bn] = bf1; } while (0)
    float acc[8][8];
#pragma unroll
    for (int i = 0; i < 8; i++)
#pragma unroll
        for (int j = 0; j < 8; j++) acc[i][j] = 0.f;
    LOADG(0);
    STORES(0);
    __syncthreads();
    int buf = 0;
#pragma unroll 1
    for (int kt = 0; kt < 16; kt++) {
        if (kt < 15) LOADG((kt + 1) * 16);
#pragma unroll
        for (int k = 0; k < 16; k++) {
            float4 a0 = *(const float4*)&As[buf][k][ty * 8];
            float4 a1 = *(const float4*)&As[buf][k][ty * 8 + 4];
            float4 b0 = *(const float4*)&Bs[buf][k][tx * 8];
            float4 b1 = *(const float4*)&Bs[buf][k][tx * 8 + 4];
            float a[8] = {a0.x, a0.y, a0.z, a0.w, a1.x, a1.y, a1.z, a1.w};
            float b[8] = {b0.x, b0.y, b0.z, b0.w, b1.x, b1.y, b1.z, b1.w};
#pragma unroll
            for (int i = 0; i < 8; i++)
#pragma unroll
                for (int j = 0; j < 8; j++)
                    acc[i][j] += a[i] * b[j];
        }
        if (kt < 15) { STORES(buf ^ 1); __syncthreads(); buf ^= 1; }
    }
    // epilogue: write transposed fp16 F1t[n][m] (cols >= M stay zero-init)
#pragma unroll
    for (int i = 0; i < 8; i++) {
        int mm = m0 + ty * 8 + i;
        if (mm >= M) continue;
#pragma unroll
        for (int j = 0; j < 8; j++) {
            int nn = n0 + tx * 8 + j;
            Ft[(size_t)nn * 128 + mm] = __float2half(acc[i][j]);
        }
    }
#undef LOADG
#undef STORES
}

// ---------------- launcher ---------------------------------------------------
extern "C" void kernel_launch(void* const* d_in, const int* in_sizes, int n_in,
                              void* d_out, int out_size) {
    const float* atomic_num = (const float*)d_in[0];
    const float* coord      = (const float*)d_in[1];
    const float* radius     = (const float*)d_in[2];
    const int*   src        = (const int*)  d_in[3];
    const int*   dst        = (const int*)  d_in[4];
    const int*   abs_mask   = (const int*)  d_in[5];
    const int*   graph_id   = (const int*)  d_in[6];
    const float* W_atom     = (const float*)d_in[7];
    const float* b_atom     = (const float*)d_in[8];
    const float* W_coord    = (const float*)d_in[9];
    const float* b_coord    = (const float*)d_in[10];
    const float* W_node     = (const float*)d_in[11];
    const float* b_node     = (const float*)d_in[12];
    const float* W_edge     = (const float*)d_in[13];
    const float* b_edge     = (const float*)d_in[14];
    const float* W_agg      = (const float*)d_in[15];
    const float* b_agg      = (const float*)d_in[16];
    const float* W_glu_a    = (const float*)d_in[17];
    const float* b_glu_a    = (const float*)d_in[18];
    const float* W_glu_b    = (const float*)d_in[19];
    const float* b_glu_b    = (const float*)d_in[20];
    const float* exp_l      = (const float*)d_in[21];
    const float* eps_l      = (const float*)d_in[22];
    const float* W_mlp      = (const float*)d_in[23];
    const float* b_mlp      = (const float*)d_in[24];
    float* out = (float*)d_out;

    int N = in_sizes[5];
    int E = in_sizes[2];

    float *p_F2, *p_bf;
    __half *p_xa, *p_hf, *p_s, *p_hdh, *p_r, *p_ga, *p_gb, *p_Bt, *p_Ft;
    cudaGetSymbolAddress((void**)&p_F2,   g_F2);
    cudaGetSymbolAddress((void**)&p_bf,   g_bf);
    cudaGetSymbolAddress((void**)&p_xa,   g_xa);
    cudaGetSymbolAddress((void**)&p_hf,   g_hf);
    cudaGetSymbolAddress((void**)&p_s,    g_s);
    cudaGetSymbolAddress((void**)&p_hdh,  g_hdh);
    cudaGetSymbolAddress((void**)&p_r,    g_r);
    cudaGetSymbolAddress((void**)&p_ga,   g_ga);
    cudaGetSymbolAddress((void**)&p_gb,   g_gb);
    cudaGetSymbolAddress((void**)&p_Bt,   g_Bt);
    cudaGetSymbolAddress((void**)&p_Ft,   g_F1t);

    const int MMA_SMEM = 4 * STSZ;
    cudaFuncSetAttribute(mma_gemm, cudaFuncAttributeMaxDynamicSharedMemorySize, MMA_SMEM);

    int mtiles = (N + 127) / 128;
    int eb = (E + 255) / 256;
    int aggb = (N + 7) / 8;

    // pre (x conversion + dst histogram) -> scan -> fill
    pre_kernel<<<256, 256>>>(atomic_num, dst, N, E);
    scan_kernel<<<1, 1024>>>(N);
    fill_kernel<<<eb, 256>>>(dst, E);

    // weight prep: fold GEMM (writes F1t fp16 transposed), then merged prep
    sgemm_fold<<<dim3(1, 2, 1), 256>>>(W_atom, ATOMD, W_node, p_Ft);
    prep_w_kernel<<<dim3(8, 8, 9), dim3(32, 8)>>>(W_agg, W_glu_a, W_glu_b,
                                                  W_coord, W_node, b_atom, b_coord,
                                                  b_node, W_edge, b_edge, b_agg);

    // init: h = x@F1 + (coord@F2 + bf) fused -> g_hf (fp16)
    mma_gemm<<<dim3(mtiles, 2, 1), 256, MMA_SMEM>>>(
        p_xa, N, 128, p_Ft, p_Ft,
        nullptr, nullptr, coord, p_F2, p_bf, p_hf, p_hf);

    for (int l = 0; l < 2; l++) {
        mma_gemm<<<dim3(mtiles, 2, 2), 256, MMA_SMEM>>>(
            p_hf, N, HDIM,
            p_Bt + (size_t)(2 * l) * HH, p_Bt + (size_t)(2 * l + 1) * HH,
            nullptr, nullptr, nullptr, nullptr, nullptr, p_s, p_hdh);
        agg_kernel<<<aggb, 256>>>(src, radius, exp_l, eps_l, l, N);
        mma_gemm<<<dim3(mtiles, 2, 2), 256, MMA_SMEM>>>(
            p_r, N, HDIM,
            p_Bt + (size_t)(4 + 2 * l) * HH, p_Bt + (size_t)(5 + 2 * l) * HH,
            b_glu_a + l * HDIM, b_glu_b + l * HDIM, nullptr, nullptr, nullptr,
            p_ga, p_gb);
        if (l == 0) glu_kernel<<<(N * HDIM / 2 + 255) / 256, 256>>>(N);
    }

    glu_segsum_kernel<<<(N + 127) / 128, HDIM>>>(abs_mask, graph_id, N);
    mlp_kernel<<<GN, 128>>>(W_mlp, b_mlp, out, 1.0f / (float)N);
}

// round 17
// speedup vs baseline: 1.5878x; 1.0735x over previous
#include <cuda_runtime.h>
#include <cuda_fp16.h>
#include <stdint.h>
#include <cstdint>
#include <math.h>

#define N_NODES 20000
#define N_EDGES 640000
#define HDIM    256
#define GN      16
#define OUTD    100
#define ATOMD   118
#define HH      (HDIM * HDIM)

// ---------------- scratch ----------------------------------------------------
__device__ __align__(16) float g_uv [2 * 2 * HDIM];      // [layer][u|vp]
__device__ __align__(16) float g_F2 [3 * HDIM];
__device__ __align__(16) float g_bf [HDIM];
__device__ __align__(16) float g_feat[GN * HDIM];        // zero-init; re-zeroed by mlp
__device__ int   g_cnt [N_NODES + 1];                    // zero-init; re-zeroed by scan
__device__ int   g_offs[N_NODES + 1];
__device__ int   g_wp  [N_NODES];
__device__ int   g_csr [N_EDGES];
// fp16 activations
__device__ __align__(16) __half g_xa [N_NODES * 128];
__device__ __align__(16) __half g_hf [N_NODES * HDIM];   // h
__device__ __align__(16) __half g_s  [N_NODES * HDIM];   // hs (gather src)
__device__ __align__(16) __half g_hdh[N_NODES * HDIM];   // hd
__device__ __align__(16) __half g_r  [N_NODES * HDIM];   // rst
__device__ __align__(16) __half g_ga [N_NODES * HDIM];
__device__ __align__(16) __half g_gb [N_NODES * HDIM];
// fp16 weights
__device__ __align__(16) __half g_Bt [8 * HH];
__device__ __align__(16) __half g_F1t[HDIM * 128];       // zero-init (cols 118..127 stay 0)

// ---------------- PTX helpers (all sm_80-legal) ------------------------------
__device__ __forceinline__ uint32_t smem_to_u32(const void* p) {
    uint32_t a;
    asm("{ .reg .u64 t; cvta.to.shared.u64 t, %1; cvt.u32.u64 %0, t; }" : "=r"(a) : "l"(p));
    return a;
}
__device__ __forceinline__ void ldsm4(uint32_t* r, uint32_t addr) {
    asm volatile("ldmatrix.sync.aligned.m8n8.x4.shared.b16 {%0,%1,%2,%3}, [%4];"
                 : "=r"(r[0]), "=r"(r[1]), "=r"(r[2]), "=r"(r[3]) : "r"(addr));
}
__device__ __forceinline__ void mma16816(float* c, const uint32_t* a, uint32_t b0, uint32_t b1) {
    asm volatile("mma.sync.aligned.m16n8k16.row.col.f32.f16.f16.f32 "
                 "{%0,%1,%2,%3}, {%4,%5,%6,%7}, {%8,%9}, {%0,%1,%2,%3};"
                 : "+f"(c[0]), "+f"(c[1]), "+f"(c[2]), "+f"(c[3])
                 : "r"(a[0]), "r"(a[1]), "r"(a[2]), "r"(a[3]), "r"(b0), "r"(b1));
}
__device__ __forceinline__ void cp_async16(uint32_t d, const void* s, int src_sz) {
    asm volatile("cp.async.cg.shared.global [%0], [%1], 16, %2;"
                 :: "r"(d), "l"(s), "r"(src_sz) : "memory");
}
#define CP_COMMIT() asm volatile("cp.async.commit_group;" ::: "memory")
#define CP_WAIT0()  asm volatile("cp.async.wait_group 0;" ::: "memory")
#define CP_WAIT1()  asm volatile("cp.async.wait_group 1;" ::: "memory")
#define CP_WAIT2()  asm volatile("cp.async.wait_group 2;" ::: "memory")

// ---------------- pre: x conversion + dst histogram (cnt pre-zeroed) ----------
__global__ void pre_kernel(const float* __restrict__ x,
                           const int* __restrict__ dst, int N, int E) {
    int stride = gridDim.x * blockDim.x;
    int i = blockIdx.x * blockDim.x + threadIdx.x;
    for (int e = i; e < N * 128; e += stride) {
        int n = e >> 7, kk = e & 127;
        float v = (kk < ATOMD) ? x[n * ATOMD + kk] : 0.f;
        g_xa[e] = __float2half(v);
    }
    for (int e = i; e < E; e += stride) atomicAdd(&g_cnt[dst[e]], 1);
}
__global__ void scan_kernel(int N) {
    __shared__ int partial[1024];
    int t = threadIdx.x;
    int per = (N + 1023) / 1024;
    int start = t * per;
    int stop  = min(start + per, N);
    int sum = 0;
    for (int i = start; i < stop; i++) sum += g_cnt[i];
    partial[t] = sum;
    __syncthreads();
    for (int d = 1; d < 1024; d <<= 1) {
        int v = (t >= d) ? partial[t - d] : 0;
        __syncthreads();
        partial[t] += v;
        __syncthreads();
    }
    int run = (t == 0) ? 0 : partial[t - 1];
    for (int i = start; i < stop; i++) {
        g_offs[i] = run;
        g_wp[i]   = run;
        run += g_cnt[i];
        g_cnt[i] = 0;                    // restore zero for next launch
    }
    if (t == 1023) { g_offs[N] = partial[1023]; g_cnt[N] = 0; }
}
__global__ void fill_kernel(const int* __restrict__ dst, int E) {
    int e = blockIdx.x * blockDim.x + threadIdx.x;
    if (e < E) {
        int pos = atomicAdd(&g_wp[dst[e]], 1);
        g_csr[pos] = e;
    }
}

// ---------------- parallel fold: F1t[n][m] = sum_h W_atom[m][h] * Wn[h][n] ----
// one block per m-row (118 blocks), 256 threads = n, coalesced Wn reads
__global__ void fold_F1_kernel(const float* __restrict__ Wa,
                               const float* __restrict__ Wn) {
    __shared__ float arow[HDIM];
    int m = blockIdx.x;
    int n = threadIdx.x;
    arow[n] = Wa[(size_t)m * HDIM + n];
    __syncthreads();
    float s = 0.f;
#pragma unroll 8
    for (int h = 0; h < HDIM; h++)
        s += arow[h] * Wn[(size_t)h * HDIM + n];
    g_F1t[(size_t)n * 128 + m] = __float2half(s);
}

// ---------------- merged weight prep: conv_wT (z<8) + fold/uv (z==8) ---------
__global__ void prep_w_kernel(const float* __restrict__ W_agg,
                              const float* __restrict__ W_glu_a,
                              const float* __restrict__ W_glu_b,
                              const float* __restrict__ Wc,
                              const float* __restrict__ Wn,
                              const float* __restrict__ ba,
                              const float* __restrict__ bc,
                              const float* __restrict__ bn,
                              const float* __restrict__ Wedge,
                              const float* __restrict__ bedge,
                              const float* __restrict__ b_agg) {
    int z = blockIdx.z;
    int tx = threadIdx.x, ty = threadIdx.y;
    if (z == 8) {
        if (blockIdx.y != 0 || blockIdx.x >= 3) return;
        int j = ty * 32 + tx;
        if (blockIdx.x == 0) {
            float f0 = 0.f, f1 = 0.f, f2 = 0.f, bias = 0.f;
            for (int h = 0; h < HDIM; h++) {
                float wtop = Wn[h * HDIM + j];
                float wbot = Wn[(HDIM + h) * HDIM + j];
                f0 += Wc[0 * HDIM + h] * wbot;
                f1 += Wc[1 * HDIM + h] * wbot;
                f2 += Wc[2 * HDIM + h] * wbot;
                bias += ba[h] * wtop + bc[h] * wbot;
            }
            g_F2[0 * HDIM + j] = f0;
            g_F2[1 * HDIM + j] = f1;
            g_F2[2 * HDIM + j] = f2;
            g_bf[j] = bias + bn[j];
        } else {
            int l = blockIdx.x - 1;
            const float* We = W_agg + (size_t)l * 3 * HH + HH;
            float u = 0.f, v = 0.f;
            for (int k = 0; k < HDIM; k++) {
                float we = We[k * HDIM + j];
                u += Wedge[k] * we;
                v += bedge[k] * we;
            }
            g_uv[l * 2 * HDIM + j] = u;
            g_uv[l * 2 * HDIM + HDIM + j] = v + b_agg[l * HDIM + j];
        }
        return;
    }
    __shared__ float tile[32][33];
    const float* src;
    switch (z) {
        case 0: src = W_agg; break;
        case 1: src = W_agg + 2 * HH; break;
        case 2: src = W_agg + 3 * HH; break;
        case 3: src = W_agg + 5 * HH; break;
        case 4: src = W_glu_a; break;
        case 5: src = W_glu_b; break;
        case 6: src = W_glu_a + HH; break;
        default: src = W_glu_b + HH; break;
    }
    int n0 = blockIdx.x * 32;
    int k0 = blockIdx.y * 32;
#pragma unroll
    for (int q = 0; q < 4; q++) {
        int k = k0 + ty + q * 8;
        tile[ty + q * 8][tx] = src[(size_t)k * HDIM + n0 + tx];
    }
    __syncthreads();
#pragma unroll
    for (int q = 0; q < 4; q++) {
        int n = n0 + ty + q * 8;
        size_t o = (size_t)z * HH + (size_t)n * HDIM + k0 + tx;
        g_Bt[o] = __float2half(tile[tx][ty + q * 8]);
    }
}

// ---------------- warp-per-node aggregation (fp16 gather) --------------------
__global__ void agg_kernel(const int* __restrict__ src,
                           const float* __restrict__ radius,
                           const float* __restrict__ exp_l,
                           const float* __restrict__ eps_l, int l, int N) {
    int warp = (blockIdx.x * blockDim.x + threadIdx.x) >> 5;
    int lane = threadIdx.x & 31;
    if (warp >= N) return;
    float el = __ldg(&exp_l[l]);
    const float* uvb = g_uv + l * 2 * HDIM;
    int beg = g_offs[warp], end = g_offs[warp + 1];
    float4 acc0 = make_float4(0.f, 0.f, 0.f, 0.f);
    float4 acc1 = make_float4(0.f, 0.f, 0.f, 0.f);
    float s1 = 0.f, swr = 0.f;
    int j0 = lane * 8;
    for (int base = beg; base < end; base += 32) {
        int p = base + lane;
        int s = 0;
        float w = 0.f;
        if (p < end) {
            int e = g_csr[p];
            s = src[e];
            float r = radius[e];
            w = __expf(__logf(r) * el);
            s1 += w;
            swr += w * r;
        }
        int cnt = min(32, end - base);
        for (int q = 0; q < cnt; q++) {
            int   sq = __shfl_sync(0xffffffffu, s, q);
            float wq = __shfl_sync(0xffffffffu, w, q);
            uint4 pv = *(const uint4*)(g_s + (size_t)sq * HDIM + j0);
            float2 f0 = __half22float2(*(__half2*)&pv.x);
            float2 f1 = __half22float2(*(__half2*)&pv.y);
            float2 f2 = __half22float2(*(__half2*)&pv.z);
            float2 f3 = __half22float2(*(__half2*)&pv.w);
            acc0.x += wq * f0.x; acc0.y += wq * f0.y;
            acc0.z += wq * f1.x; acc0.w += wq * f1.y;
            acc1.x += wq * f2.x; acc1.y += wq * f2.y;
            acc1.z += wq * f3.x; acc1.w += wq * f3.y;
        }
    }
#pragma unroll
    for (int off = 16; off; off >>= 1) {
        s1  += __shfl_xor_sync(0xffffffffu, s1, off);
        swr += __shfl_xor_sync(0xffffffffu, swr, off);
    }
    float ep = 1.f + __ldg(&eps_l[l]);
    float4 u0  = *(const float4*)(uvb + j0);
    float4 u1  = *(const float4*)(uvb + j0 + 4);
    float4 vp0 = *(const float4*)(uvb + HDIM + j0);
    float4 vp1 = *(const float4*)(uvb + HDIM + j0 + 4);
    size_t idx = (size_t)warp * HDIM + j0;
    uint4 hv = *(const uint4*)(g_hf + idx);
    uint4 dv = *(const uint4*)(g_hdh + idx);
    float2 h01 = __half22float2(*(__half2*)&hv.x);
    float2 h23 = __half22float2(*(__half2*)&hv.y);
    float2 h45 = __half22float2(*(__half2*)&hv.z);
    float2 h67 = __half22float2(*(__half2*)&hv.w);
    float2 d01 = __half22float2(*(__half2*)&dv.x);
    float2 d23 = __half22float2(*(__half2*)&dv.y);
    float2 d45 = __half22float2(*(__half2*)&dv.z);
    float2 d67 = __half22float2(*(__half2*)&dv.w);
    float v[8];
    v[0] = ep * h01.x + acc0.x + s1 * (d01.x + vp0.x) + swr * u0.x;
    v[1] = ep * h01.y + acc0.y + s1 * (d01.y + vp0.y) + swr * u0.y;
    v[2] = ep * h23.x + acc0.z + s1 * (d23.x + vp0.z) + swr * u0.z;
    v[3] = ep * h23.y + acc0.w + s1 * (d23.y + vp0.w) + swr * u0.w;
    v[4] = ep * h45.x + acc1.x + s1 * (d45.x + vp1.x) + swr * u1.x;
    v[5] = ep * h45.y + acc1.y + s1 * (d45.y + vp1.y) + swr * u1.y;
    v[6] = ep * h67.x + acc1.z + s1 * (d67.x + vp1.z) + swr * u1.z;
    v[7] = ep * h67.y + acc1.w + s1 * (d67.y + vp1.w) + swr * u1.w;
    uint4 rv;
    *(__half2*)&rv.x = __float22half2_rn(make_float2(v[0], v[1]));
    *(__half2*)&rv.y = __float22half2_rn(make_float2(v[2], v[3]));
    *(__half2*)&rv.z = __float22half2_rn(make_float2(v[4], v[5]));
    *(__half2*)&rv.w = __float22half2_rn(make_float2(v[6], v[7]));
    *(uint4*)(g_r + idx) = rv;
}

// layer-0 GLU: h = ga * sigmoid(gb), fp16 in/out
__global__ void glu_kernel(int N) {
    int i = blockIdx.x * blockDim.x + threadIdx.x;
    if (i >= N * HDIM / 2) return;
    float2 ga = __half22float2(((const __half2*)g_ga)[i]);
    float2 gb = __half22float2(((const __half2*)g_gb)[i]);
    float h0 = ga.x * (1.f / (1.f + __expf(-gb.x)));
    float h1 = ga.y * (1.f / (1.f + __expf(-gb.y)));
    ((__half2*)g_hf)[i] = __float22half2_rn(make_float2(h0, h1));
}

// last layer: fused GLU + masked segment-sum from fp16 ga/gb
__global__ void glu_segsum_kernel(const int* __restrict__ mask,
                                  const int* __restrict__ gid, int N) {
    int j  = threadIdx.x;
    int n0 = blockIdx.x * 128;
    if (n0 >= N) return;
    int n1 = min(n0 + 128, N);
    float acc = 0.f;
    int curg = gid[n0];
    for (int n = n0; n < n1; n++) {
        int g = gid[n];
        if (g != curg) {
            atomicAdd(&g_feat[curg * HDIM + j], acc);
            acc = 0.f;
            curg = g;
        }
        if (mask[n]) {
            size_t o = (size_t)n * HDIM + j;
            float ga = __half2float(g_ga[o]);
            float gb = __half2float(g_gb[o]);
            acc += ga * (1.f / (1.f + __expf(-gb)));
        }
    }
    atomicAdd(&g_feat[curg * HDIM + j], acc);
}

// MLP head; re-zeroes g_feat row after use (graph-replay invariant)
__global__ void mlp_kernel(const float* __restrict__ Wm,
                           const float* __restrict__ bm,
                           float* __restrict__ out, float invN) {
    int g = blockIdx.x;
    int o = threadIdx.x;
    if (o < OUTD) {
        float s = 0.f;
        for (int j = 0; j < HDIM; j++)
            s += g_feat[g * HDIM + j] * Wm[j * OUTD + o];
        s = s * invN + bm[o];
        out[g * OUTD + o] = 1.f / (1.f + __expf(-s));
    }
    __syncthreads();
    for (int j = threadIdx.x; j < HDIM; j += blockDim.x)
        g_feat[g * HDIM + j] = 0.f;
}

// ---------------- mma.sync fp16 GEMM (4-stage cp.async pipeline) -------------
#define STSZ   20480
#define SOFF_B 10240

__global__ __launch_bounds__(256, 2)
void mma_gemm(const __half* __restrict__ A, int M, int Ktot,
              const __half* __restrict__ B0, const __half* __restrict__ B1,
              const float* __restrict__ bias0, const float* __restrict__ bias1,
              const float* __restrict__ coord,
              const float* __restrict__ F2v, const float* __restrict__ bfv,
              __half* __restrict__ H0, __half* __restrict__ H1) {
    extern __shared__ char smem[];
    const __half* B = blockIdx.z ? B1 : B0;
    const float* bias = blockIdx.z ? bias1 : bias0;
    __half* Hout = blockIdx.z ? H1 : H0;

    int tid = threadIdx.x;
    int wid = tid >> 5;
    int lane = tid & 31;
    int warp_m = wid & 3;
    int warp_n = wid >> 2;
    int m0 = blockIdx.x * 128;
    int n0 = blockIdx.y * 128;
    uint32_t sb = smem_to_u32(smem);

    float acc[2][8][4];
#pragma unroll
    for (int a = 0; a < 2; a++)
#pragma unroll
        for (int b = 0; b < 8; b++)
#pragma unroll
            for (int c = 0; c < 4; c++) acc[a][b][c] = 0.f;

    int KT = Ktot >> 5;
    int lrow = (lane & 7) + ((lane >> 3) & 1) * 8;
    int lcol = (lane >> 4) * 8;

    int row0 = tid >> 2,         kc0 = (tid & 3) * 8;
    int row1 = (tid + 256) >> 2, kc1 = (tid & 3) * 8;
    int arow0 = (m0 + row0 < M) ? (m0 + row0) : 0;
    int arow1 = (m0 + row1 < M) ? (m0 + row1) : 0;
    int asz0  = (m0 + row0 < M) ? 16 : 0;
    int asz1  = (m0 + row1 < M) ? 16 : 0;

#define LOAD_STAGE(kt, buf)                                                        \
    do {                                                                           \
        int k0 = (kt) * 32;                                                        \
        uint32_t d0 = sb + (buf) * STSZ + ((uint32_t)row0 * 40 + kc0) * 2;         \
        uint32_t d1 = sb + (buf) * STSZ + ((uint32_t)row1 * 40 + kc1) * 2;         \
        size_t ao0 = (size_t)arow0 * Ktot + k0 + kc0;                              \
        size_t ao1 = (size_t)arow1 * Ktot + k0 + kc1;                              \
        size_t bo0 = (size_t)(n0 + row0) * Ktot + k0 + kc0;                        \
        size_t bo1 = (size_t)(n0 + row1) * Ktot + k0 + kc1;                        \
        cp_async16(d0,          A + ao0, asz0);                                    \
        cp_async16(d0 + SOFF_B, B + bo0, 16);                                      \
        cp_async16(d1,          A + ao1, asz1);                                    \
        cp_async16(d1 + SOFF_B, B + bo1, 16);                                      \
    } while (0)

    LOAD_STAGE(0, 0);
    CP_COMMIT();
    if (KT > 1) { LOAD_STAGE(1, 1); CP_COMMIT(); }
    if (KT > 2) { LOAD_STAGE(2, 2); CP_COMMIT(); }

    int buf = 0;
#pragma unroll 1
    for (int kt = 0; kt < KT; kt++) {
        if (kt + 2 < KT)      CP_WAIT2();
        else if (kt + 1 < KT) CP_WAIT1();
        else                  CP_WAIT0();
        __syncthreads();
        if (kt + 3 < KT) {
            int nb = buf + 3; if (nb >= 4) nb -= 4;
            LOAD_STAGE(kt + 3, nb);
            CP_COMMIT();
        }
#pragma unroll
        for (int ks = 0; ks < 2; ks++) {
            int kc = ks * 16 + lcol;
            uint32_t ah[2][4];
#pragma unroll
            for (int mt = 0; mt < 2; mt++) {
                int r = warp_m * 32 + mt * 16 + lrow;
                ldsm4(ah[mt], sb + buf * STSZ + ((uint32_t)r * 40 + kc) * 2);
            }
#pragma unroll
            for (int ng = 0; ng < 4; ng++) {
                int r = warp_n * 64 + ng * 16 + lrow;
                uint32_t bh[4];
                ldsm4(bh, sb + buf * STSZ + ((uint32_t)r * 40 + kc) * 2 + SOFF_B);
#pragma unroll
                for (int mt = 0; mt < 2; mt++) {
                    mma16816(acc[mt][2 * ng],     ah[mt], bh[0], bh[2]);
                    mma16816(acc[mt][2 * ng + 1], ah[mt], bh[1], bh[3]);
                }
            }
        }
        buf++; if (buf == 4) buf = 0;
    }

    // ---- epilogue: fp16 output, optional bias / rank-3 coord addend ----
    int gi = lane >> 2;
    int ci = (lane & 3) * 2;
#pragma unroll
    for (int mt = 0; mt < 2; mt++) {
#pragma unroll
        for (int half_ = 0; half_ < 2; half_++) {
            int row = m0 + warp_m * 32 + mt * 16 + gi + half_ * 8;
            if (row >= M) continue;
            float c0 = 0.f, c1 = 0.f, c2 = 0.f;
            if (coord) {
                c0 = __ldg(&coord[row * 3]);
                c1 = __ldg(&coord[row * 3 + 1]);
                c2 = __ldg(&coord[row * 3 + 2]);
            }
#pragma unroll
            for (int nt = 0; nt < 8; nt++) {
                float* a4 = acc[mt][nt];
                int col = n0 + warp_n * 64 + nt * 8 + ci;
                float v0 = a4[half_ * 2];
                float v1 = a4[half_ * 2 + 1];
                if (bias) {
                    v0 += __ldg(&bias[col]);
                    v1 += __ldg(&bias[col + 1]);
                }
                if (coord) {
                    v0 += c0 * __ldg(&F2v[col])     + c1 * __ldg(&F2v[HDIM + col])
                        + c2 * __ldg(&F2v[2 * HDIM + col])     + __ldg(&bfv[col]);
                    v1 += c0 * __ldg(&F2v[col + 1]) + c1 * __ldg(&F2v[HDIM + col + 1])
                        + c2 * __ldg(&F2v[2 * HDIM + col + 1]) + __ldg(&bfv[col + 1]);
                }
                size_t o = (size_t)row * HDIM + col;
                *(__half2*)(Hout + o) = __float22half2_rn(make_float2(v0, v1));
            }
        }
    }
#undef LOAD_STAGE
}

// ---------------- launcher ---------------------------------------------------
extern "C" void kernel_launch(void* const* d_in, const int* in_sizes, int n_in,
                              void* d_out, int out_size) {
    const float* atomic_num = (const float*)d_in[0];
    const float* coord      = (const float*)d_in[1];
    const float* radius     = (const float*)d_in[2];
    const int*   src        = (const int*)  d_in[3];
    const int*   dst        = (const int*)  d_in[4];
    const int*   abs_mask   = (const int*)  d_in[5];
    const int*   graph_id   = (const int*)  d_in[6];
    const float* W_atom     = (const float*)d_in[7];
    const float* b_atom     = (const float*)d_in[8];
    const float* W_coord    = (const float*)d_in[9];
    const float* b_coord    = (const float*)d_in[10];
    const float* W_node     = (const float*)d_in[11];
    const float* b_node     = (const float*)d_in[12];
    const float* W_edge     = (const float*)d_in[13];
    const float* b_edge     = (const float*)d_in[14];
    const float* W_agg      = (const float*)d_in[15];
    const float* b_agg      = (const float*)d_in[16];
    const float* W_glu_a    = (const float*)d_in[17];
    const float* b_glu_a    = (const float*)d_in[18];
    const float* W_glu_b    = (const float*)d_in[19];
    const float* b_glu_b    = (const float*)d_in[20];
    const float* exp_l      = (const float*)d_in[21];
    const float* eps_l      = (const float*)d_in[22];
    const float* W_mlp      = (const float*)d_in[23];
    const float* b_mlp      = (const float*)d_in[24];
    float* out = (float*)d_out;

    int N = in_sizes[5];
    int E = in_sizes[2];

    float *p_F2, *p_bf;
    __half *p_xa, *p_hf, *p_s, *p_hdh, *p_r, *p_ga, *p_gb, *p_Bt, *p_Ft;
    cudaGetSymbolAddress((void**)&p_F2,   g_F2);
    cudaGetSymbolAddress((void**)&p_bf,   g_bf);
    cudaGetSymbolAddress((void**)&p_xa,   g_xa);
    cudaGetSymbolAddress((void**)&p_hf,   g_hf);
    cudaGetSymbolAddress((void**)&p_s,    g_s);
    cudaGetSymbolAddress((void**)&p_hdh,  g_hdh);
    cudaGetSymbolAddress((void**)&p_r,    g_r);
    cudaGetSymbolAddress((void**)&p_ga,   g_ga);
    cudaGetSymbolAddress((void**)&p_gb,   g_gb);
    cudaGetSymbolAddress((void**)&p_Bt,   g_Bt);
    cudaGetSymbolAddress((void**)&p_Ft,   g_F1t);

    const int MMA_SMEM = 4 * STSZ;
    cudaFuncSetAttribute(mma_gemm, cudaFuncAttributeMaxDynamicSharedMemorySize, MMA_SMEM);

    int mtiles = (N + 127) / 128;
    int eb = (E + 255) / 256;
    int aggb = (N + 7) / 8;

    // pre (x conversion + dst histogram) -> scan -> fill
    pre_kernel<<<256, 256>>>(atomic_num, dst, N, E);
    scan_kernel<<<1, 1024>>>(N);
    fill_kernel<<<eb, 256>>>(dst, E);

    // weight prep: parallel fold (118 blocks), then merged transpose/uv prep
    fold_F1_kernel<<<ATOMD, HDIM>>>(W_atom, W_node);
    prep_w_kernel<<<dim3(8, 8, 9), dim3(32, 8)>>>(W_agg, W_glu_a, W_glu_b,
                                                  W_coord, W_node, b_atom, b_coord,
                                                  b_node, W_edge, b_edge, b_agg);

    // init: h = x@F1 + (coord@F2 + bf) fused -> g_hf (fp16)
    mma_gemm<<<dim3(mtiles, 2, 1), 256, MMA_SMEM>>>(
        p_xa, N, 128, p_Ft, p_Ft,
        nullptr, nullptr, coord, p_F2, p_bf, p_hf, p_hf);

    for (int l = 0; l < 2; l++) {
        mma_gemm<<<dim3(mtiles, 2, 2), 256, MMA_SMEM>>>(
            p_hf, N, HDIM,
            p_Bt + (size_t)(2 * l) * HH, p_Bt + (size_t)(2 * l + 1) * HH,
            nullptr, nullptr, nullptr, nullptr, nullptr, p_s, p_hdh);
        agg_kernel<<<aggb, 256>>>(src, radius, exp_l, eps_l, l, N);
        mma_gemm<<<dim3(mtiles, 2, 2), 256, MMA_SMEM>>>(
            p_r, N, HDIM,
            p_Bt + (size_t)(4 + 2 * l) * HH, p_Bt + (size_t)(5 + 2 * l) * HH,
            b_glu_a + l * HDIM, b_glu_b + l * HDIM, nullptr, nullptr, nullptr,
            p_ga, p_gb);
        if (l == 0) glu_kernel<<<(N * HDIM / 2 + 255) / 256, 256>>>(N);
    }

    glu_segsum_kernel<<<(N + 127) / 128, HDIM>>>(abs_mask, graph_id, N);
    mlp_kernel<<<GN, 128>>>(W_mlp, b_mlp, out, 1.0f / (float)N);
}